// round 9
// baseline (speedup 1.0000x reference)
#include <cuda_runtime.h>
#include <math.h>
#include <cstdint>

// ---------------- problem constants ----------------
#define BATCH 4
#define D64   64
#define D32   32
#define D16   16
#define NTOK  (BATCH*4096)
#define EDIM  16
#define KCODE 8192
#define N_MC  (BATCH*8*D64*D64*D64)
#define OFF_MC     8388608
#define OFF_COMMIT 16777216
#define OFF_IDX    16777217

// ---------------- device scratch ----------------
__device__ float g_bufA[BATCH*32*D64*D64*D64];
__device__ float g_bufB[BATCH*64*D32*D32*D32];
__device__ float g_bufC[BATCH*128*D16*D16*D16];
__device__ float g_bufD[BATCH*128*D16*D16*D16];
__device__ float g_seq[NTOK*EDIM];
__device__ float g_q[BATCH*EDIM*4096];
__device__ float g_cl[BATCH*4096*128];
__device__ float g_wt [27*128*128];
__device__ float g_wt1[27*128*64];
__device__ float g_wt2[27*64*32];
__device__ float g_cnorm[KCODE];
__device__ float g_part[128];
__device__ int   g_idx[NTOK];
__device__ unsigned char g_zmask[NTOK];
__device__ int   g_flags;
__device__ int   g_nnz;
__device__ int   g_toklist[NTOK];

__device__ __forceinline__ float silu(float v) { return v * __frcp_rn(1.f + __expf(-v)); }

__device__ __forceinline__ uint32_t f2tf(float f) {
    uint32_t r; asm("cvt.rna.tf32.f32 %0, %1;" : "=r"(r) : "f"(f)); return r;
}
__device__ __forceinline__ void mma_tf32(float* d, const uint32_t* a, const uint32_t* b) {
    asm volatile("mma.sync.aligned.m16n8k8.row.col.f32.tf32.tf32.f32 "
                 "{%0,%1,%2,%3}, {%4,%5,%6,%7}, {%8,%9}, {%0,%1,%2,%3};"
                 : "+f"(d[0]), "+f"(d[1]), "+f"(d[2]), "+f"(d[3])
                 : "r"(a[0]), "r"(a[1]), "r"(a[2]), "r"(a[3]), "r"(b[0]), "r"(b[1]));
}

// -------- weight transform: w[OC][IC][27] -> dst[tap][ic][oc], tf32-rounded --------
__global__ void wtrans2(const float* __restrict__ w, float* __restrict__ dst, int IC, int OC) {
    int i = blockIdx.x * 256 + threadIdx.x;
    int total = 27 * IC * OC;
    if (i >= total) return;
    int tap = i / (IC * OC); int rem = i % (IC * OC); int ic = rem / OC; int oc = rem % OC;
    dst[i] = __uint_as_float(f2tf(w[(oc * IC + ic) * 27 + tap]));
}

// ---------- mma.sync tf32 implicit-GEMM 3x3x3 conv (128ch -> 128ch, 16^3) ----------
#define SA 36
#define SB 136
#define STAGE_F (128*SA + 32*SB)

__launch_bounds__(256)
__global__ void conv_mma_dec(const float* __restrict__ in_cl, const float* __restrict__ bias,
                             float* __restrict__ out_cl)
{
    extern __shared__ float dsm[];
    const int tid = threadIdx.x;
    const int lane = tid & 31, wid = tid >> 5;
    const int wm = wid >> 2, wn = wid & 3;
    const int bb = blockIdx.z;
    const int pos0 = blockIdx.x * 128;
    const float* inb = in_cl + (size_t)bb * 4096 * 128;

    float acc[4][4][4];
#pragma unroll
    for (int mt = 0; mt < 4; mt++)
#pragma unroll
        for (int nt = 0; nt < 4; nt++)
#pragma unroll
            for (int k = 0; k < 4; k++) acc[mt][nt][k] = 0.f;

    const int ar = tid >> 1, aseg = tid & 1;
    const int apos = pos0 + ar;
    const int ax = apos & 15, ay = (apos >> 4) & 15, az = apos >> 8;
    const int bk = tid >> 3, bseg = tid & 7;

    float4 ra[4], rb[4];
    auto ldg = [&](int c) {
        int tap = c >> 2, ic0 = (c & 3) * 32;
        int tz = tap / 9, ty = (tap / 3) % 3, tx = tap % 3;
        int xx = ax + tx - 1, yy = ay + ty - 1, zz = az + tz - 1;
        bool valid = ((unsigned)xx < 16u) & ((unsigned)yy < 16u) & ((unsigned)zz < 16u);
        if (valid) {
            const float4* sa = (const float4*)(inb + (size_t)((zz * 16 + yy) * 16 + xx) * 128
                                               + ic0 + aseg * 16);
            ra[0] = sa[0]; ra[1] = sa[1]; ra[2] = sa[2]; ra[3] = sa[3];
        } else {
            ra[0] = ra[1] = ra[2] = ra[3] = make_float4(0.f, 0.f, 0.f, 0.f);
        }
        const float4* sb = (const float4*)(g_wt + (size_t)(tap * 128 + ic0 + bk) * 128
                                           + bseg * 16);
        rb[0] = sb[0]; rb[1] = sb[1]; rb[2] = sb[2]; rb[3] = sb[3];
    };
    auto sts = [&](int s) {
        float* Au = dsm + s * STAGE_F;
        float* Bu = Au + 128 * SA;
#pragma unroll
        for (int j = 0; j < 4; j++) {
            *(float4*)(Au + ar * SA + aseg * 16 + 4 * j) = ra[j];
            *(float4*)(Bu + bk * SB + bseg * 16 + 4 * j) = rb[j];
        }
    };
    auto domma = [&](int s) {
        const uint32_t* Au = (const uint32_t*)(dsm + s * STAGE_F);
        const uint32_t* Bu = Au + 128 * SA;
        const int rq = lane >> 2, cq = lane & 3;
#pragma unroll
        for (int q = 0; q < 4; q++) {
            const int kk = q * 8 + cq;
            uint32_t af[4][4], bf[4][2];
#pragma unroll
            for (int mt = 0; mt < 4; mt++) {
                int row = wm * 64 + mt * 16 + rq;
                af[mt][0] = Au[row * SA + kk];
                af[mt][1] = Au[(row + 8) * SA + kk];
                af[mt][2] = Au[row * SA + kk + 4];
                af[mt][3] = Au[(row + 8) * SA + kk + 4];
            }
#pragma unroll
            for (int nt = 0; nt < 4; nt++) {
                int col = wn * 32 + nt * 8 + rq;
                bf[nt][0] = Bu[kk * SB + col];
                bf[nt][1] = Bu[(kk + 4) * SB + col];
            }
#pragma unroll
            for (int mt = 0; mt < 4; mt++)
#pragma unroll
                for (int nt = 0; nt < 4; nt++)
                    mma_tf32(acc[mt][nt], af[mt], bf[nt]);
        }
    };

    ldg(0); sts(0); __syncthreads();
#pragma unroll 1
    for (int c = 0; c < 108; c++) {
        if (c < 107) ldg(c + 1);
        domma(c & 1);
        if (c < 107) sts((c + 1) & 1);
        __syncthreads();
    }

    float* E = dsm;
    const int rq = lane >> 2, cq = lane & 3;
#pragma unroll
    for (int mt = 0; mt < 4; mt++)
#pragma unroll
        for (int nt = 0; nt < 4; nt++) {
            int row = wm * 64 + mt * 16 + rq;
            int col = wn * 32 + nt * 8 + 2 * cq;
            E[row * 129 + col]           = acc[mt][nt][0];
            E[row * 129 + col + 1]       = acc[mt][nt][1];
            E[(row + 8) * 129 + col]     = acc[mt][nt][2];
            E[(row + 8) * 129 + col + 1] = acc[mt][nt][3];
        }
    __syncthreads();
    float* ob = out_cl + ((size_t)bb * 4096 + pos0 + ar) * 128;
#pragma unroll
    for (int j4 = 0; j4 < 16; j4++) {
        float4 v; float* pv = (float*)&v;
#pragma unroll
        for (int t = 0; t < 4; t++) {
            int ch = aseg * 64 + j4 * 4 + t;
            float x = E[ar * 129 + ch] + bias[ch];
            pv[t] = __uint_as_float(f2tf(silu(x)));
        }
        *(float4*)(ob + aseg * 64 + j4 * 4) = v;
    }
}

// ---------- mma.sync tf32 transposed conv via octant decomposition ----------
template<int CIN, int COUT, int DIN, int LOGD, int CLOUT>
__launch_bounds__(256)
__global__ void tconv_mma(const float* __restrict__ in_cl, const float* __restrict__ wtr,
                          const float* __restrict__ bias, float* __restrict__ out)
{
    extern __shared__ float dsm[];
    constexpr int NW_N = COUT / 32;
    constexpr int NW_M = 8 / NW_N;
    constexpr int MT = 128 / (NW_M * 16);
    constexpr int SAs = 36;
    constexpr int SBs = COUT + 8;
    constexpr int STG = 128 * SAs + 32 * SBs;
    constexpr int NIC = CIN / 32;
    constexpr int DOUT = 2 * DIN;
    constexpr int BF4 = COUT / 32;

    const int tid = threadIdx.x;
    const int lane = tid & 31, wid = tid >> 5;
    const int wm = wid / NW_N, wn = wid % NW_N;
    const int bb = blockIdx.z;
    const int oct = blockIdx.y;
    const int px = oct & 1, py = (oct >> 1) & 1, pz = (oct >> 2) & 1;
    const int ntx = 2 - px, nty = 2 - py;
    const int nchunks = ntx * nty * (2 - pz) * NIC;
    const int pos0 = blockIdx.x * 128;
    const float* inb = in_cl + (size_t)bb * (DIN * DIN * DIN) * CIN;

    float acc[MT][4][4];
#pragma unroll
    for (int mt = 0; mt < MT; mt++)
#pragma unroll
        for (int nt = 0; nt < 4; nt++)
#pragma unroll
            for (int k = 0; k < 4; k++) acc[mt][nt][k] = 0.f;

    const int ar = tid >> 1, aseg = tid & 1;
    const int pa = pos0 + ar;
    const int gx = pa & (DIN - 1), gy = (pa >> LOGD) & (DIN - 1), gz = pa >> (2 * LOGD);
    const int bk = tid >> 3, bseg = tid & 7;

    float4 ra[4], rb[BF4];

    auto ldg = [&](int c) {
        int tap = c / NIC, ic0 = (c % NIC) * 32;
        int txi = tap % ntx; int r2 = tap / ntx; int tyi = r2 % nty; int tzi = r2 / nty;
        int tx = px ? 1 : txi * 2, ty = py ? 1 : tyi * 2, tz = pz ? 1 : tzi * 2;
        int ix = gx + (px ? 0 : txi - 1);
        int iy = gy + (py ? 0 : tyi - 1);
        int iz = gz + (pz ? 0 : tzi - 1);
        bool valid = (ix >= 0) && (iy >= 0) && (iz >= 0);
        if (valid) {
            const float4* sa = (const float4*)(inb + (size_t)((iz * DIN + iy) * DIN + ix) * CIN
                                               + ic0 + aseg * 16);
            ra[0] = sa[0]; ra[1] = sa[1]; ra[2] = sa[2]; ra[3] = sa[3];
        } else {
            ra[0] = ra[1] = ra[2] = ra[3] = make_float4(0.f, 0.f, 0.f, 0.f);
        }
        int tap27 = tz * 9 + ty * 3 + tx;
        const float4* sb = (const float4*)(wtr + ((size_t)(tap27 * CIN) + ic0 + bk) * COUT
                                           + bseg * (COUT / 8));
#pragma unroll
        for (int j = 0; j < BF4; j++) rb[j] = sb[j];
    };
    auto sts = [&](int s) {
        float* Au = dsm + s * STG;
        float* Bu = Au + 128 * SAs;
#pragma unroll
        for (int j = 0; j < 4; j++)
            *(float4*)(Au + ar * SAs + aseg * 16 + 4 * j) = ra[j];
#pragma unroll
        for (int j = 0; j < BF4; j++)
            *(float4*)(Bu + bk * SBs + bseg * (COUT / 8) + 4 * j) = rb[j];
    };
    auto domma = [&](int s) {
        const uint32_t* Au = (const uint32_t*)(dsm + s * STG);
        const uint32_t* Bu = Au + 128 * SAs;
        const int rq = lane >> 2, cq = lane & 3;
#pragma unroll
        for (int q = 0; q < 4; q++) {
            const int kk = q * 8 + cq;
            uint32_t af[MT][4], bf[4][2];
#pragma unroll
            for (int mt = 0; mt < MT; mt++) {
                int row = wm * (MT * 16) + mt * 16 + rq;
                af[mt][0] = Au[row * SAs + kk];
                af[mt][1] = Au[(row + 8) * SAs + kk];
                af[mt][2] = Au[row * SAs + kk + 4];
                af[mt][3] = Au[(row + 8) * SAs + kk + 4];
            }
#pragma unroll
            for (int nt = 0; nt < 4; nt++) {
                int col = wn * 32 + nt * 8 + rq;
                bf[nt][0] = Bu[kk * SBs + col];
                bf[nt][1] = Bu[(kk + 4) * SBs + col];
            }
#pragma unroll
            for (int mt = 0; mt < MT; mt++)
#pragma unroll
                for (int nt = 0; nt < 4; nt++)
                    mma_tf32(acc[mt][nt], af[mt], bf[nt]);
        }
    };

    ldg(0); sts(0); __syncthreads();
#pragma unroll 1
    for (int c = 0; c < nchunks; c++) {
        if (c + 1 < nchunks) ldg(c + 1);
        domma(c & 1);
        if (c + 1 < nchunks) sts((c + 1) & 1);
        __syncthreads();
    }

    float* E = dsm;
    const int rq = lane >> 2, cq = lane & 3;
    if (CLOUT) {
        constexpr int SE = COUT + 1;
#pragma unroll
        for (int mt = 0; mt < MT; mt++)
#pragma unroll
            for (int nt = 0; nt < 4; nt++) {
                int row = wm * (MT * 16) + mt * 16 + rq;
                int col = wn * 32 + nt * 8 + 2 * cq;
                E[row * SE + col]           = acc[mt][nt][0];
                E[row * SE + col + 1]       = acc[mt][nt][1];
                E[(row + 8) * SE + col]     = acc[mt][nt][2];
                E[(row + 8) * SE + col + 1] = acc[mt][nt][3];
            }
        __syncthreads();
        int opos = ((2 * gz + pz) * DOUT + (2 * gy + py)) * DOUT + (2 * gx + px);
        float* ob = out + ((size_t)bb * DOUT * DOUT * DOUT + opos) * COUT;
#pragma unroll
        for (int j4 = 0; j4 < COUT / 8; j4++) {
            float4 v; float* pv = (float*)&v;
#pragma unroll
            for (int t = 0; t < 4; t++) {
                int ch = aseg * (COUT / 2) + j4 * 4 + t;
                float x = E[ar * SE + ch] + bias[ch];
                pv[t] = __uint_as_float(f2tf(silu(x)));
            }
            *(float4*)(ob + aseg * (COUT / 2) + j4 * 4) = v;
        }
    } else {
        constexpr int SE = 36;
#pragma unroll
        for (int mt = 0; mt < MT; mt++)
#pragma unroll
            for (int nt = 0; nt < 4; nt++) {
                int row = wm * (MT * 16) + mt * 16 + rq;
                int col = nt * 8 + 2 * cq;
                E[row * SE + col]           = acc[mt][nt][0];
                E[row * SE + col + 1]       = acc[mt][nt][1];
                E[(row + 8) * SE + col]     = acc[mt][nt][2];
                E[(row + 8) * SE + col + 1] = acc[mt][nt][3];
            }
        __syncthreads();
        int ch = tid >> 3;
        float bv = bias[ch];
        float* ob = out + ((size_t)bb * COUT + ch) * (DOUT * DOUT * DOUT);
#pragma unroll
        for (int j = 0; j < 16; j++) {
            int p = (tid & 7) + 8 * j;
            int pp = pos0 + p;
            int hx = pp & (DIN - 1), hy = (pp >> LOGD) & (DIN - 1), hz = pp >> (2 * LOGD);
            int opos = ((2 * hz + pz) * DOUT + (2 * hy + py)) * DOUT + (2 * hx + px);
            ob[opos] = silu(E[p * SE + ch] + bv);
        }
    }
}

// ---------------- input dtype probe ----------------
__global__ void initflag_kernel() { g_flags = 0; g_nnz = 0; }

__global__ void scan_kernel(const unsigned int* __restrict__ xw) {
    int base = blockIdx.x * 256 + threadIdx.x;
    unsigned int f = 0, u = 0;
#pragma unroll
    for (int j = 0; j < 16; j++) {
        unsigned int w = xw[base + j * 1048576];
        f |= (w & 0xFEFEFEFEu);
        u |= (w & 0x01010100u);
    }
    int bits = (f ? 1 : 0) | (u ? 2 : 0);
    if (bits) atomicOr(&g_flags, bits);
}

// ---------------- bit pack ----------------
__global__ void pack_kernel(const unsigned char* __restrict__ xb, float* __restrict__ mc) {
    int i = blockIdx.x * 256 + threadIdx.x;
    if (i >= N_MC) return;
    int k  = i & 63;
    int j  = (i >> 6) & 63;
    int zi = (i >> 12) & 63;
    int c  = (i >> 18) & 7;
    int b  = i >> 21;
    int a   = c >> 1;
    int bb0 = (2 * c) & 3;
    int base = (((b * 256) + 4 * zi + a) * 256 + 4 * j + bb0) * 256 + 4 * k;
    int s = 0;
    int flags = g_flags;
    if (flags & 1) {
        const float* xf = (const float*)xb;
        float4 f0 = *(const float4*)(xf + base);
        float4 f1 = *(const float4*)(xf + base + 256);
        if (f0.x != 0.f) s |= 1;   if (f0.y != 0.f) s |= 2;
        if (f0.z != 0.f) s |= 4;   if (f0.w != 0.f) s |= 8;
        if (f1.x != 0.f) s |= 16;  if (f1.y != 0.f) s |= 32;
        if (f1.z != 0.f) s |= 64;  if (f1.w != 0.f) s |= 128;
    } else if (flags & 2) {
        unsigned int r0 = *(const unsigned int*)(xb + base);
        unsigned int r1 = *(const unsigned int*)(xb + base + 256);
#pragma unroll
        for (int cc = 0; cc < 4; cc++) {
            if ((r0 >> (8 * cc)) & 0xFF) s |= 1 << cc;
            if ((r1 >> (8 * cc)) & 0xFF) s |= 1 << (4 + cc);
        }
    } else {
        const int* xi = (const int*)xb;
        int4 a0 = *(const int4*)(xi + base);
        int4 a1 = *(const int4*)(xi + base + 256);
        if (a0.x) s |= 1;   if (a0.y) s |= 2;
        if (a0.z) s |= 4;   if (a0.w) s |= 8;
        if (a1.x) s |= 16;  if (a1.y) s |= 32;
        if (a1.z) s |= 64;  if (a1.w) s |= 128;
    }
    mc[i] = (float)s * (1.0f / 255.0f);
}

// ---------------- zero-patch mask + nonzero-token compaction ----------------
__global__ void zmask_kernel(const float* __restrict__ mc) {
    int idx = blockIdx.x * 256 + threadIdx.x;
    int tok = idx >> 3, c = idx & 7;
    int p = tok & 4095, b = tok >> 12;
    int zk = p & 15, zj = (p >> 4) & 15, zi = p >> 8;
    bool any = false;
    const float* basep = mc + (((b * 8 + c) * 64 + 4 * zi) * 64 + 4 * zj) * 64 + 4 * zk;
#pragma unroll
    for (int dz = 0; dz < 4; dz++)
#pragma unroll
        for (int dy = 0; dy < 4; dy++) {
            float4 v = *(const float4*)(basep + (dz * 64 + dy) * 64);
            any |= (v.x != 0.f) | (v.y != 0.f) | (v.z != 0.f) | (v.w != 0.f);
        }
    unsigned m = __ballot_sync(0xFFFFFFFFu, any);
    if (c == 0) {
        int sh = threadIdx.x & 24;
        bool nz = ((m >> sh) & 0xFF) != 0;
        g_zmask[tok] = nz ? 0 : 1;
        if (nz) { int pp = atomicAdd(&g_nnz, 1); g_toklist[pp] = tok; }
    }
}

// ---------------- SIMT 3x3x3 conv, stride 1, XW=8, OCW=4, LDS.128 weights ----------------
template<int CIN>
__launch_bounds__(256)
__global__ void conv_s1_x8(const float* __restrict__ in, const float* __restrict__ wt,
                           const float* __restrict__ bias, float* __restrict__ out,
                           int Din, int COUT, int act)
{
    extern __shared__ float sw[];   // [CIN*27][4]
    const int oc0 = blockIdx.y * 4;
    const int b   = blockIdx.z;
    for (int idx = threadIdx.x; idx < CIN * 27 * 4; idx += 256) {
        int r = idx >> 2, o = idx & 3;
        sw[idx] = wt[(oc0 + o) * (CIN * 27) + r];
    }
    __syncthreads();
    const int spatial = Din * Din * Din;
    int gpos = (blockIdx.x * 256 + threadIdx.x) * 8;
    if (gpos >= spatial) return;
    int x0 = gpos % Din; int t1 = gpos / Din; int y = t1 % Din; int z = t1 / Din;

    float acc[4][8];
#pragma unroll
    for (int o = 0; o < 4; o++) {
        float bv = bias[oc0 + o];
#pragma unroll
        for (int xx = 0; xx < 8; xx++) acc[o][xx] = bv;
    }
    const float* inb = in + b * CIN * Din * Din * Din;
#pragma unroll 1
    for (int ic = 0; ic < CIN; ic++) {
        const float* inc = inb + ic * Din * Din * Din;
#pragma unroll 1
        for (int tz = 0; tz < 3; tz++) {
            int iz = z + tz - 1; if ((unsigned)iz >= (unsigned)Din) continue;
#pragma unroll
            for (int ty = 0; ty < 3; ty++) {
                int iy = y + ty - 1; if ((unsigned)iy >= (unsigned)Din) continue;
                const float* row = inc + (iz * Din + iy) * Din;
                float4 v0 = *(const float4*)(row + x0);
                float4 v1 = *(const float4*)(row + x0 + 4);
                float r[10];
                r[0] = (x0 > 0) ? row[x0 - 1] : 0.f;
                r[1] = v0.x; r[2] = v0.y; r[3] = v0.z; r[4] = v0.w;
                r[5] = v1.x; r[6] = v1.y; r[7] = v1.z; r[8] = v1.w;
                r[9] = (x0 + 8 < Din) ? row[x0 + 8] : 0.f;
                const float* swp = sw + (ic * 27 + tz * 9 + ty * 3) * 4;
#pragma unroll
                for (int tx = 0; tx < 3; tx++) {
                    float w[4];
                    *(float4*)w = *(const float4*)(swp + tx * 4);
#pragma unroll
                    for (int o = 0; o < 4; o++)
#pragma unroll
                        for (int xx = 0; xx < 8; xx++) acc[o][xx] += w[o] * r[xx + tx];
                }
            }
        }
    }
    int obase0 = (z * Din + y) * Din + x0;
#pragma unroll
    for (int o = 0; o < 4; o++) {
        float s[8];
#pragma unroll
        for (int xx = 0; xx < 8; xx++) {
            s[xx] = acc[o][xx];
            if (act) s[xx] = silu(s[xx]);
        }
        float* op = out + (size_t)(b * COUT + oc0 + o) * spatial + obase0;
        *(float4*)op = make_float4(s[0], s[1], s[2], s[3]);
        *(float4*)(op + 4) = make_float4(s[4], s[5], s[6], s[7]);
    }
}

// ---------------- SIMT 3x3x3 conv, stride 2, XW=8, OCW=4, LDS.128 weights ----------------
template<int CIN>
__launch_bounds__(256)
__global__ void conv_s2_x8(const float* __restrict__ in, const float* __restrict__ wt,
                           const float* __restrict__ bias, float* __restrict__ out,
                           int Din, int COUT, int act)
{
    extern __shared__ float sw[];   // [CIN*27][4]
    const int Dout = Din >> 1;
    const int oc0 = blockIdx.y * 4;
    const int b   = blockIdx.z;
    for (int idx = threadIdx.x; idx < CIN * 27 * 4; idx += 256) {
        int r = idx >> 2, o = idx & 3;
        sw[idx] = wt[(oc0 + o) * (CIN * 27) + r];
    }
    __syncthreads();
    const int spatial = Dout * Dout * Dout;
    int gpos = (blockIdx.x * 256 + threadIdx.x) * 8;
    if (gpos >= spatial) return;
    int x0 = gpos % Dout; int t1 = gpos / Dout; int y = t1 % Dout; int z = t1 / Dout;

    float acc[4][8];
#pragma unroll
    for (int o = 0; o < 4; o++) {
        float bv = bias[oc0 + o];
#pragma unroll
        for (int xx = 0; xx < 8; xx++) acc[o][xx] = bv;
    }
    const float* inb = in + b * CIN * Din * Din * Din;
#pragma unroll 1
    for (int ic = 0; ic < CIN; ic++) {
        const float* inc = inb + ic * Din * Din * Din;
#pragma unroll 1
        for (int tz = 0; tz < 3; tz++) {
            int iz = 2 * z + tz - 1; if ((unsigned)iz >= (unsigned)Din) continue;
#pragma unroll
            for (int ty = 0; ty < 3; ty++) {
                int iy = 2 * y + ty - 1; if ((unsigned)iy >= (unsigned)Din) continue;
                const float* row = inc + (iz * Din + iy) * Din;
                // inputs 2*x0-1 .. 2*x0+15 (17 values); right side always in-bounds
                float r[17];
                r[0] = (x0 > 0) ? row[2 * x0 - 1] : 0.f;
                float4 v0 = *(const float4*)(row + 2 * x0);
                float4 v1 = *(const float4*)(row + 2 * x0 + 4);
                float4 v2 = *(const float4*)(row + 2 * x0 + 8);
                float4 v3 = *(const float4*)(row + 2 * x0 + 12);
                r[1] = v0.x;  r[2] = v0.y;  r[3] = v0.z;  r[4] = v0.w;
                r[5] = v1.x;  r[6] = v1.y;  r[7] = v1.z;  r[8] = v1.w;
                r[9] = v2.x;  r[10] = v2.y; r[11] = v2.z; r[12] = v2.w;
                r[13] = v3.x; r[14] = v3.y; r[15] = v3.z; r[16] = v3.w;
                const float* swp = sw + (ic * 27 + tz * 9 + ty * 3) * 4;
#pragma unroll
                for (int tx = 0; tx < 3; tx++) {
                    float w[4];
                    *(float4*)w = *(const float4*)(swp + tx * 4);
#pragma unroll
                    for (int o = 0; o < 4; o++)
#pragma unroll
                        for (int xx = 0; xx < 8; xx++) acc[o][xx] += w[o] * r[2 * xx + tx];
                }
            }
        }
    }
    int obase0 = (z * Dout + y) * Dout + x0;
#pragma unroll
    for (int o = 0; o < 4; o++) {
        float s[8];
#pragma unroll
        for (int xx = 0; xx < 8; xx++) {
            s[xx] = acc[o][xx];
            if (act) s[xx] = silu(s[xx]);
        }
        float* op = out + (size_t)(b * COUT + oc0 + o) * spatial + obase0;
        *(float4*)op = make_float4(s[0], s[1], s[2], s[3]);
        *(float4*)(op + 4) = make_float4(s[4], s[5], s[6], s[7]);
    }
}

// ---------------- 1x1x1 convs ----------------
__global__ void quant_conv_kernel(const float* __restrict__ h, const float* __restrict__ w,
                                  const float* __restrict__ bias, float* __restrict__ seq)
{
    int i = blockIdx.x * 256 + threadIdx.x;
    if (i >= NTOK * EDIM) return;
    int e = i & 15; int p = (i >> 4) & 4095; int b = i >> 16;
    float acc = bias[e];
    const float* hp = h + (b * 128) * 4096 + p;
    const float* wp = w + e * 128;
#pragma unroll 8
    for (int ic = 0; ic < 128; ic++) acc += wp[ic] * hp[ic * 4096];
    seq[i] = acc;
}

__global__ void post_quant_cl_kernel(const float* __restrict__ q, const float* __restrict__ w,
                                     const float* __restrict__ bias, float* __restrict__ out_cl)
{
    int i = blockIdx.x * 256 + threadIdx.x;
    if (i >= BATCH * 4096 * 128) return;
    int oc = i & 127; int p = (i >> 7) & 4095; int b = i >> 19;
    float acc = bias[oc];
    const float* qp = q + (b * EDIM) * 4096 + p;
    const float* wp = w + oc * EDIM;
#pragma unroll
    for (int e = 0; e < EDIM; e++) acc += wp[e] * qp[e * 4096];
    out_cl[i] = __uint_as_float(f2tf(acc));
}

// ---------------- VQ ----------------
__global__ void cnorm_kernel(const float* __restrict__ cb) {
    int k = blockIdx.x * 128 + threadIdx.x;
    if (k < KCODE) {
        float s = 0.f;
#pragma unroll
        for (int e = 0; e < EDIM; e++) { float c = cb[k * EDIM + e]; s += c * c; }
        g_cnorm[k] = s;
    }
}

__global__ void vq_kernel(const float* __restrict__ seq, const float* __restrict__ cb)
{
    __shared__ float stok[32 * 16];
    __shared__ float sc[128 * 16];
    __shared__ float sn[128];
    __shared__ float rd[128];
    __shared__ int   ri[128];
    const int nnz = g_nnz;
    const int tok0 = blockIdx.x * 32;
    if (tok0 >= nnz) return;
    const int tid = threadIdx.x;
    for (int i = tid; i < 512; i += 128) {
        int ti = tok0 + (i >> 4);
        int tok = g_toklist[ti < nnz ? ti : (nnz - 1)];
        stok[i] = seq[tok * 16 + (i & 15)];
    }
    __syncthreads();
    const int t = tid & 31, g = tid >> 5;
    float s[16];
#pragma unroll
    for (int e = 0; e < 16; e++) s[e] = stok[t * 16 + e];
    float best = 3.4e38f; int bidx = 0;
    for (int tile = 0; tile < KCODE / 128; tile++) {
        __syncthreads();
        for (int i = tid; i < 512; i += 128)
            *(float4*)&sc[i * 4] = *(const float4*)&cb[tile * 2048 + i * 4];
        if (tid < 128) sn[tid] = g_cnorm[tile * 128 + tid];
        __syncthreads();
#pragma unroll 4
        for (int kk = g; kk < 128; kk += 4) {
            const float4* c4 = (const float4*)&sc[kk * 16];
            float4 c0 = c4[0], c1 = c4[1], c2 = c4[2], c3 = c4[3];
            float dot = c0.x * s[0] + c0.y * s[1] + c0.z * s[2] + c0.w * s[3]
                      + c1.x * s[4] + c1.y * s[5] + c1.z * s[6] + c1.w * s[7]
                      + c2.x * s[8] + c2.y * s[9] + c2.z * s[10] + c2.w * s[11]
                      + c3.x * s[12] + c3.y * s[13] + c3.z * s[14] + c3.w * s[15];
            float d = sn[kk] - 2.f * dot;
            if (d < best) { best = d; bidx = tile * 128 + kk; }
        }
    }
    rd[tid] = best; ri[tid] = bidx;
    __syncthreads();
    if (g == 0) {
        for (int gg = 1; gg < 4; gg++) {
            float d = rd[gg * 32 + t]; int k = ri[gg * 32 + t];
            if (d < best || (d == best && k < bidx)) { best = d; bidx = k; }
        }
        int ti = tok0 + t;
        if (ti < nnz) g_idx[g_toklist[ti]] = bidx;
    }
}

// ---------------- commit loss ----------------
__global__ void commit_kernel(const float* __restrict__ seq, const float* __restrict__ cb)
{
    __shared__ float sh[128];
    int t = blockIdx.x * 128 + threadIdx.x;
    float v = 0.f;
    if (!g_zmask[t]) {
        const float* s = seq + t * 16;
        const float* c = cb + g_idx[t] * 16;
        float a = 0.f;
#pragma unroll
        for (int e = 0; e < 16; e++) { float d = c[e] - s[e]; a += d * d; }
        v = a * (1.f / 16.f);
    }
    sh[threadIdx.x] = v; __syncthreads();
    for (int st = 64; st; st >>= 1) {
        if (threadIdx.x < st) sh[threadIdx.x] += sh[threadIdx.x + st];
        __syncthreads();
    }
    if (threadIdx.x == 0) g_part[blockIdx.x] = sh[0];
}

__global__ void commit_final(float* __restrict__ out) {
    if (threadIdx.x == 0) {
        float s = 0.f;
        for (int i = 0; i < 128; i++) s += g_part[i];
        out[0] = 0.25f * s / 16384.f;
    }
}

__global__ void fullidx_kernel(float* __restrict__ out) {
    int i = blockIdx.x * 256 + threadIdx.x;
    if (i < NTOK) out[i] = g_zmask[i] ? 0.f : (float)(g_idx[i] + 1);
}

__global__ void qbuild_kernel(const float* __restrict__ cb, const float* __restrict__ rep,
                              const float* __restrict__ pos)
{
    int i = blockIdx.x * 256 + threadIdx.x;
    if (i >= BATCH * EDIM * 4096) return;
    int p = i & 4095; int e = (i >> 12) & 15; int b = i >> 16;
    int tok = (b << 12) + p;
    float v = g_zmask[tok] ? rep[e] : cb[g_idx[tok] * 16 + e];
    g_q[i] = v + pos[e * 4096 + p];
}

// ---------------- launch ----------------
extern "C" void kernel_launch(void* const* d_in, const int* in_sizes, int n_in,
                              void* d_out_, int out_size)
{
    const unsigned char* x = (const unsigned char*)d_in[0];
    const float* enc_in_w  = (const float*)d_in[1];
    const float* enc_in_b  = (const float*)d_in[2];
    const float* enc_d1_w  = (const float*)d_in[3];
    const float* enc_d1_b  = (const float*)d_in[4];
    const float* enc_d2_w  = (const float*)d_in[5];
    const float* enc_d2_b  = (const float*)d_in[6];
    const float* enc_out_w = (const float*)d_in[7];
    const float* enc_out_b = (const float*)d_in[8];
    const float* quant_w   = (const float*)d_in[9];
    const float* quant_b   = (const float*)d_in[10];
    const float* codebook  = (const float*)d_in[11];
    const float* rep_tok   = (const float*)d_in[12];
    const float* pos_emb   = (const float*)d_in[13];
    const float* pq_w      = (const float*)d_in[14];
    const float* pq_b      = (const float*)d_in[15];
    const float* dec_in_w  = (const float*)d_in[16];
    const float* dec_in_b  = (const float*)d_in[17];
    const float* dec_u1_w  = (const float*)d_in[18];
    const float* dec_u1_b  = (const float*)d_in[19];
    const float* dec_u2_w  = (const float*)d_in[20];
    const float* dec_u2_b  = (const float*)d_in[21];
    const float* dec_out_w = (const float*)d_in[22];
    const float* dec_out_b = (const float*)d_in[23];
    float* out = (float*)d_out_;

    float *pA, *pB, *pC, *pD, *pSeq, *pQ, *pCL, *pW, *pW1, *pW2;
    cudaGetSymbolAddress((void**)&pA, g_bufA);
    cudaGetSymbolAddress((void**)&pB, g_bufB);
    cudaGetSymbolAddress((void**)&pC, g_bufC);
    cudaGetSymbolAddress((void**)&pD, g_bufD);
    cudaGetSymbolAddress((void**)&pSeq, g_seq);
    cudaGetSymbolAddress((void**)&pQ, g_q);
    cudaGetSymbolAddress((void**)&pCL, g_cl);
    cudaGetSymbolAddress((void**)&pW, g_wt);
    cudaGetSymbolAddress((void**)&pW1, g_wt1);
    cudaGetSymbolAddress((void**)&pW2, g_wt2);
    cudaFuncSetAttribute(conv_s1_x8<128>, cudaFuncAttributeMaxDynamicSharedMemorySize, 65536);
    cudaFuncSetAttribute(conv_mma_dec,    cudaFuncAttributeMaxDynamicSharedMemorySize, 2 * STAGE_F * 4);
    cudaFuncSetAttribute((tconv_mma<128, 64, 16, 4, 1>), cudaFuncAttributeMaxDynamicSharedMemorySize, 55296);
    cudaFuncSetAttribute((tconv_mma<64, 32, 32, 5, 0>),  cudaFuncAttributeMaxDynamicSharedMemorySize, 47104);

    float* mc = out + OFF_MC;
    dim3 blk(256);

    initflag_kernel<<<1, 1>>>();
    scan_kernel<<<4096, 256>>>((const unsigned int*)x);
    pack_kernel<<<N_MC / 256, 256>>>(x, mc);

    // encoder (fp32 SIMT — VQ index exactness)
    conv_s1_x8<8><<<dim3(128, 8, 4), blk, 8 * 27 * 16>>>(mc, enc_in_w, enc_in_b, pA, 64, 32, 1);
    zmask_kernel<<<512, 256>>>(mc);
    conv_s2_x8<32><<<dim3(16, 16, 4), blk, 32 * 27 * 16>>>(pA, enc_d1_w, enc_d1_b, pB, 64, 64, 1);
    conv_s2_x8<64><<<dim3(2, 32, 4), blk, 64 * 27 * 16>>>(pB, enc_d2_w, enc_d2_b, pC, 32, 128, 1);
    conv_s1_x8<128><<<dim3(2, 32, 4), blk, 128 * 27 * 16>>>(pC, enc_out_w, enc_out_b, pD, 16, 128, 0);

    wtrans2<<<1728, 256>>>(dec_in_w, pW, 128, 128);
    wtrans2<<<864, 256>>>(dec_u1_w, pW1, 128, 64);
    wtrans2<<<216, 256>>>(dec_u2_w, pW2, 64, 32);

    // quantization path
    cnorm_kernel<<<KCODE / 128, 128>>>(codebook);
    quant_conv_kernel<<<(NTOK * EDIM) / 256, 256>>>(pD, quant_w, quant_b, pSeq);
    vq_kernel<<<NTOK / 32, 128>>>(pSeq, codebook);
    commit_kernel<<<NTOK / 128, 128>>>(pSeq, codebook);
    commit_final<<<1, 1>>>(out + OFF_COMMIT);
    fullidx_kernel<<<NTOK / 256, 256>>>(out + OFF_IDX);
    qbuild_kernel<<<(BATCH * EDIM * 4096) / 256, 256>>>(codebook, rep_tok, pos_emb);
    post_quant_cl_kernel<<<(BATCH * 4096 * 128) / 256, 256>>>(pQ, pq_w, pq_b, pCL);

    // decoder: dec_in + both tconvs on tensor cores (tf32), dec_out SIMT
    conv_mma_dec<<<dim3(32, 1, 4), 256, 2 * STAGE_F * 4>>>(pCL, dec_in_b, pD);
    tconv_mma<128, 64, 16, 4, 1><<<dim3(32, 8, 4), 256, 55296>>>(pD, pW1, dec_u1_b, pB);
    tconv_mma<64, 32, 32, 5, 0><<<dim3(256, 8, 4), 256, 47104>>>(pB, pW2, dec_u2_b, pA);
    conv_s1_x8<32><<<dim3(128, 2, 4), blk, 32 * 27 * 16>>>(pA, dec_out_w, dec_out_b, out, 64, 8, 0);
}

// round 10
// speedup vs baseline: 1.1396x; 1.1396x over previous
#include <cuda_runtime.h>
#include <math.h>
#include <cstdint>

// ---------------- problem constants ----------------
#define BATCH 4
#define D64   64
#define D32   32
#define D16   16
#define NTOK  (BATCH*4096)
#define EDIM  16
#define KCODE 8192
#define N_MC  (BATCH*8*D64*D64*D64)
#define OFF_MC     8388608
#define OFF_COMMIT 16777216
#define OFF_IDX    16777217

// ---------------- device scratch ----------------
__device__ float g_bufA[BATCH*32*D64*D64*D64];
__device__ float g_bufB[BATCH*64*D32*D32*D32];
__device__ float g_bufC[BATCH*128*D16*D16*D16];
__device__ float g_bufD[BATCH*128*D16*D16*D16];
__device__ float g_seq[NTOK*EDIM];
__device__ float g_q[BATCH*EDIM*4096];
__device__ float g_cl[BATCH*4096*128];
__device__ float g_wt [27*128*128];
__device__ float g_wt1[27*128*64];
__device__ float g_wt2[27*64*32];
__device__ float g_cnorm[KCODE];
__device__ float g_part[128];
__device__ int   g_idx[NTOK];
__device__ unsigned char g_zmask[NTOK];
__device__ int   g_flags;
__device__ int   g_nnz;
__device__ int   g_toklist[NTOK];

__device__ __forceinline__ float silu(float v) { return v * __frcp_rn(1.f + __expf(-v)); }

__device__ __forceinline__ uint32_t f2tf(float f) {
    uint32_t r; asm("cvt.rna.tf32.f32 %0, %1;" : "=r"(r) : "f"(f)); return r;
}
__device__ __forceinline__ void mma_tf32(float* d, const uint32_t* a, const uint32_t* b) {
    asm volatile("mma.sync.aligned.m16n8k8.row.col.f32.tf32.tf32.f32 "
                 "{%0,%1,%2,%3}, {%4,%5,%6,%7}, {%8,%9}, {%0,%1,%2,%3};"
                 : "+f"(d[0]), "+f"(d[1]), "+f"(d[2]), "+f"(d[3])
                 : "r"(a[0]), "r"(a[1]), "r"(a[2]), "r"(a[3]), "r"(b[0]), "r"(b[1]));
}

// -------- weight transform: w[OC][IC][27] -> dst[tap][ic][oc], tf32-rounded --------
__global__ void wtrans2(const float* __restrict__ w, float* __restrict__ dst, int IC, int OC) {
    int i = blockIdx.x * 256 + threadIdx.x;
    int total = 27 * IC * OC;
    if (i >= total) return;
    int tap = i / (IC * OC); int rem = i % (IC * OC); int ic = rem / OC; int oc = rem % OC;
    dst[i] = __uint_as_float(f2tf(w[(oc * IC + ic) * 27 + tap]));
}

// ---------- mma.sync tf32 implicit-GEMM 3x3x3 conv (128ch -> 128ch, 16^3) ----------
#define SA 36
#define SB 136
#define STAGE_F (128*SA + 32*SB)

__launch_bounds__(256)
__global__ void conv_mma_dec(const float* __restrict__ in_cl, const float* __restrict__ bias,
                             float* __restrict__ out_cl)
{
    extern __shared__ float dsm[];
    const int tid = threadIdx.x;
    const int lane = tid & 31, wid = tid >> 5;
    const int wm = wid >> 2, wn = wid & 3;
    const int bb = blockIdx.z;
    const int pos0 = blockIdx.x * 128;
    const float* inb = in_cl + (size_t)bb * 4096 * 128;

    float acc[4][4][4];
#pragma unroll
    for (int mt = 0; mt < 4; mt++)
#pragma unroll
        for (int nt = 0; nt < 4; nt++)
#pragma unroll
            for (int k = 0; k < 4; k++) acc[mt][nt][k] = 0.f;

    const int ar = tid >> 1, aseg = tid & 1;
    const int apos = pos0 + ar;
    const int ax = apos & 15, ay = (apos >> 4) & 15, az = apos >> 8;
    const int bk = tid >> 3, bseg = tid & 7;

    float4 ra[4], rb[4];
    auto ldg = [&](int c) {
        int tap = c >> 2, ic0 = (c & 3) * 32;
        int tz = tap / 9, ty = (tap / 3) % 3, tx = tap % 3;
        int xx = ax + tx - 1, yy = ay + ty - 1, zz = az + tz - 1;
        bool valid = ((unsigned)xx < 16u) & ((unsigned)yy < 16u) & ((unsigned)zz < 16u);
        if (valid) {
            const float4* sa = (const float4*)(inb + (size_t)((zz * 16 + yy) * 16 + xx) * 128
                                               + ic0 + aseg * 16);
            ra[0] = sa[0]; ra[1] = sa[1]; ra[2] = sa[2]; ra[3] = sa[3];
        } else {
            ra[0] = ra[1] = ra[2] = ra[3] = make_float4(0.f, 0.f, 0.f, 0.f);
        }
        const float4* sb = (const float4*)(g_wt + (size_t)(tap * 128 + ic0 + bk) * 128
                                           + bseg * 16);
        rb[0] = sb[0]; rb[1] = sb[1]; rb[2] = sb[2]; rb[3] = sb[3];
    };
    auto sts = [&](int s) {
        float* Au = dsm + s * STAGE_F;
        float* Bu = Au + 128 * SA;
#pragma unroll
        for (int j = 0; j < 4; j++) {
            *(float4*)(Au + ar * SA + aseg * 16 + 4 * j) = ra[j];
            *(float4*)(Bu + bk * SB + bseg * 16 + 4 * j) = rb[j];
        }
    };
    auto domma = [&](int s) {
        const uint32_t* Au = (const uint32_t*)(dsm + s * STAGE_F);
        const uint32_t* Bu = Au + 128 * SA;
        const int rq = lane >> 2, cq = lane & 3;
#pragma unroll
        for (int q = 0; q < 4; q++) {
            const int kk = q * 8 + cq;
            uint32_t af[4][4], bf[4][2];
#pragma unroll
            for (int mt = 0; mt < 4; mt++) {
                int row = wm * 64 + mt * 16 + rq;
                af[mt][0] = Au[row * SA + kk];
                af[mt][1] = Au[(row + 8) * SA + kk];
                af[mt][2] = Au[row * SA + kk + 4];
                af[mt][3] = Au[(row + 8) * SA + kk + 4];
            }
#pragma unroll
            for (int nt = 0; nt < 4; nt++) {
                int col = wn * 32 + nt * 8 + rq;
                bf[nt][0] = Bu[kk * SB + col];
                bf[nt][1] = Bu[(kk + 4) * SB + col];
            }
#pragma unroll
            for (int mt = 0; mt < 4; mt++)
#pragma unroll
                for (int nt = 0; nt < 4; nt++)
                    mma_tf32(acc[mt][nt], af[mt], bf[nt]);
        }
    };

    ldg(0); sts(0); __syncthreads();
#pragma unroll 1
    for (int c = 0; c < 108; c++) {
        if (c < 107) ldg(c + 1);
        domma(c & 1);
        if (c < 107) sts((c + 1) & 1);
        __syncthreads();
    }

    float* E = dsm;
    const int rq = lane >> 2, cq = lane & 3;
#pragma unroll
    for (int mt = 0; mt < 4; mt++)
#pragma unroll
        for (int nt = 0; nt < 4; nt++) {
            int row = wm * 64 + mt * 16 + rq;
            int col = wn * 32 + nt * 8 + 2 * cq;
            E[row * 129 + col]           = acc[mt][nt][0];
            E[row * 129 + col + 1]       = acc[mt][nt][1];
            E[(row + 8) * 129 + col]     = acc[mt][nt][2];
            E[(row + 8) * 129 + col + 1] = acc[mt][nt][3];
        }
    __syncthreads();
    float* ob = out_cl + ((size_t)bb * 4096 + pos0 + ar) * 128;
#pragma unroll
    for (int j4 = 0; j4 < 16; j4++) {
        float4 v; float* pv = (float*)&v;
#pragma unroll
        for (int t = 0; t < 4; t++) {
            int ch = aseg * 64 + j4 * 4 + t;
            float x = E[ar * 129 + ch] + bias[ch];
            pv[t] = __uint_as_float(f2tf(silu(x)));
        }
        *(float4*)(ob + aseg * 64 + j4 * 4) = v;
    }
}

// ---------- mma.sync tf32 transposed conv via octant decomposition ----------
template<int CIN, int COUT, int DIN, int LOGD, int CLOUT>
__launch_bounds__(256)
__global__ void tconv_mma(const float* __restrict__ in_cl, const float* __restrict__ wtr,
                          const float* __restrict__ bias, float* __restrict__ out)
{
    extern __shared__ float dsm[];
    constexpr int NW_N = COUT / 32;
    constexpr int NW_M = 8 / NW_N;
    constexpr int MT = 128 / (NW_M * 16);
    constexpr int SAs = 36;
    constexpr int SBs = COUT + 8;
    constexpr int STG = 128 * SAs + 32 * SBs;
    constexpr int NIC = CIN / 32;
    constexpr int DOUT = 2 * DIN;
    constexpr int BF4 = COUT / 32;

    const int tid = threadIdx.x;
    const int lane = tid & 31, wid = tid >> 5;
    const int wm = wid / NW_N, wn = wid % NW_N;
    const int bb = blockIdx.z;
    const int oct = blockIdx.y;
    const int px = oct & 1, py = (oct >> 1) & 1, pz = (oct >> 2) & 1;
    const int ntx = 2 - px, nty = 2 - py;
    const int nchunks = ntx * nty * (2 - pz) * NIC;
    const int pos0 = blockIdx.x * 128;
    const float* inb = in_cl + (size_t)bb * (DIN * DIN * DIN) * CIN;

    float acc[MT][4][4];
#pragma unroll
    for (int mt = 0; mt < MT; mt++)
#pragma unroll
        for (int nt = 0; nt < 4; nt++)
#pragma unroll
            for (int k = 0; k < 4; k++) acc[mt][nt][k] = 0.f;

    const int ar = tid >> 1, aseg = tid & 1;
    const int pa = pos0 + ar;
    const int gx = pa & (DIN - 1), gy = (pa >> LOGD) & (DIN - 1), gz = pa >> (2 * LOGD);
    const int bk = tid >> 3, bseg = tid & 7;

    float4 ra[4], rb[BF4];

    auto ldg = [&](int c) {
        int tap = c / NIC, ic0 = (c % NIC) * 32;
        int txi = tap % ntx; int r2 = tap / ntx; int tyi = r2 % nty; int tzi = r2 / nty;
        int tx = px ? 1 : txi * 2, ty = py ? 1 : tyi * 2, tz = pz ? 1 : tzi * 2;
        int ix = gx + (px ? 0 : txi - 1);
        int iy = gy + (py ? 0 : tyi - 1);
        int iz = gz + (pz ? 0 : tzi - 1);
        bool valid = (ix >= 0) && (iy >= 0) && (iz >= 0);
        if (valid) {
            const float4* sa = (const float4*)(inb + (size_t)((iz * DIN + iy) * DIN + ix) * CIN
                                               + ic0 + aseg * 16);
            ra[0] = sa[0]; ra[1] = sa[1]; ra[2] = sa[2]; ra[3] = sa[3];
        } else {
            ra[0] = ra[1] = ra[2] = ra[3] = make_float4(0.f, 0.f, 0.f, 0.f);
        }
        int tap27 = tz * 9 + ty * 3 + tx;
        const float4* sb = (const float4*)(wtr + ((size_t)(tap27 * CIN) + ic0 + bk) * COUT
                                           + bseg * (COUT / 8));
#pragma unroll
        for (int j = 0; j < BF4; j++) rb[j] = sb[j];
    };
    auto sts = [&](int s) {
        float* Au = dsm + s * STG;
        float* Bu = Au + 128 * SAs;
#pragma unroll
        for (int j = 0; j < 4; j++)
            *(float4*)(Au + ar * SAs + aseg * 16 + 4 * j) = ra[j];
#pragma unroll
        for (int j = 0; j < BF4; j++)
            *(float4*)(Bu + bk * SBs + bseg * (COUT / 8) + 4 * j) = rb[j];
    };
    auto domma = [&](int s) {
        const uint32_t* Au = (const uint32_t*)(dsm + s * STG);
        const uint32_t* Bu = Au + 128 * SAs;
        const int rq = lane >> 2, cq = lane & 3;
#pragma unroll
        for (int q = 0; q < 4; q++) {
            const int kk = q * 8 + cq;
            uint32_t af[MT][4], bf[4][2];
#pragma unroll
            for (int mt = 0; mt < MT; mt++) {
                int row = wm * (MT * 16) + mt * 16 + rq;
                af[mt][0] = Au[row * SAs + kk];
                af[mt][1] = Au[(row + 8) * SAs + kk];
                af[mt][2] = Au[row * SAs + kk + 4];
                af[mt][3] = Au[(row + 8) * SAs + kk + 4];
            }
#pragma unroll
            for (int nt = 0; nt < 4; nt++) {
                int col = wn * 32 + nt * 8 + rq;
                bf[nt][0] = Bu[kk * SBs + col];
                bf[nt][1] = Bu[(kk + 4) * SBs + col];
            }
#pragma unroll
            for (int mt = 0; mt < MT; mt++)
#pragma unroll
                for (int nt = 0; nt < 4; nt++)
                    mma_tf32(acc[mt][nt], af[mt], bf[nt]);
        }
    };

    ldg(0); sts(0); __syncthreads();
#pragma unroll 1
    for (int c = 0; c < nchunks; c++) {
        if (c + 1 < nchunks) ldg(c + 1);
        domma(c & 1);
        if (c + 1 < nchunks) sts((c + 1) & 1);
        __syncthreads();
    }

    float* E = dsm;
    const int rq = lane >> 2, cq = lane & 3;
    if (CLOUT) {
        constexpr int SE = COUT + 1;
#pragma unroll
        for (int mt = 0; mt < MT; mt++)
#pragma unroll
            for (int nt = 0; nt < 4; nt++) {
                int row = wm * (MT * 16) + mt * 16 + rq;
                int col = wn * 32 + nt * 8 + 2 * cq;
                E[row * SE + col]           = acc[mt][nt][0];
                E[row * SE + col + 1]       = acc[mt][nt][1];
                E[(row + 8) * SE + col]     = acc[mt][nt][2];
                E[(row + 8) * SE + col + 1] = acc[mt][nt][3];
            }
        __syncthreads();
        int opos = ((2 * gz + pz) * DOUT + (2 * gy + py)) * DOUT + (2 * gx + px);
        float* ob = out + ((size_t)bb * DOUT * DOUT * DOUT + opos) * COUT;
#pragma unroll
        for (int j4 = 0; j4 < COUT / 8; j4++) {
            float4 v; float* pv = (float*)&v;
#pragma unroll
            for (int t = 0; t < 4; t++) {
                int ch = aseg * (COUT / 2) + j4 * 4 + t;
                float x = E[ar * SE + ch] + bias[ch];
                pv[t] = __uint_as_float(f2tf(silu(x)));
            }
            *(float4*)(ob + aseg * (COUT / 2) + j4 * 4) = v;
        }
    } else {
        constexpr int SE = 36;
#pragma unroll
        for (int mt = 0; mt < MT; mt++)
#pragma unroll
            for (int nt = 0; nt < 4; nt++) {
                int row = wm * (MT * 16) + mt * 16 + rq;
                int col = nt * 8 + 2 * cq;
                E[row * SE + col]           = acc[mt][nt][0];
                E[row * SE + col + 1]       = acc[mt][nt][1];
                E[(row + 8) * SE + col]     = acc[mt][nt][2];
                E[(row + 8) * SE + col + 1] = acc[mt][nt][3];
            }
        __syncthreads();
        int ch = tid >> 3;
        float bv = bias[ch];
        float* ob = out + ((size_t)bb * COUT + ch) * (DOUT * DOUT * DOUT);
#pragma unroll
        for (int j = 0; j < 16; j++) {
            int p = (tid & 7) + 8 * j;
            int pp = pos0 + p;
            int hx = pp & (DIN - 1), hy = (pp >> LOGD) & (DIN - 1), hz = pp >> (2 * LOGD);
            int opos = ((2 * hz + pz) * DOUT + (2 * hy + py)) * DOUT + (2 * hx + px);
            ob[opos] = silu(E[p * SE + ch] + bv);
        }
    }
}

// ---------------- input dtype probe ----------------
__global__ void initflag_kernel() { g_flags = 0; g_nnz = 0; }

__global__ void scan_kernel(const unsigned int* __restrict__ xw) {
    int base = blockIdx.x * 256 + threadIdx.x;
    unsigned int f = 0, u = 0;
#pragma unroll
    for (int j = 0; j < 16; j++) {
        unsigned int w = xw[base + j * 1048576];
        f |= (w & 0xFEFEFEFEu);
        u |= (w & 0x01010100u);
    }
    int bits = (f ? 1 : 0) | (u ? 2 : 0);
    if (bits) atomicOr(&g_flags, bits);
}

// ---------------- bit pack ----------------
__global__ void pack_kernel(const unsigned char* __restrict__ xb, float* __restrict__ mc) {
    int i = blockIdx.x * 256 + threadIdx.x;
    if (i >= N_MC) return;
    int k  = i & 63;
    int j  = (i >> 6) & 63;
    int zi = (i >> 12) & 63;
    int c  = (i >> 18) & 7;
    int b  = i >> 21;
    int a   = c >> 1;
    int bb0 = (2 * c) & 3;
    int base = (((b * 256) + 4 * zi + a) * 256 + 4 * j + bb0) * 256 + 4 * k;
    int s = 0;
    int flags = g_flags;
    if (flags & 1) {
        const float* xf = (const float*)xb;
        float4 f0 = *(const float4*)(xf + base);
        float4 f1 = *(const float4*)(xf + base + 256);
        if (f0.x != 0.f) s |= 1;   if (f0.y != 0.f) s |= 2;
        if (f0.z != 0.f) s |= 4;   if (f0.w != 0.f) s |= 8;
        if (f1.x != 0.f) s |= 16;  if (f1.y != 0.f) s |= 32;
        if (f1.z != 0.f) s |= 64;  if (f1.w != 0.f) s |= 128;
    } else if (flags & 2) {
        unsigned int r0 = *(const unsigned int*)(xb + base);
        unsigned int r1 = *(const unsigned int*)(xb + base + 256);
#pragma unroll
        for (int cc = 0; cc < 4; cc++) {
            if ((r0 >> (8 * cc)) & 0xFF) s |= 1 << cc;
            if ((r1 >> (8 * cc)) & 0xFF) s |= 1 << (4 + cc);
        }
    } else {
        const int* xi = (const int*)xb;
        int4 a0 = *(const int4*)(xi + base);
        int4 a1 = *(const int4*)(xi + base + 256);
        if (a0.x) s |= 1;   if (a0.y) s |= 2;
        if (a0.z) s |= 4;   if (a0.w) s |= 8;
        if (a1.x) s |= 16;  if (a1.y) s |= 32;
        if (a1.z) s |= 64;  if (a1.w) s |= 128;
    }
    mc[i] = (float)s * (1.0f / 255.0f);
}

// ---------------- zero-patch mask + nonzero-token compaction ----------------
__global__ void zmask_kernel(const float* __restrict__ mc) {
    int idx = blockIdx.x * 256 + threadIdx.x;
    int tok = idx >> 3, c = idx & 7;
    int p = tok & 4095, b = tok >> 12;
    int zk = p & 15, zj = (p >> 4) & 15, zi = p >> 8;
    bool any = false;
    const float* basep = mc + (((b * 8 + c) * 64 + 4 * zi) * 64 + 4 * zj) * 64 + 4 * zk;
#pragma unroll
    for (int dz = 0; dz < 4; dz++)
#pragma unroll
        for (int dy = 0; dy < 4; dy++) {
            float4 v = *(const float4*)(basep + (dz * 64 + dy) * 64);
            any |= (v.x != 0.f) | (v.y != 0.f) | (v.z != 0.f) | (v.w != 0.f);
        }
    unsigned m = __ballot_sync(0xFFFFFFFFu, any);
    if (c == 0) {
        int sh = threadIdx.x & 24;
        bool nz = ((m >> sh) & 0xFF) != 0;
        g_zmask[tok] = nz ? 0 : 1;
        if (nz) { int pp = atomicAdd(&g_nnz, 1); g_toklist[pp] = tok; }
    }
}

// ---------------- SIMT 3x3x3 conv (XW=4, OCW=8, vectorized weight LDS) ----------------
template<int CIN, int OCW>
__launch_bounds__(256)
__global__ void conv_k3(const float* __restrict__ in, const float* __restrict__ wt,
                        const float* __restrict__ bias, float* __restrict__ out,
                        int Din, int Dout, int stride, int COUT, int act)
{
    extern __shared__ float sw[];   // [CIN*27][OCW]
    const int oc0 = blockIdx.y * OCW;
    const int b   = blockIdx.z;
    for (int idx = threadIdx.x; idx < CIN * 27 * OCW; idx += 256) {
        int r = idx / OCW, o = idx % OCW;
        sw[idx] = wt[(oc0 + o) * (CIN * 27) + r];
    }
    __syncthreads();
    const int spatial = Dout * Dout * Dout;
    int gpos = (blockIdx.x * 256 + threadIdx.x) * 4;
    if (gpos >= spatial) return;
    int x0 = gpos % Dout; int t1 = gpos / Dout; int y = t1 % Dout; int z = t1 / Dout;

    float acc[OCW][4];
#pragma unroll
    for (int o = 0; o < OCW; o++) {
        float bv = bias[oc0 + o];
#pragma unroll
        for (int xx = 0; xx < 4; xx++) acc[o][xx] = bv;
    }
    const float* inb = in + b * CIN * Din * Din * Din;
    if (stride == 1) {
#pragma unroll 1
        for (int ic = 0; ic < CIN; ic++) {
            const float* inc = inb + ic * Din * Din * Din;
#pragma unroll 1
            for (int tz = 0; tz < 3; tz++) {
                int iz = z + tz - 1; if ((unsigned)iz >= (unsigned)Din) continue;
#pragma unroll
                for (int ty = 0; ty < 3; ty++) {
                    int iy = y + ty - 1; if ((unsigned)iy >= (unsigned)Din) continue;
                    const float* row = inc + (iz * Din + iy) * Din;
                    float4 v = *(const float4*)(row + x0);
                    float r[6];
                    r[0] = (x0 > 0) ? row[x0 - 1] : 0.f;
                    r[1] = v.x; r[2] = v.y; r[3] = v.z; r[4] = v.w;
                    r[5] = (x0 + 4 < Din) ? row[x0 + 4] : 0.f;
                    const float* swp = sw + (ic * 27 + tz * 9 + ty * 3) * OCW;
#pragma unroll
                    for (int tx = 0; tx < 3; tx++) {
                        float w[OCW];
#pragma unroll
                        for (int o4 = 0; o4 < OCW / 4; o4++)
                            *(float4*)(w + 4 * o4) = *(const float4*)(swp + tx * OCW + 4 * o4);
#pragma unroll
                        for (int o = 0; o < OCW; o++)
#pragma unroll
                            for (int xx = 0; xx < 4; xx++) acc[o][xx] += w[o] * r[xx + tx];
                    }
                }
            }
        }
    } else {
#pragma unroll 1
        for (int ic = 0; ic < CIN; ic++) {
            const float* inc = inb + ic * Din * Din * Din;
#pragma unroll 1
            for (int tz = 0; tz < 3; tz++) {
                int iz = 2 * z + tz - 1; if ((unsigned)iz >= (unsigned)Din) continue;
#pragma unroll
                for (int ty = 0; ty < 3; ty++) {
                    int iy = 2 * y + ty - 1; if ((unsigned)iy >= (unsigned)Din) continue;
                    const float* row = inc + (iz * Din + iy) * Din;
                    float4 v0 = *(const float4*)(row + 2 * x0);
                    float4 v1 = *(const float4*)(row + 2 * x0 + 4);
                    float r[9];
                    r[0] = (x0 > 0) ? row[2 * x0 - 1] : 0.f;
                    r[1] = v0.x; r[2] = v0.y; r[3] = v0.z; r[4] = v0.w;
                    r[5] = v1.x; r[6] = v1.y; r[7] = v1.z; r[8] = v1.w;
                    const float* swp = sw + (ic * 27 + tz * 9 + ty * 3) * OCW;
#pragma unroll
                    for (int tx = 0; tx < 3; tx++) {
                        float w[OCW];
#pragma unroll
                        for (int o4 = 0; o4 < OCW / 4; o4++)
                            *(float4*)(w + 4 * o4) = *(const float4*)(swp + tx * OCW + 4 * o4);
#pragma unroll
                        for (int o = 0; o < OCW; o++)
#pragma unroll
                            for (int xx = 0; xx < 4; xx++) acc[o][xx] += w[o] * r[2 * xx + tx];
                    }
                }
            }
        }
    }
    int obase0 = (z * Dout + y) * Dout + x0;
#pragma unroll
    for (int o = 0; o < OCW; o++) {
        float s0 = acc[o][0], s1 = acc[o][1], s2 = acc[o][2], s3 = acc[o][3];
        if (act) { s0 = silu(s0); s1 = silu(s1); s2 = silu(s2); s3 = silu(s3); }
        *(float4*)(out + (size_t)(b * COUT + oc0 + o) * spatial + obase0) =
            make_float4(s0, s1, s2, s3);
    }
}

// ---------------- SIMT 3x3x3 conv, stride 1, XW=8, OCW=8, vectorized weight LDS ----------------
template<int CIN, int OCW>
__launch_bounds__(256)
__global__ void conv_k3_x8(const float* __restrict__ in, const float* __restrict__ wt,
                           const float* __restrict__ bias, float* __restrict__ out,
                           int Din, int COUT, int act)
{
    extern __shared__ float sw[];
    const int oc0 = blockIdx.y * OCW;
    const int b   = blockIdx.z;
    for (int idx = threadIdx.x; idx < CIN * 27 * OCW; idx += 256) {
        int r = idx / OCW, o = idx % OCW;
        sw[idx] = wt[(oc0 + o) * (CIN * 27) + r];
    }
    __syncthreads();
    const int spatial = Din * Din * Din;
    int gpos = (blockIdx.x * 256 + threadIdx.x) * 8;
    if (gpos >= spatial) return;
    int x0 = gpos % Din; int t1 = gpos / Din; int y = t1 % Din; int z = t1 / Din;

    float acc[OCW][8];
#pragma unroll
    for (int o = 0; o < OCW; o++) {
        float bv = bias[oc0 + o];
#pragma unroll
        for (int xx = 0; xx < 8; xx++) acc[o][xx] = bv;
    }
    const float* inb = in + b * CIN * Din * Din * Din;
#pragma unroll 1
    for (int ic = 0; ic < CIN; ic++) {
        const float* inc = inb + ic * Din * Din * Din;
#pragma unroll 1
        for (int tz = 0; tz < 3; tz++) {
            int iz = z + tz - 1; if ((unsigned)iz >= (unsigned)Din) continue;
#pragma unroll
            for (int ty = 0; ty < 3; ty++) {
                int iy = y + ty - 1; if ((unsigned)iy >= (unsigned)Din) continue;
                const float* row = inc + (iz * Din + iy) * Din;
                float4 v0 = *(const float4*)(row + x0);
                float4 v1 = *(const float4*)(row + x0 + 4);
                float r[10];
                r[0] = (x0 > 0) ? row[x0 - 1] : 0.f;
                r[1] = v0.x; r[2] = v0.y; r[3] = v0.z; r[4] = v0.w;
                r[5] = v1.x; r[6] = v1.y; r[7] = v1.z; r[8] = v1.w;
                r[9] = (x0 + 8 < Din) ? row[x0 + 8] : 0.f;
                const float* swp = sw + (ic * 27 + tz * 9 + ty * 3) * OCW;
#pragma unroll
                for (int tx = 0; tx < 3; tx++) {
                    float w[OCW];
#pragma unroll
                    for (int o4 = 0; o4 < OCW / 4; o4++)
                        *(float4*)(w + 4 * o4) = *(const float4*)(swp + tx * OCW + 4 * o4);
#pragma unroll
                    for (int o = 0; o < OCW; o++)
#pragma unroll
                        for (int xx = 0; xx < 8; xx++) acc[o][xx] += w[o] * r[xx + tx];
                }
            }
        }
    }
    int obase0 = (z * Din + y) * Din + x0;
#pragma unroll
    for (int o = 0; o < OCW; o++) {
        float s[8];
#pragma unroll
        for (int xx = 0; xx < 8; xx++) {
            s[xx] = acc[o][xx];
            if (act) s[xx] = silu(s[xx]);
        }
        float* op = out + (size_t)(b * COUT + oc0 + o) * spatial + obase0;
        *(float4*)op = make_float4(s[0], s[1], s[2], s[3]);
        *(float4*)(op + 4) = make_float4(s[4], s[5], s[6], s[7]);
    }
}

// ---------------- 1x1x1 convs ----------------
__global__ void quant_conv_kernel(const float* __restrict__ h, const float* __restrict__ w,
                                  const float* __restrict__ bias, float* __restrict__ seq)
{
    int i = blockIdx.x * 256 + threadIdx.x;
    if (i >= NTOK * EDIM) return;
    int e = i & 15; int p = (i >> 4) & 4095; int b = i >> 16;
    float acc = bias[e];
    const float* hp = h + (b * 128) * 4096 + p;
    const float* wp = w + e * 128;
#pragma unroll 8
    for (int ic = 0; ic < 128; ic++) acc += wp[ic] * hp[ic * 4096];
    seq[i] = acc;
}

__global__ void post_quant_cl_kernel(const float* __restrict__ q, const float* __restrict__ w,
                                     const float* __restrict__ bias, float* __restrict__ out_cl)
{
    int i = blockIdx.x * 256 + threadIdx.x;
    if (i >= BATCH * 4096 * 128) return;
    int oc = i & 127; int p = (i >> 7) & 4095; int b = i >> 19;
    float acc = bias[oc];
    const float* qp = q + (b * EDIM) * 4096 + p;
    const float* wp = w + oc * EDIM;
#pragma unroll
    for (int e = 0; e < EDIM; e++) acc += wp[e] * qp[e * 4096];
    out_cl[i] = __uint_as_float(f2tf(acc));
}

// ---------------- VQ ----------------
__global__ void cnorm_kernel(const float* __restrict__ cb) {
    int k = blockIdx.x * 128 + threadIdx.x;
    if (k < KCODE) {
        float s = 0.f;
#pragma unroll
        for (int e = 0; e < EDIM; e++) { float c = cb[k * EDIM + e]; s += c * c; }
        g_cnorm[k] = s;
    }
}

__global__ void vq_kernel(const float* __restrict__ seq, const float* __restrict__ cb)
{
    __shared__ float stok[32 * 16];
    __shared__ float sc[128 * 16];
    __shared__ float sn[128];
    __shared__ float rd[128];
    __shared__ int   ri[128];
    const int nnz = g_nnz;
    const int tok0 = blockIdx.x * 32;
    if (tok0 >= nnz) return;
    const int tid = threadIdx.x;
    for (int i = tid; i < 512; i += 128) {
        int ti = tok0 + (i >> 4);
        int tok = g_toklist[ti < nnz ? ti : (nnz - 1)];
        stok[i] = seq[tok * 16 + (i & 15)];
    }
    __syncthreads();
    const int t = tid & 31, g = tid >> 5;
    float s[16];
#pragma unroll
    for (int e = 0; e < 16; e++) s[e] = stok[t * 16 + e];
    float best = 3.4e38f; int bidx = 0;
    for (int tile = 0; tile < KCODE / 128; tile++) {
        __syncthreads();
        for (int i = tid; i < 512; i += 128)
            *(float4*)&sc[i * 4] = *(const float4*)&cb[tile * 2048 + i * 4];
        if (tid < 128) sn[tid] = g_cnorm[tile * 128 + tid];
        __syncthreads();
#pragma unroll 4
        for (int kk = g; kk < 128; kk += 4) {
            const float4* c4 = (const float4*)&sc[kk * 16];
            float4 c0 = c4[0], c1 = c4[1], c2 = c4[2], c3 = c4[3];
            float dot = c0.x * s[0] + c0.y * s[1] + c0.z * s[2] + c0.w * s[3]
                      + c1.x * s[4] + c1.y * s[5] + c1.z * s[6] + c1.w * s[7]
                      + c2.x * s[8] + c2.y * s[9] + c2.z * s[10] + c2.w * s[11]
                      + c3.x * s[12] + c3.y * s[13] + c3.z * s[14] + c3.w * s[15];
            float d = sn[kk] - 2.f * dot;
            if (d < best) { best = d; bidx = tile * 128 + kk; }
        }
    }
    rd[tid] = best; ri[tid] = bidx;
    __syncthreads();
    if (g == 0) {
        for (int gg = 1; gg < 4; gg++) {
            float d = rd[gg * 32 + t]; int k = ri[gg * 32 + t];
            if (d < best || (d == best && k < bidx)) { best = d; bidx = k; }
        }
        int ti = tok0 + t;
        if (ti < nnz) g_idx[g_toklist[ti]] = bidx;
    }
}

// ---------------- commit loss ----------------
__global__ void commit_kernel(const float* __restrict__ seq, const float* __restrict__ cb)
{
    __shared__ float sh[128];
    int t = blockIdx.x * 128 + threadIdx.x;
    float v = 0.f;
    if (!g_zmask[t]) {
        const float* s = seq + t * 16;
        const float* c = cb + g_idx[t] * 16;
        float a = 0.f;
#pragma unroll
        for (int e = 0; e < 16; e++) { float d = c[e] - s[e]; a += d * d; }
        v = a * (1.f / 16.f);
    }
    sh[threadIdx.x] = v; __syncthreads();
    for (int st = 64; st; st >>= 1) {
        if (threadIdx.x < st) sh[threadIdx.x] += sh[threadIdx.x + st];
        __syncthreads();
    }
    if (threadIdx.x == 0) g_part[blockIdx.x] = sh[0];
}

__global__ void commit_final(float* __restrict__ out) {
    if (threadIdx.x == 0) {
        float s = 0.f;
        for (int i = 0; i < 128; i++) s += g_part[i];
        out[0] = 0.25f * s / 16384.f;
    }
}

__global__ void fullidx_kernel(float* __restrict__ out) {
    int i = blockIdx.x * 256 + threadIdx.x;
    if (i < NTOK) out[i] = g_zmask[i] ? 0.f : (float)(g_idx[i] + 1);
}

__global__ void qbuild_kernel(const float* __restrict__ cb, const float* __restrict__ rep,
                              const float* __restrict__ pos)
{
    int i = blockIdx.x * 256 + threadIdx.x;
    if (i >= BATCH * EDIM * 4096) return;
    int p = i & 4095; int e = (i >> 12) & 15; int b = i >> 16;
    int tok = (b << 12) + p;
    float v = g_zmask[tok] ? rep[e] : cb[g_idx[tok] * 16 + e];
    g_q[i] = v + pos[e * 4096 + p];
}

// ---------------- launch ----------------
extern "C" void kernel_launch(void* const* d_in, const int* in_sizes, int n_in,
                              void* d_out_, int out_size)
{
    const unsigned char* x = (const unsigned char*)d_in[0];
    const float* enc_in_w  = (const float*)d_in[1];
    const float* enc_in_b  = (const float*)d_in[2];
    const float* enc_d1_w  = (const float*)d_in[3];
    const float* enc_d1_b  = (const float*)d_in[4];
    const float* enc_d2_w  = (const float*)d_in[5];
    const float* enc_d2_b  = (const float*)d_in[6];
    const float* enc_out_w = (const float*)d_in[7];
    const float* enc_out_b = (const float*)d_in[8];
    const float* quant_w   = (const float*)d_in[9];
    const float* quant_b   = (const float*)d_in[10];
    const float* codebook  = (const float*)d_in[11];
    const float* rep_tok   = (const float*)d_in[12];
    const float* pos_emb   = (const float*)d_in[13];
    const float* pq_w      = (const float*)d_in[14];
    const float* pq_b      = (const float*)d_in[15];
    const float* dec_in_w  = (const float*)d_in[16];
    const float* dec_in_b  = (const float*)d_in[17];
    const float* dec_u1_w  = (const float*)d_in[18];
    const float* dec_u1_b  = (const float*)d_in[19];
    const float* dec_u2_w  = (const float*)d_in[20];
    const float* dec_u2_b  = (const float*)d_in[21];
    const float* dec_out_w = (const float*)d_in[22];
    const float* dec_out_b = (const float*)d_in[23];
    float* out = (float*)d_out_;

    float *pA, *pB, *pC, *pD, *pSeq, *pQ, *pCL, *pW, *pW1, *pW2;
    cudaGetSymbolAddress((void**)&pA, g_bufA);
    cudaGetSymbolAddress((void**)&pB, g_bufB);
    cudaGetSymbolAddress((void**)&pC, g_bufC);
    cudaGetSymbolAddress((void**)&pD, g_bufD);
    cudaGetSymbolAddress((void**)&pSeq, g_seq);
    cudaGetSymbolAddress((void**)&pQ, g_q);
    cudaGetSymbolAddress((void**)&pCL, g_cl);
    cudaGetSymbolAddress((void**)&pW, g_wt);
    cudaGetSymbolAddress((void**)&pW1, g_wt1);
    cudaGetSymbolAddress((void**)&pW2, g_wt2);
    cudaFuncSetAttribute(conv_k3<64, 8>,  cudaFuncAttributeMaxDynamicSharedMemorySize, 131072);
    cudaFuncSetAttribute(conv_k3<128, 8>, cudaFuncAttributeMaxDynamicSharedMemorySize, 131072);
    cudaFuncSetAttribute(conv_mma_dec,    cudaFuncAttributeMaxDynamicSharedMemorySize, 2 * STAGE_F * 4);
    cudaFuncSetAttribute((tconv_mma<128, 64, 16, 4, 1>), cudaFuncAttributeMaxDynamicSharedMemorySize, 55296);
    cudaFuncSetAttribute((tconv_mma<64, 32, 32, 5, 0>),  cudaFuncAttributeMaxDynamicSharedMemorySize, 47104);

    float* mc = out + OFF_MC;
    dim3 blk(256);

    initflag_kernel<<<1, 1>>>();
    scan_kernel<<<4096, 256>>>((const unsigned int*)x);
    pack_kernel<<<N_MC / 256, 256>>>(x, mc);

    // encoder (fp32 SIMT — VQ index exactness)
    conv_k3_x8<8, 8><<<dim3(128, 4, 4), blk, 8 * 27 * 8 * 4>>>(mc, enc_in_w, enc_in_b, pA, 64, 32, 1);
    zmask_kernel<<<512, 256>>>(mc);
    conv_k3<32, 8><<<dim3(32, 8, 4), blk, 32 * 27 * 8 * 4>>>(pA, enc_d1_w, enc_d1_b, pB, 64, 32, 2, 64, 1);
    conv_k3<64, 8><<<dim3(4, 16, 4), blk, 64 * 27 * 8 * 4>>>(pB, enc_d2_w, enc_d2_b, pC, 32, 16, 2, 128, 1);
    conv_k3<128, 8><<<dim3(4, 16, 4), blk, 128 * 27 * 8 * 4>>>(pC, enc_out_w, enc_out_b, pD, 16, 16, 1, 128, 0);

    wtrans2<<<1728, 256>>>(dec_in_w, pW, 128, 128);
    wtrans2<<<864, 256>>>(dec_u1_w, pW1, 128, 64);
    wtrans2<<<216, 256>>>(dec_u2_w, pW2, 64, 32);

    // quantization path
    cnorm_kernel<<<KCODE / 128, 128>>>(codebook);
    quant_conv_kernel<<<(NTOK * EDIM) / 256, 256>>>(pD, quant_w, quant_b, pSeq);
    vq_kernel<<<NTOK / 32, 128>>>(pSeq, codebook);
    commit_kernel<<<NTOK / 128, 128>>>(pSeq, codebook);
    commit_final<<<1, 1>>>(out + OFF_COMMIT);
    fullidx_kernel<<<NTOK / 256, 256>>>(out + OFF_IDX);
    qbuild_kernel<<<(BATCH * EDIM * 4096) / 256, 256>>>(codebook, rep_tok, pos_emb);
    post_quant_cl_kernel<<<(BATCH * 4096 * 128) / 256, 256>>>(pQ, pq_w, pq_b, pCL);

    // decoder: dec_in + both tconvs on tensor cores (tf32), dec_out SIMT XW=8
    conv_mma_dec<<<dim3(32, 1, 4), 256, 2 * STAGE_F * 4>>>(pCL, dec_in_b, pD);
    tconv_mma<128, 64, 16, 4, 1><<<dim3(32, 8, 4), 256, 55296>>>(pD, pW1, dec_u1_b, pB);
    tconv_mma<64, 32, 32, 5, 0><<<dim3(256, 8, 4), 256, 47104>>>(pB, pW2, dec_u2_b, pA);
    conv_k3_x8<32, 8><<<dim3(128, 1, 4), blk, 32 * 27 * 8 * 4>>>(pA, dec_out_w, dec_out_b, out, 64, 8, 0);
}

// round 11
// speedup vs baseline: 1.1800x; 1.0355x over previous
#include <cuda_runtime.h>
#include <math.h>
#include <cstdint>

// ---------------- problem constants ----------------
#define BATCH 4
#define D64   64
#define D32   32
#define D16   16
#define NTOK  (BATCH*4096)
#define EDIM  16
#define KCODE 8192
#define N_MC  (BATCH*8*D64*D64*D64)
#define OFF_MC     8388608
#define OFF_COMMIT 16777216
#define OFF_IDX    16777217

// ---------------- device scratch ----------------
__device__ float g_bufA[BATCH*32*D64*D64*D64];
__device__ float g_bufB[BATCH*64*D32*D32*D32];
__device__ float g_bufC[BATCH*128*D16*D16*D16];
__device__ float g_bufD[BATCH*128*D16*D16*D16];   // also h (channel-last) / dec_in out
__device__ float g_seq[NTOK*EDIM];
__device__ float g_q[BATCH*EDIM*4096];
__device__ float g_cl[BATCH*4096*128];            // channel-last activations
__device__ float g_wt [27*128*128];               // dec_in weights (tf32)
__device__ float g_wt1[27*128*64];                // dec_u1
__device__ float g_wt2[27*64*32];                 // dec_u2
__device__ float g_wth[27*128*128];               // enc_out weights hi (tf32)
__device__ float g_wtl[27*128*128];               // enc_out weights lo (tf32)
__device__ float g_cnorm[KCODE];
__device__ float g_part[128];
__device__ int   g_idx[NTOK];
__device__ unsigned char g_zmask[NTOK];
__device__ int   g_flags;
__device__ int   g_nnz;
__device__ int   g_toklist[NTOK];

__device__ __forceinline__ float silu(float v) { return v * __frcp_rn(1.f + __expf(-v)); }

__device__ __forceinline__ uint32_t f2tf(float f) {
    uint32_t r; asm("cvt.rna.tf32.f32 %0, %1;" : "=r"(r) : "f"(f)); return r;
}
__device__ __forceinline__ void mma_tf32(float* d, const uint32_t* a, const uint32_t* b) {
    asm volatile("mma.sync.aligned.m16n8k8.row.col.f32.tf32.tf32.f32 "
                 "{%0,%1,%2,%3}, {%4,%5,%6,%7}, {%8,%9}, {%0,%1,%2,%3};"
                 : "+f"(d[0]), "+f"(d[1]), "+f"(d[2]), "+f"(d[3])
                 : "r"(a[0]), "r"(a[1]), "r"(a[2]), "r"(a[3]), "r"(b[0]), "r"(b[1]));
}

// -------- weight transform: w[OC][IC][27] -> dst[tap][ic][oc], tf32-rounded --------
__global__ void wtrans2(const float* __restrict__ w, float* __restrict__ dst, int IC, int OC) {
    int i = blockIdx.x * 256 + threadIdx.x;
    int total = 27 * IC * OC;
    if (i >= total) return;
    int tap = i / (IC * OC); int rem = i % (IC * OC); int ic = rem / OC; int oc = rem % OC;
    dst[i] = __uint_as_float(f2tf(w[(oc * IC + ic) * 27 + tap]));
}

// -------- hi/lo split weight transform (3xtf32): w[128][128][27] -> [tap][ic][oc] --------
__global__ void wtrans_hilo(const float* __restrict__ w) {
    int i = blockIdx.x * 256 + threadIdx.x;
    if (i >= 27 * 128 * 128) return;
    int tap = i >> 14; int rem = i & 16383; int ic = rem >> 7; int oc = rem & 127;
    float v = w[(oc * 128 + ic) * 27 + tap];
    float hi = __uint_as_float(f2tf(v));
    g_wth[i] = hi;
    g_wtl[i] = __uint_as_float(f2tf(v - hi));
}

// ---------- mma.sync tf32 implicit-GEMM 3x3x3 conv (128->128, 16^3), dec_in ----------
#define SA 36
#define SB 136
#define STAGE_F (128*SA + 32*SB)

__launch_bounds__(256)
__global__ void conv_mma_dec(const float* __restrict__ in_cl, const float* __restrict__ bias,
                             float* __restrict__ out_cl)
{
    extern __shared__ float dsm[];
    const int tid = threadIdx.x;
    const int lane = tid & 31, wid = tid >> 5;
    const int wm = wid >> 2, wn = wid & 3;
    const int bb = blockIdx.z;
    const int pos0 = blockIdx.x * 128;
    const float* inb = in_cl + (size_t)bb * 4096 * 128;

    float acc[4][4][4];
#pragma unroll
    for (int mt = 0; mt < 4; mt++)
#pragma unroll
        for (int nt = 0; nt < 4; nt++)
#pragma unroll
            for (int k = 0; k < 4; k++) acc[mt][nt][k] = 0.f;

    const int ar = tid >> 1, aseg = tid & 1;
    const int apos = pos0 + ar;
    const int ax = apos & 15, ay = (apos >> 4) & 15, az = apos >> 8;
    const int bk = tid >> 3, bseg = tid & 7;

    float4 ra[4], rb[4];
    auto ldg = [&](int c) {
        int tap = c >> 2, ic0 = (c & 3) * 32;
        int tz = tap / 9, ty = (tap / 3) % 3, tx = tap % 3;
        int xx = ax + tx - 1, yy = ay + ty - 1, zz = az + tz - 1;
        bool valid = ((unsigned)xx < 16u) & ((unsigned)yy < 16u) & ((unsigned)zz < 16u);
        if (valid) {
            const float4* sa = (const float4*)(inb + (size_t)((zz * 16 + yy) * 16 + xx) * 128
                                               + ic0 + aseg * 16);
            ra[0] = sa[0]; ra[1] = sa[1]; ra[2] = sa[2]; ra[3] = sa[3];
        } else {
            ra[0] = ra[1] = ra[2] = ra[3] = make_float4(0.f, 0.f, 0.f, 0.f);
        }
        const float4* sb = (const float4*)(g_wt + (size_t)(tap * 128 + ic0 + bk) * 128
                                           + bseg * 16);
        rb[0] = sb[0]; rb[1] = sb[1]; rb[2] = sb[2]; rb[3] = sb[3];
    };
    auto sts = [&](int s) {
        float* Au = dsm + s * STAGE_F;
        float* Bu = Au + 128 * SA;
#pragma unroll
        for (int j = 0; j < 4; j++) {
            *(float4*)(Au + ar * SA + aseg * 16 + 4 * j) = ra[j];
            *(float4*)(Bu + bk * SB + bseg * 16 + 4 * j) = rb[j];
        }
    };
    auto domma = [&](int s) {
        const uint32_t* Au = (const uint32_t*)(dsm + s * STAGE_F);
        const uint32_t* Bu = Au + 128 * SA;
        const int rq = lane >> 2, cq = lane & 3;
#pragma unroll
        for (int q = 0; q < 4; q++) {
            const int kk = q * 8 + cq;
            uint32_t af[4][4], bf[4][2];
#pragma unroll
            for (int mt = 0; mt < 4; mt++) {
                int row = wm * 64 + mt * 16 + rq;
                af[mt][0] = Au[row * SA + kk];
                af[mt][1] = Au[(row + 8) * SA + kk];
                af[mt][2] = Au[row * SA + kk + 4];
                af[mt][3] = Au[(row + 8) * SA + kk + 4];
            }
#pragma unroll
            for (int nt = 0; nt < 4; nt++) {
                int col = wn * 32 + nt * 8 + rq;
                bf[nt][0] = Bu[kk * SB + col];
                bf[nt][1] = Bu[(kk + 4) * SB + col];
            }
#pragma unroll
            for (int mt = 0; mt < 4; mt++)
#pragma unroll
                for (int nt = 0; nt < 4; nt++)
                    mma_tf32(acc[mt][nt], af[mt], bf[nt]);
        }
    };

    ldg(0); sts(0); __syncthreads();
#pragma unroll 1
    for (int c = 0; c < 108; c++) {
        if (c < 107) ldg(c + 1);
        domma(c & 1);
        if (c < 107) sts((c + 1) & 1);
        __syncthreads();
    }

    float* E = dsm;
    const int rq = lane >> 2, cq = lane & 3;
#pragma unroll
    for (int mt = 0; mt < 4; mt++)
#pragma unroll
        for (int nt = 0; nt < 4; nt++) {
            int row = wm * 64 + mt * 16 + rq;
            int col = wn * 32 + nt * 8 + 2 * cq;
            E[row * 129 + col]           = acc[mt][nt][0];
            E[row * 129 + col + 1]       = acc[mt][nt][1];
            E[(row + 8) * 129 + col]     = acc[mt][nt][2];
            E[(row + 8) * 129 + col + 1] = acc[mt][nt][3];
        }
    __syncthreads();
    float* ob = out_cl + ((size_t)bb * 4096 + pos0 + ar) * 128;
#pragma unroll
    for (int j4 = 0; j4 < 16; j4++) {
        float4 v; float* pv = (float*)&v;
#pragma unroll
        for (int t = 0; t < 4; t++) {
            int ch = aseg * 64 + j4 * 4 + t;
            float x = E[ar * 129 + ch] + bias[ch];
            pv[t] = __uint_as_float(f2tf(silu(x)));
        }
        *(float4*)(ob + aseg * 64 + j4 * 4) = v;
    }
}

// ---------- 3xtf32 error-compensated implicit GEMM conv (128->128, 16^3), enc_out ----------
// in_cl: channel-last fp32; out_cl: channel-last fp32 (NO rounding — feeds VQ path).
#define STG3 (2*128*SA + 2*32*SB)   // Ahi, Alo, Bhi, Blo = 17920 floats per stage

__launch_bounds__(256)
__global__ void conv_mma_3x(const float* __restrict__ in_cl, const float* __restrict__ bias,
                            float* __restrict__ out_cl)
{
    extern __shared__ float dsm[];
    const int tid = threadIdx.x;
    const int lane = tid & 31, wid = tid >> 5;
    const int wm = wid >> 2, wn = wid & 3;
    const int bb = blockIdx.z;
    const int pos0 = blockIdx.x * 128;
    const float* inb = in_cl + (size_t)bb * 4096 * 128;

    float acc[4][4][4];
#pragma unroll
    for (int mt = 0; mt < 4; mt++)
#pragma unroll
        for (int nt = 0; nt < 4; nt++)
#pragma unroll
            for (int k = 0; k < 4; k++) acc[mt][nt][k] = 0.f;

    const int ar = tid >> 1, aseg = tid & 1;
    const int apos = pos0 + ar;
    const int ax = apos & 15, ay = (apos >> 4) & 15, az = apos >> 8;
    const int bk = tid >> 3, bseg = tid & 7;

    float4 ra[4], rbh[4], rbl[4];
    auto ldg = [&](int c) {
        int tap = c >> 2, ic0 = (c & 3) * 32;
        int tz = tap / 9, ty = (tap / 3) % 3, tx = tap % 3;
        int xx = ax + tx - 1, yy = ay + ty - 1, zz = az + tz - 1;
        bool valid = ((unsigned)xx < 16u) & ((unsigned)yy < 16u) & ((unsigned)zz < 16u);
        if (valid) {
            const float4* sa = (const float4*)(inb + (size_t)((zz * 16 + yy) * 16 + xx) * 128
                                               + ic0 + aseg * 16);
            ra[0] = sa[0]; ra[1] = sa[1]; ra[2] = sa[2]; ra[3] = sa[3];
        } else {
            ra[0] = ra[1] = ra[2] = ra[3] = make_float4(0.f, 0.f, 0.f, 0.f);
        }
        size_t woff = (size_t)(tap * 128 + ic0 + bk) * 128 + bseg * 16;
        const float4* sbh = (const float4*)(g_wth + woff);
        const float4* sbl = (const float4*)(g_wtl + woff);
        rbh[0] = sbh[0]; rbh[1] = sbh[1]; rbh[2] = sbh[2]; rbh[3] = sbh[3];
        rbl[0] = sbl[0]; rbl[1] = sbl[1]; rbl[2] = sbl[2]; rbl[3] = sbl[3];
    };
    auto sts = [&](int s) {
        float* Ah = dsm + s * STG3;
        float* Al = Ah + 128 * SA;
        float* Bh = Al + 128 * SA;
        float* Bl = Bh + 32 * SB;
#pragma unroll
        for (int j = 0; j < 4; j++) {
            float4 v = ra[j];
            uint4 h, l;
            h.x = f2tf(v.x); l.x = f2tf(v.x - __uint_as_float(h.x));
            h.y = f2tf(v.y); l.y = f2tf(v.y - __uint_as_float(h.y));
            h.z = f2tf(v.z); l.z = f2tf(v.z - __uint_as_float(h.z));
            h.w = f2tf(v.w); l.w = f2tf(v.w - __uint_as_float(h.w));
            *(uint4*)(Ah + ar * SA + aseg * 16 + 4 * j) = h;
            *(uint4*)(Al + ar * SA + aseg * 16 + 4 * j) = l;
            *(float4*)(Bh + bk * SB + bseg * 16 + 4 * j) = rbh[j];
            *(float4*)(Bl + bk * SB + bseg * 16 + 4 * j) = rbl[j];
        }
    };
    const int rq = lane >> 2, cq = lane & 3;
    auto dom = [&](const uint32_t* Au, const uint32_t* Bu) {
#pragma unroll
        for (int q = 0; q < 4; q++) {
            const int kk = q * 8 + cq;
            uint32_t af[4][4], bf[4][2];
#pragma unroll
            for (int mt = 0; mt < 4; mt++) {
                int row = wm * 64 + mt * 16 + rq;
                af[mt][0] = Au[row * SA + kk];
                af[mt][1] = Au[(row + 8) * SA + kk];
                af[mt][2] = Au[row * SA + kk + 4];
                af[mt][3] = Au[(row + 8) * SA + kk + 4];
            }
#pragma unroll
            for (int nt = 0; nt < 4; nt++) {
                int col = wn * 32 + nt * 8 + rq;
                bf[nt][0] = Bu[kk * SB + col];
                bf[nt][1] = Bu[(kk + 4) * SB + col];
            }
#pragma unroll
            for (int mt = 0; mt < 4; mt++)
#pragma unroll
                for (int nt = 0; nt < 4; nt++)
                    mma_tf32(acc[mt][nt], af[mt], bf[nt]);
        }
    };
    auto domma3 = [&](int s) {
        const uint32_t* Ah = (const uint32_t*)(dsm + s * STG3);
        const uint32_t* Al = Ah + 128 * SA;
        const uint32_t* Bh = Al + 128 * SA;
        const uint32_t* Bl = Bh + 32 * SB;
        dom(Ah, Bh);
        dom(Ah, Bl);
        dom(Al, Bh);
    };

    ldg(0); sts(0); __syncthreads();
#pragma unroll 1
    for (int c = 0; c < 108; c++) {
        if (c < 107) ldg(c + 1);
        domma3(c & 1);
        if (c < 107) sts((c + 1) & 1);
        __syncthreads();
    }

    float* E = dsm;
#pragma unroll
    for (int mt = 0; mt < 4; mt++)
#pragma unroll
        for (int nt = 0; nt < 4; nt++) {
            int row = wm * 64 + mt * 16 + rq;
            int col = wn * 32 + nt * 8 + 2 * cq;
            E[row * 129 + col]           = acc[mt][nt][0];
            E[row * 129 + col + 1]       = acc[mt][nt][1];
            E[(row + 8) * 129 + col]     = acc[mt][nt][2];
            E[(row + 8) * 129 + col + 1] = acc[mt][nt][3];
        }
    __syncthreads();
    float* ob = out_cl + ((size_t)bb * 4096 + pos0 + ar) * 128;
#pragma unroll
    for (int j4 = 0; j4 < 16; j4++) {
        float4 v; float* pv = (float*)&v;
#pragma unroll
        for (int t = 0; t < 4; t++) {
            int ch = aseg * 64 + j4 * 4 + t;
            pv[t] = E[ar * 129 + ch] + bias[ch];   // fp32, no rounding
        }
        *(float4*)(ob + aseg * 64 + j4 * 4) = v;
    }
}

// ---------- mma.sync tf32 transposed conv via octant decomposition ----------
template<int CIN, int COUT, int DIN, int LOGD, int CLOUT>
__launch_bounds__(256)
__global__ void tconv_mma(const float* __restrict__ in_cl, const float* __restrict__ wtr,
                          const float* __restrict__ bias, float* __restrict__ out)
{
    extern __shared__ float dsm[];
    constexpr int NW_N = COUT / 32;
    constexpr int NW_M = 8 / NW_N;
    constexpr int MT = 128 / (NW_M * 16);
    constexpr int SAs = 36;
    constexpr int SBs = COUT + 8;
    constexpr int STG = 128 * SAs + 32 * SBs;
    constexpr int NIC = CIN / 32;
    constexpr int DOUT = 2 * DIN;
    constexpr int BF4 = COUT / 32;

    const int tid = threadIdx.x;
    const int lane = tid & 31, wid = tid >> 5;
    const int wm = wid / NW_N, wn = wid % NW_N;
    const int bb = blockIdx.z;
    const int oct = blockIdx.y;
    const int px = oct & 1, py = (oct >> 1) & 1, pz = (oct >> 2) & 1;
    const int ntx = 2 - px, nty = 2 - py;
    const int nchunks = ntx * nty * (2 - pz) * NIC;
    const int pos0 = blockIdx.x * 128;
    const float* inb = in_cl + (size_t)bb * (DIN * DIN * DIN) * CIN;

    float acc[MT][4][4];
#pragma unroll
    for (int mt = 0; mt < MT; mt++)
#pragma unroll
        for (int nt = 0; nt < 4; nt++)
#pragma unroll
            for (int k = 0; k < 4; k++) acc[mt][nt][k] = 0.f;

    const int ar = tid >> 1, aseg = tid & 1;
    const int pa = pos0 + ar;
    const int gx = pa & (DIN - 1), gy = (pa >> LOGD) & (DIN - 1), gz = pa >> (2 * LOGD);
    const int bk = tid >> 3, bseg = tid & 7;

    float4 ra[4], rb[BF4];

    auto ldg = [&](int c) {
        int tap = c / NIC, ic0 = (c % NIC) * 32;
        int txi = tap % ntx; int r2 = tap / ntx; int tyi = r2 % nty; int tzi = r2 / nty;
        int tx = px ? 1 : txi * 2, ty = py ? 1 : tyi * 2, tz = pz ? 1 : tzi * 2;
        int ix = gx + (px ? 0 : txi - 1);
        int iy = gy + (py ? 0 : tyi - 1);
        int iz = gz + (pz ? 0 : tzi - 1);
        bool valid = (ix >= 0) && (iy >= 0) && (iz >= 0);
        if (valid) {
            const float4* sa = (const float4*)(inb + (size_t)((iz * DIN + iy) * DIN + ix) * CIN
                                               + ic0 + aseg * 16);
            ra[0] = sa[0]; ra[1] = sa[1]; ra[2] = sa[2]; ra[3] = sa[3];
        } else {
            ra[0] = ra[1] = ra[2] = ra[3] = make_float4(0.f, 0.f, 0.f, 0.f);
        }
        int tap27 = tz * 9 + ty * 3 + tx;
        const float4* sb = (const float4*)(wtr + ((size_t)(tap27 * CIN) + ic0 + bk) * COUT
                                           + bseg * (COUT / 8));
#pragma unroll
        for (int j = 0; j < BF4; j++) rb[j] = sb[j];
    };
    auto sts = [&](int s) {
        float* Au = dsm + s * STG;
        float* Bu = Au + 128 * SAs;
#pragma unroll
        for (int j = 0; j < 4; j++)
            *(float4*)(Au + ar * SAs + aseg * 16 + 4 * j) = ra[j];
#pragma unroll
        for (int j = 0; j < BF4; j++)
            *(float4*)(Bu + bk * SBs + bseg * (COUT / 8) + 4 * j) = rb[j];
    };
    auto domma = [&](int s) {
        const uint32_t* Au = (const uint32_t*)(dsm + s * STG);
        const uint32_t* Bu = Au + 128 * SAs;
        const int rq = lane >> 2, cq = lane & 3;
#pragma unroll
        for (int q = 0; q < 4; q++) {
            const int kk = q * 8 + cq;
            uint32_t af[MT][4], bf[4][2];
#pragma unroll
            for (int mt = 0; mt < MT; mt++) {
                int row = wm * (MT * 16) + mt * 16 + rq;
                af[mt][0] = Au[row * SAs + kk];
                af[mt][1] = Au[(row + 8) * SAs + kk];
                af[mt][2] = Au[row * SAs + kk + 4];
                af[mt][3] = Au[(row + 8) * SAs + kk + 4];
            }
#pragma unroll
            for (int nt = 0; nt < 4; nt++) {
                int col = wn * 32 + nt * 8 + rq;
                bf[nt][0] = Bu[kk * SBs + col];
                bf[nt][1] = Bu[(kk + 4) * SBs + col];
            }
#pragma unroll
            for (int mt = 0; mt < MT; mt++)
#pragma unroll
                for (int nt = 0; nt < 4; nt++)
                    mma_tf32(acc[mt][nt], af[mt], bf[nt]);
        }
    };

    ldg(0); sts(0); __syncthreads();
#pragma unroll 1
    for (int c = 0; c < nchunks; c++) {
        if (c + 1 < nchunks) ldg(c + 1);
        domma(c & 1);
        if (c + 1 < nchunks) sts((c + 1) & 1);
        __syncthreads();
    }

    float* E = dsm;
    const int rq = lane >> 2, cq = lane & 3;
    if (CLOUT) {
        constexpr int SE = COUT + 1;
#pragma unroll
        for (int mt = 0; mt < MT; mt++)
#pragma unroll
            for (int nt = 0; nt < 4; nt++) {
                int row = wm * (MT * 16) + mt * 16 + rq;
                int col = wn * 32 + nt * 8 + 2 * cq;
                E[row * SE + col]           = acc[mt][nt][0];
                E[row * SE + col + 1]       = acc[mt][nt][1];
                E[(row + 8) * SE + col]     = acc[mt][nt][2];
                E[(row + 8) * SE + col + 1] = acc[mt][nt][3];
            }
        __syncthreads();
        int opos = ((2 * gz + pz) * DOUT + (2 * gy + py)) * DOUT + (2 * gx + px);
        float* ob = out + ((size_t)bb * DOUT * DOUT * DOUT + opos) * COUT;
#pragma unroll
        for (int j4 = 0; j4 < COUT / 8; j4++) {
            float4 v; float* pv = (float*)&v;
#pragma unroll
            for (int t = 0; t < 4; t++) {
                int ch = aseg * (COUT / 2) + j4 * 4 + t;
                float x = E[ar * SE + ch] + bias[ch];
                pv[t] = __uint_as_float(f2tf(silu(x)));
            }
            *(float4*)(ob + aseg * (COUT / 2) + j4 * 4) = v;
        }
    } else {
        constexpr int SE = 36;
#pragma unroll
        for (int mt = 0; mt < MT; mt++)
#pragma unroll
            for (int nt = 0; nt < 4; nt++) {
                int row = wm * (MT * 16) + mt * 16 + rq;
                int col = nt * 8 + 2 * cq;
                E[row * SE + col]           = acc[mt][nt][0];
                E[row * SE + col + 1]       = acc[mt][nt][1];
                E[(row + 8) * SE + col]     = acc[mt][nt][2];
                E[(row + 8) * SE + col + 1] = acc[mt][nt][3];
            }
        __syncthreads();
        int ch = tid >> 3;
        float bv = bias[ch];
        float* ob = out + ((size_t)bb * COUT + ch) * (DOUT * DOUT * DOUT);
#pragma unroll
        for (int j = 0; j < 16; j++) {
            int p = (tid & 7) + 8 * j;
            int pp = pos0 + p;
            int hx = pp & (DIN - 1), hy = (pp >> LOGD) & (DIN - 1), hz = pp >> (2 * LOGD);
            int opos = ((2 * hz + pz) * DOUT + (2 * hy + py)) * DOUT + (2 * hx + px);
            ob[opos] = silu(E[p * SE + ch] + bv);
        }
    }
}

// ---------------- input dtype probe ----------------
__global__ void initflag_kernel() { g_flags = 0; g_nnz = 0; }

__global__ void scan_kernel(const unsigned int* __restrict__ xw) {
    int base = blockIdx.x * 256 + threadIdx.x;
    unsigned int f = 0, u = 0;
#pragma unroll
    for (int j = 0; j < 16; j++) {
        unsigned int w = xw[base + j * 1048576];
        f |= (w & 0xFEFEFEFEu);
        u |= (w & 0x01010100u);
    }
    int bits = (f ? 1 : 0) | (u ? 2 : 0);
    if (bits) atomicOr(&g_flags, bits);
}

// ---------------- bit pack ----------------
__global__ void pack_kernel(const unsigned char* __restrict__ xb, float* __restrict__ mc) {
    int i = blockIdx.x * 256 + threadIdx.x;
    if (i >= N_MC) return;
    int k  = i & 63;
    int j  = (i >> 6) & 63;
    int zi = (i >> 12) & 63;
    int c  = (i >> 18) & 7;
    int b  = i >> 21;
    int a   = c >> 1;
    int bb0 = (2 * c) & 3;
    int base = (((b * 256) + 4 * zi + a) * 256 + 4 * j + bb0) * 256 + 4 * k;
    int s = 0;
    int flags = g_flags;
    if (flags & 1) {
        const float* xf = (const float*)xb;
        float4 f0 = *(const float4*)(xf + base);
        float4 f1 = *(const float4*)(xf + base + 256);
        if (f0.x != 0.f) s |= 1;   if (f0.y != 0.f) s |= 2;
        if (f0.z != 0.f) s |= 4;   if (f0.w != 0.f) s |= 8;
        if (f1.x != 0.f) s |= 16;  if (f1.y != 0.f) s |= 32;
        if (f1.z != 0.f) s |= 64;  if (f1.w != 0.f) s |= 128;
    } else if (flags & 2) {
        unsigned int r0 = *(const unsigned int*)(xb + base);
        unsigned int r1 = *(const unsigned int*)(xb + base + 256);
#pragma unroll
        for (int cc = 0; cc < 4; cc++) {
            if ((r0 >> (8 * cc)) & 0xFF) s |= 1 << cc;
            if ((r1 >> (8 * cc)) & 0xFF) s |= 1 << (4 + cc);
        }
    } else {
        const int* xi = (const int*)xb;
        int4 a0 = *(const int4*)(xi + base);
        int4 a1 = *(const int4*)(xi + base + 256);
        if (a0.x) s |= 1;   if (a0.y) s |= 2;
        if (a0.z) s |= 4;   if (a0.w) s |= 8;
        if (a1.x) s |= 16;  if (a1.y) s |= 32;
        if (a1.z) s |= 64;  if (a1.w) s |= 128;
    }
    mc[i] = (float)s * (1.0f / 255.0f);
}

// ---------------- zero-patch mask + nonzero-token compaction ----------------
__global__ void zmask_kernel(const float* __restrict__ mc) {
    int idx = blockIdx.x * 256 + threadIdx.x;
    int tok = idx >> 3, c = idx & 7;
    int p = tok & 4095, b = tok >> 12;
    int zk = p & 15, zj = (p >> 4) & 15, zi = p >> 8;
    bool any = false;
    const float* basep = mc + (((b * 8 + c) * 64 + 4 * zi) * 64 + 4 * zj) * 64 + 4 * zk;
#pragma unroll
    for (int dz = 0; dz < 4; dz++)
#pragma unroll
        for (int dy = 0; dy < 4; dy++) {
            float4 v = *(const float4*)(basep + (dz * 64 + dy) * 64);
            any |= (v.x != 0.f) | (v.y != 0.f) | (v.z != 0.f) | (v.w != 0.f);
        }
    unsigned m = __ballot_sync(0xFFFFFFFFu, any);
    if (c == 0) {
        int sh = threadIdx.x & 24;
        bool nz = ((m >> sh) & 0xFF) != 0;
        g_zmask[tok] = nz ? 0 : 1;
        if (nz) { int pp = atomicAdd(&g_nnz, 1); g_toklist[pp] = tok; }
    }
}

// ---------------- SIMT 3x3x3 conv (XW=4, OCW=8, vectorized weight LDS) ----------------
// CL: 1 -> channel-last output (for feeding mma kernels)
template<int CIN, int OCW, int CL>
__launch_bounds__(256)
__global__ void conv_k3(const float* __restrict__ in, const float* __restrict__ wt,
                        const float* __restrict__ bias, float* __restrict__ out,
                        int Din, int Dout, int stride, int COUT, int act)
{
    extern __shared__ float sw[];
    const int oc0 = blockIdx.y * OCW;
    const int b   = blockIdx.z;
    for (int idx = threadIdx.x; idx < CIN * 27 * OCW; idx += 256) {
        int r = idx / OCW, o = idx % OCW;
        sw[idx] = wt[(oc0 + o) * (CIN * 27) + r];
    }
    __syncthreads();
    const int spatial = Dout * Dout * Dout;
    int gpos = (blockIdx.x * 256 + threadIdx.x) * 4;
    if (gpos >= spatial) return;
    int x0 = gpos % Dout; int t1 = gpos / Dout; int y = t1 % Dout; int z = t1 / Dout;

    float acc[OCW][4];
#pragma unroll
    for (int o = 0; o < OCW; o++) {
        float bv = bias[oc0 + o];
#pragma unroll
        for (int xx = 0; xx < 4; xx++) acc[o][xx] = bv;
    }
    const float* inb = in + b * CIN * Din * Din * Din;
    if (stride == 1) {
#pragma unroll 1
        for (int ic = 0; ic < CIN; ic++) {
            const float* inc = inb + ic * Din * Din * Din;
#pragma unroll 1
            for (int tz = 0; tz < 3; tz++) {
                int iz = z + tz - 1; if ((unsigned)iz >= (unsigned)Din) continue;
#pragma unroll
                for (int ty = 0; ty < 3; ty++) {
                    int iy = y + ty - 1; if ((unsigned)iy >= (unsigned)Din) continue;
                    const float* row = inc + (iz * Din + iy) * Din;
                    float4 v = *(const float4*)(row + x0);
                    float r[6];
                    r[0] = (x0 > 0) ? row[x0 - 1] : 0.f;
                    r[1] = v.x; r[2] = v.y; r[3] = v.z; r[4] = v.w;
                    r[5] = (x0 + 4 < Din) ? row[x0 + 4] : 0.f;
                    const float* swp = sw + (ic * 27 + tz * 9 + ty * 3) * OCW;
#pragma unroll
                    for (int tx = 0; tx < 3; tx++) {
                        float w[OCW];
#pragma unroll
                        for (int o4 = 0; o4 < OCW / 4; o4++)
                            *(float4*)(w + 4 * o4) = *(const float4*)(swp + tx * OCW + 4 * o4);
#pragma unroll
                        for (int o = 0; o < OCW; o++)
#pragma unroll
                            for (int xx = 0; xx < 4; xx++) acc[o][xx] += w[o] * r[xx + tx];
                    }
                }
            }
        }
    } else {
#pragma unroll 1
        for (int ic = 0; ic < CIN; ic++) {
            const float* inc = inb + ic * Din * Din * Din;
#pragma unroll 1
            for (int tz = 0; tz < 3; tz++) {
                int iz = 2 * z + tz - 1; if ((unsigned)iz >= (unsigned)Din) continue;
#pragma unroll
                for (int ty = 0; ty < 3; ty++) {
                    int iy = 2 * y + ty - 1; if ((unsigned)iy >= (unsigned)Din) continue;
                    const float* row = inc + (iz * Din + iy) * Din;
                    float4 v0 = *(const float4*)(row + 2 * x0);
                    float4 v1 = *(const float4*)(row + 2 * x0 + 4);
                    float r[9];
                    r[0] = (x0 > 0) ? row[2 * x0 - 1] : 0.f;
                    r[1] = v0.x; r[2] = v0.y; r[3] = v0.z; r[4] = v0.w;
                    r[5] = v1.x; r[6] = v1.y; r[7] = v1.z; r[8] = v1.w;
                    const float* swp = sw + (ic * 27 + tz * 9 + ty * 3) * OCW;
#pragma unroll
                    for (int tx = 0; tx < 3; tx++) {
                        float w[OCW];
#pragma unroll
                        for (int o4 = 0; o4 < OCW / 4; o4++)
                            *(float4*)(w + 4 * o4) = *(const float4*)(swp + tx * OCW + 4 * o4);
#pragma unroll
                        for (int o = 0; o < OCW; o++)
#pragma unroll
                            for (int xx = 0; xx < 4; xx++) acc[o][xx] += w[o] * r[2 * xx + tx];
                    }
                }
            }
        }
    }
    if (CL) {
        // channel-last: out[b][pos][COUT], 8 contiguous channels per store pair
        int pos = (z * Dout + y) * Dout + x0;
#pragma unroll
        for (int xx = 0; xx < 4; xx++) {
            float s[OCW];
#pragma unroll
            for (int o = 0; o < OCW; o++) {
                s[o] = acc[o][xx];
                if (act) s[o] = silu(s[o]);
            }
            float* op = out + ((size_t)b * spatial + pos + xx) * COUT + oc0;
#pragma unroll
            for (int o4 = 0; o4 < OCW / 4; o4++)
                *(float4*)(op + 4 * o4) = *(float4*)(s + 4 * o4);
        }
    } else {
        int obase0 = (z * Dout + y) * Dout + x0;
#pragma unroll
        for (int o = 0; o < OCW; o++) {
            float s0 = acc[o][0], s1 = acc[o][1], s2 = acc[o][2], s3 = acc[o][3];
            if (act) { s0 = silu(s0); s1 = silu(s1); s2 = silu(s2); s3 = silu(s3); }
            *(float4*)(out + (size_t)(b * COUT + oc0 + o) * spatial + obase0) =
                make_float4(s0, s1, s2, s3);
        }
    }
}

// ---------------- SIMT 3x3x3 conv, stride 1, XW=8, OCW=8 ----------------
template<int CIN, int OCW>
__launch_bounds__(256)
__global__ void conv_k3_x8(const float* __restrict__ in, const float* __restrict__ wt,
                           const float* __restrict__ bias, float* __restrict__ out,
                           int Din, int COUT, int act)
{
    extern __shared__ float sw[];
    const int oc0 = blockIdx.y * OCW;
    const int b   = blockIdx.z;
    for (int idx = threadIdx.x; idx < CIN * 27 * OCW; idx += 256) {
        int r = idx / OCW, o = idx % OCW;
        sw[idx] = wt[(oc0 + o) * (CIN * 27) + r];
    }
    __syncthreads();
    const int spatial = Din * Din * Din;
    int gpos = (blockIdx.x * 256 + threadIdx.x) * 8;
    if (gpos >= spatial) return;
    int x0 = gpos % Din; int t1 = gpos / Din; int y = t1 % Din; int z = t1 / Din;

    float acc[OCW][8];
#pragma unroll
    for (int o = 0; o < OCW; o++) {
        float bv = bias[oc0 + o];
#pragma unroll
        for (int xx = 0; xx < 8; xx++) acc[o][xx] = bv;
    }
    const float* inb = in + b * CIN * Din * Din * Din;
#pragma unroll 1
    for (int ic = 0; ic < CIN; ic++) {
        const float* inc = inb + ic * Din * Din * Din;
#pragma unroll 1
        for (int tz = 0; tz < 3; tz++) {
            int iz = z + tz - 1; if ((unsigned)iz >= (unsigned)Din) continue;
#pragma unroll
            for (int ty = 0; ty < 3; ty++) {
                int iy = y + ty - 1; if ((unsigned)iy >= (unsigned)Din) continue;
                const float* row = inc + (iz * Din + iy) * Din;
                float4 v0 = *(const float4*)(row + x0);
                float4 v1 = *(const float4*)(row + x0 + 4);
                float r[10];
                r[0] = (x0 > 0) ? row[x0 - 1] : 0.f;
                r[1] = v0.x; r[2] = v0.y; r[3] = v0.z; r[4] = v0.w;
                r[5] = v1.x; r[6] = v1.y; r[7] = v1.z; r[8] = v1.w;
                r[9] = (x0 + 8 < Din) ? row[x0 + 8] : 0.f;
                const float* swp = sw + (ic * 27 + tz * 9 + ty * 3) * OCW;
#pragma unroll
                for (int tx = 0; tx < 3; tx++) {
                    float w[OCW];
#pragma unroll
                    for (int o4 = 0; o4 < OCW / 4; o4++)
                        *(float4*)(w + 4 * o4) = *(const float4*)(swp + tx * OCW + 4 * o4);
#pragma unroll
                    for (int o = 0; o < OCW; o++)
#pragma unroll
                        for (int xx = 0; xx < 8; xx++) acc[o][xx] += w[o] * r[xx + tx];
                }
            }
        }
    }
    int obase0 = (z * Din + y) * Din + x0;
#pragma unroll
    for (int o = 0; o < OCW; o++) {
        float s[8];
#pragma unroll
        for (int xx = 0; xx < 8; xx++) {
            s[xx] = acc[o][xx];
            if (act) s[xx] = silu(s[xx]);
        }
        float* op = out + (size_t)(b * COUT + oc0 + o) * spatial + obase0;
        *(float4*)op = make_float4(s[0], s[1], s[2], s[3]);
        *(float4*)(op + 4) = make_float4(s[4], s[5], s[6], s[7]);
    }
}

// ---------------- 1x1x1 convs ----------------
// quant_conv reading channel-last h: h_cl[b][p][128]
__global__ void quant_conv_cl_kernel(const float* __restrict__ h_cl, const float* __restrict__ w,
                                     const float* __restrict__ bias, float* __restrict__ seq)
{
    int i = blockIdx.x * 256 + threadIdx.x;
    if (i >= NTOK * EDIM) return;
    int e = i & 15; int p = (i >> 4) & 4095; int b = i >> 16;
    float acc = bias[e];
    const float4* hp = (const float4*)(h_cl + ((size_t)(b * 4096 + p)) * 128);
    const float4* wp = (const float4*)(w + e * 128);
#pragma unroll 8
    for (int ic4 = 0; ic4 < 32; ic4++) {
        float4 hv = hp[ic4], wv = wp[ic4];
        acc += wv.x * hv.x + wv.y * hv.y + wv.z * hv.z + wv.w * hv.w;
    }
    seq[i] = acc;
}

__global__ void post_quant_cl_kernel(const float* __restrict__ q, const float* __restrict__ w,
                                     const float* __restrict__ bias, float* __restrict__ out_cl)
{
    int i = blockIdx.x * 256 + threadIdx.x;
    if (i >= BATCH * 4096 * 128) return;
    int oc = i & 127; int p = (i >> 7) & 4095; int b = i >> 19;
    float acc = bias[oc];
    const float* qp = q + (b * EDIM) * 4096 + p;
    const float* wp = w + oc * EDIM;
#pragma unroll
    for (int e = 0; e < EDIM; e++) acc += wp[e] * qp[e * 4096];
    out_cl[i] = __uint_as_float(f2tf(acc));
}

// ---------------- VQ ----------------
__global__ void cnorm_kernel(const float* __restrict__ cb) {
    int k = blockIdx.x * 128 + threadIdx.x;
    if (k < KCODE) {
        float s = 0.f;
#pragma unroll
        for (int e = 0; e < EDIM; e++) { float c = cb[k * EDIM + e]; s += c * c; }
        g_cnorm[k] = s;
    }
}

__global__ void vq_kernel(const float* __restrict__ seq, const float* __restrict__ cb)
{
    __shared__ float stok[32 * 16];
    __shared__ float sc[128 * 16];
    __shared__ float sn[128];
    __shared__ float rd[128];
    __shared__ int   ri[128];
    const int nnz = g_nnz;
    const int tok0 = blockIdx.x * 32;
    if (tok0 >= nnz) return;
    const int tid = threadIdx.x;
    for (int i = tid; i < 512; i += 128) {
        int ti = tok0 + (i >> 4);
        int tok = g_toklist[ti < nnz ? ti : (nnz - 1)];
        stok[i] = seq[tok * 16 + (i & 15)];
    }
    __syncthreads();
    const int t = tid & 31, g = tid >> 5;
    float s[16];
#pragma unroll
    for (int e = 0; e < 16; e++) s[e] = stok[t * 16 + e];
    float best = 3.4e38f; int bidx = 0;
    for (int tile = 0; tile < KCODE / 128; tile++) {
        __syncthreads();
        for (int i = tid; i < 512; i += 128)
            *(float4*)&sc[i * 4] = *(const float4*)&cb[tile * 2048 + i * 4];
        if (tid < 128) sn[tid] = g_cnorm[tile * 128 + tid];
        __syncthreads();
#pragma unroll 4
        for (int kk = g; kk < 128; kk += 4) {
            const float4* c4 = (const float4*)&sc[kk * 16];
            float4 c0 = c4[0], c1 = c4[1], c2 = c4[2], c3 = c4[3];
            float dot = c0.x * s[0] + c0.y * s[1] + c0.z * s[2] + c0.w * s[3]
                      + c1.x * s[4] + c1.y * s[5] + c1.z * s[6] + c1.w * s[7]
                      + c2.x * s[8] + c2.y * s[9] + c2.z * s[10] + c2.w * s[11]
                      + c3.x * s[12] + c3.y * s[13] + c3.z * s[14] + c3.w * s[15];
            float d = sn[kk] - 2.f * dot;
            if (d < best) { best = d; bidx = tile * 128 + kk; }
        }
    }
    rd[tid] = best; ri[tid] = bidx;
    __syncthreads();
    if (g == 0) {
        for (int gg = 1; gg < 4; gg++) {
            float d = rd[gg * 32 + t]; int k = ri[gg * 32 + t];
            if (d < best || (d == best && k < bidx)) { best = d; bidx = k; }
        }
        int ti = tok0 + t;
        if (ti < nnz) g_idx[g_toklist[ti]] = bidx;
    }
}

// ---------------- commit loss ----------------
__global__ void commit_kernel(const float* __restrict__ seq, const float* __restrict__ cb)
{
    __shared__ float sh[128];
    int t = blockIdx.x * 128 + threadIdx.x;
    float v = 0.f;
    if (!g_zmask[t]) {
        const float* s = seq + t * 16;
        const float* c = cb + g_idx[t] * 16;
        float a = 0.f;
#pragma unroll
        for (int e = 0; e < 16; e++) { float d = c[e] - s[e]; a += d * d; }
        v = a * (1.f / 16.f);
    }
    sh[threadIdx.x] = v; __syncthreads();
    for (int st = 64; st; st >>= 1) {
        if (threadIdx.x < st) sh[threadIdx.x] += sh[threadIdx.x + st];
        __syncthreads();
    }
    if (threadIdx.x == 0) g_part[blockIdx.x] = sh[0];
}

__global__ void commit_final(float* __restrict__ out) {
    if (threadIdx.x == 0) {
        float s = 0.f;
        for (int i = 0; i < 128; i++) s += g_part[i];
        out[0] = 0.25f * s / 16384.f;
    }
}

__global__ void fullidx_kernel(float* __restrict__ out) {
    int i = blockIdx.x * 256 + threadIdx.x;
    if (i < NTOK) out[i] = g_zmask[i] ? 0.f : (float)(g_idx[i] + 1);
}

__global__ void qbuild_kernel(const float* __restrict__ cb, const float* __restrict__ rep,
                              const float* __restrict__ pos)
{
    int i = blockIdx.x * 256 + threadIdx.x;
    if (i >= BATCH * EDIM * 4096) return;
    int p = i & 4095; int e = (i >> 12) & 15; int b = i >> 16;
    int tok = (b << 12) + p;
    float v = g_zmask[tok] ? rep[e] : cb[g_idx[tok] * 16 + e];
    g_q[i] = v + pos[e * 4096 + p];
}

// ---------------- launch ----------------
extern "C" void kernel_launch(void* const* d_in, const int* in_sizes, int n_in,
                              void* d_out_, int out_size)
{
    const unsigned char* x = (const unsigned char*)d_in[0];
    const float* enc_in_w  = (const float*)d_in[1];
    const float* enc_in_b  = (const float*)d_in[2];
    const float* enc_d1_w  = (const float*)d_in[3];
    const float* enc_d1_b  = (const float*)d_in[4];
    const float* enc_d2_w  = (const float*)d_in[5];
    const float* enc_d2_b  = (const float*)d_in[6];
    const float* enc_out_w = (const float*)d_in[7];
    const float* enc_out_b = (const float*)d_in[8];
    const float* quant_w   = (const float*)d_in[9];
    const float* quant_b   = (const float*)d_in[10];
    const float* codebook  = (const float*)d_in[11];
    const float* rep_tok   = (const float*)d_in[12];
    const float* pos_emb   = (const float*)d_in[13];
    const float* pq_w      = (const float*)d_in[14];
    const float* pq_b      = (const float*)d_in[15];
    const float* dec_in_w  = (const float*)d_in[16];
    const float* dec_in_b  = (const float*)d_in[17];
    const float* dec_u1_w  = (const float*)d_in[18];
    const float* dec_u1_b  = (const float*)d_in[19];
    const float* dec_u2_w  = (const float*)d_in[20];
    const float* dec_u2_b  = (const float*)d_in[21];
    const float* dec_out_w = (const float*)d_in[22];
    const float* dec_out_b = (const float*)d_in[23];
    float* out = (float*)d_out_;

    float *pA, *pB, *pC, *pD, *pSeq, *pQ, *pCL, *pW, *pW1, *pW2;
    cudaGetSymbolAddress((void**)&pA, g_bufA);
    cudaGetSymbolAddress((void**)&pB, g_bufB);
    cudaGetSymbolAddress((void**)&pC, g_bufC);
    cudaGetSymbolAddress((void**)&pD, g_bufD);
    cudaGetSymbolAddress((void**)&pSeq, g_seq);
    cudaGetSymbolAddress((void**)&pQ, g_q);
    cudaGetSymbolAddress((void**)&pCL, g_cl);
    cudaGetSymbolAddress((void**)&pW, g_wt);
    cudaGetSymbolAddress((void**)&pW1, g_wt1);
    cudaGetSymbolAddress((void**)&pW2, g_wt2);
    cudaFuncSetAttribute((conv_k3<64, 8, 1>), cudaFuncAttributeMaxDynamicSharedMemorySize, 65536);
    cudaFuncSetAttribute(conv_mma_dec, cudaFuncAttributeMaxDynamicSharedMemorySize, 2 * STAGE_F * 4);
    cudaFuncSetAttribute(conv_mma_3x,  cudaFuncAttributeMaxDynamicSharedMemorySize, 2 * STG3 * 4);
    cudaFuncSetAttribute((tconv_mma<128, 64, 16, 4, 1>), cudaFuncAttributeMaxDynamicSharedMemorySize, 55296);
    cudaFuncSetAttribute((tconv_mma<64, 32, 32, 5, 0>),  cudaFuncAttributeMaxDynamicSharedMemorySize, 47104);

    float* mc = out + OFF_MC;
    dim3 blk(256);

    initflag_kernel<<<1, 1>>>();
    scan_kernel<<<4096, 256>>>((const unsigned int*)x);
    pack_kernel<<<N_MC / 256, 256>>>(x, mc);

    // encoder: enc_in/d1/d2 fp32 SIMT, enc_out 3xtf32 mma (fp32-accurate)
    conv_k3_x8<8, 8><<<dim3(128, 4, 4), blk, 8 * 27 * 8 * 4>>>(mc, enc_in_w, enc_in_b, pA, 64, 32, 1);
    zmask_kernel<<<512, 256>>>(mc);
    conv_k3<32, 8, 0><<<dim3(32, 8, 4), blk, 32 * 27 * 8 * 4>>>(pA, enc_d1_w, enc_d1_b, pB, 64, 32, 2, 64, 1);
    conv_k3<64, 8, 1><<<dim3(4, 16, 4), blk, 64 * 27 * 8 * 4>>>(pB, enc_d2_w, enc_d2_b, pCL, 32, 16, 2, 128, 1);
    wtrans_hilo<<<1728, 256>>>(enc_out_w);
    conv_mma_3x<<<dim3(32, 1, 4), 256, 2 * STG3 * 4>>>(pCL, enc_out_b, pD);   // pD = h channel-last fp32

    wtrans2<<<1728, 256>>>(dec_in_w, pW, 128, 128);
    wtrans2<<<864, 256>>>(dec_u1_w, pW1, 128, 64);
    wtrans2<<<216, 256>>>(dec_u2_w, pW2, 64, 32);

    // quantization path
    cnorm_kernel<<<KCODE / 128, 128>>>(codebook);
    quant_conv_cl_kernel<<<(NTOK * EDIM) / 256, 256>>>(pD, quant_w, quant_b, pSeq);
    vq_kernel<<<NTOK / 32, 128>>>(pSeq, codebook);
    commit_kernel<<<NTOK / 128, 128>>>(pSeq, codebook);
    commit_final<<<1, 1>>>(out + OFF_COMMIT);
    fullidx_kernel<<<NTOK / 256, 256>>>(out + OFF_IDX);
    qbuild_kernel<<<(BATCH * EDIM * 4096) / 256, 256>>>(codebook, rep_tok, pos_emb);
    post_quant_cl_kernel<<<(BATCH * 4096 * 128) / 256, 256>>>(pQ, pq_w, pq_b, pCL);

    // decoder: dec_in + both tconvs on tensor cores (tf32), dec_out SIMT XW=8
    conv_mma_dec<<<dim3(32, 1, 4), 256, 2 * STAGE_F * 4>>>(pCL, dec_in_b, pD);
    tconv_mma<128, 64, 16, 4, 1><<<dim3(32, 8, 4), 256, 55296>>>(pD, pW1, dec_u1_b, pB);
    tconv_mma<64, 32, 32, 5, 0><<<dim3(256, 8, 4), 256, 47104>>>(pB, pW2, dec_u2_b, pA);
    conv_k3_x8<32, 8><<<dim3(128, 1, 4), blk, 32 * 27 * 8 * 4>>>(pA, dec_out_w, dec_out_b, out, 64, 8, 0);
}

// round 12
// speedup vs baseline: 1.2876x; 1.0912x over previous
#include <cuda_runtime.h>
#include <math.h>
#include <cstdint>

// ---------------- problem constants ----------------
#define BATCH 4
#define D64   64
#define D32   32
#define D16   16
#define NTOK  (BATCH*4096)
#define EDIM  16
#define KCODE 8192
#define N_MC  (BATCH*8*D64*D64*D64)
#define OFF_MC     8388608
#define OFF_COMMIT 16777216
#define OFF_IDX    16777217

// ---------------- device scratch ----------------
__device__ float g_bufA[BATCH*32*D64*D64*D64];    // enc_in out CL / dec_u2 out CF
__device__ float g_bufB[BATCH*64*D32*D32*D32];    // enc_d1 out CL / dec_u1 out CL
__device__ float g_bufC[BATCH*128*D16*D16*D16];
__device__ float g_bufD[BATCH*128*D16*D16*D16];   // h CL / dec_in out CL
__device__ float g_seq[NTOK*EDIM];
__device__ float g_q[BATCH*EDIM*4096];
__device__ float g_cl[BATCH*4096*128];            // enc_d2 out CL / post_quant out CL
__device__ float g_wt [27*128*128];               // dec_in weights (tf32)
__device__ float g_wt1[27*128*64];                // dec_u1
__device__ float g_wt2[27*64*32];                 // dec_u2
__device__ float g_wh0[27*128*128];               // enc_out hi
__device__ float g_wl0[27*128*128];               // enc_out lo
__device__ float g_wh1[27*32*64];                 // enc_d1 hi
__device__ float g_wl1[27*32*64];                 // enc_d1 lo
__device__ float g_wh2[27*64*128];                // enc_d2 hi
__device__ float g_wl2[27*64*128];                // enc_d2 lo
__device__ float g_cnorm[KCODE];
__device__ float g_part[128];
__device__ int   g_idx[NTOK];
__device__ unsigned char g_zmask[NTOK];
__device__ int   g_flags;
__device__ int   g_nnz;
__device__ int   g_toklist[NTOK];

__device__ __forceinline__ float silu(float v) { return v * __frcp_rn(1.f + __expf(-v)); }

__device__ __forceinline__ uint32_t f2tf(float f) {
    uint32_t r; asm("cvt.rna.tf32.f32 %0, %1;" : "=r"(r) : "f"(f)); return r;
}
__device__ __forceinline__ void mma_tf32(float* d, const uint32_t* a, const uint32_t* b) {
    asm volatile("mma.sync.aligned.m16n8k8.row.col.f32.tf32.tf32.f32 "
                 "{%0,%1,%2,%3}, {%4,%5,%6,%7}, {%8,%9}, {%0,%1,%2,%3};"
                 : "+f"(d[0]), "+f"(d[1]), "+f"(d[2]), "+f"(d[3])
                 : "r"(a[0]), "r"(a[1]), "r"(a[2]), "r"(a[3]), "r"(b[0]), "r"(b[1]));
}

// -------- weight transform: w[OC][IC][27] -> dst[tap][ic][oc], tf32-rounded --------
__global__ void wtrans2(const float* __restrict__ w, float* __restrict__ dst, int IC, int OC) {
    int i = blockIdx.x * 256 + threadIdx.x;
    int total = 27 * IC * OC;
    if (i >= total) return;
    int tap = i / (IC * OC); int rem = i % (IC * OC); int ic = rem / OC; int oc = rem % OC;
    dst[i] = __uint_as_float(f2tf(w[(oc * IC + ic) * 27 + tap]));
}

// -------- hi/lo split weight transform (3xtf32): w[OC][IC][27] -> [tap][ic][oc] --------
__global__ void wtrans_hilo(const float* __restrict__ w, float* __restrict__ dh,
                            float* __restrict__ dl, int IC, int OC) {
    int i = blockIdx.x * 256 + threadIdx.x;
    int total = 27 * IC * OC;
    if (i >= total) return;
    int tap = i / (IC * OC); int rem = i % (IC * OC); int ic = rem / OC; int oc = rem % OC;
    float v = w[(oc * IC + ic) * 27 + tap];
    float hi = __uint_as_float(f2tf(v));
    dh[i] = hi;
    dl[i] = __uint_as_float(f2tf(v - hi));
}

#define SA 36

// ---------- 3xtf32 error-compensated implicit GEMM conv (fp32-accurate) ----------
// in_cl: channel-last fp32 [B][DIN^3][CIN]; out_cl: channel-last fp32 [B][DOUT^3][COUT].
// STRIDE 1 or 2 (DIN = DOUT*STRIDE), pad 1, kernel 3. ACT: silu.
template<int CIN, int COUT, int DOUT, int LOGD, int STRIDE, int ACT>
__launch_bounds__(256)
__global__ void conv_mma3(const float* __restrict__ in_cl, const float* __restrict__ wh,
                          const float* __restrict__ wl, const float* __restrict__ bias,
                          float* __restrict__ out_cl)
{
    extern __shared__ float dsm[];
    constexpr int NW_N = COUT / 32;
    constexpr int NW_M = 8 / NW_N;
    constexpr int MT = 128 / (NW_M * 16);
    constexpr int SBs = COUT + 8;
    constexpr int STG = 2 * 128 * SA + 2 * 32 * SBs;
    constexpr int NIC = CIN / 32;
    constexpr int DIN = DOUT * STRIDE;
    constexpr int BF4 = COUT / 32;
    constexpr int NCH = 27 * NIC;

    const int tid = threadIdx.x;
    const int lane = tid & 31, wid = tid >> 5;
    const int wm = wid / NW_N, wn = wid % NW_N;
    const int bb = blockIdx.z;
    const int pos0 = blockIdx.x * 128;
    const float* inb = in_cl + (size_t)bb * (DIN * DIN * DIN) * CIN;

    float acc[MT][4][4];
#pragma unroll
    for (int mt = 0; mt < MT; mt++)
#pragma unroll
        for (int nt = 0; nt < 4; nt++)
#pragma unroll
            for (int k = 0; k < 4; k++) acc[mt][nt][k] = 0.f;

    const int ar = tid >> 1, aseg = tid & 1;
    const int apos = pos0 + ar;
    const int gx = apos & (DOUT - 1), gy = (apos >> LOGD) & (DOUT - 1), gz = apos >> (2 * LOGD);
    const int bk = tid >> 3, bseg = tid & 7;

    float4 ra[4], rbh[BF4], rbl[BF4];
    auto ldg = [&](int c) {
        int tap = c / NIC, ic0 = (c % NIC) * 32;
        int tz = tap / 9, ty = (tap / 3) % 3, tx = tap % 3;
        int ix = STRIDE * gx + tx - 1, iy = STRIDE * gy + ty - 1, iz = STRIDE * gz + tz - 1;
        bool valid = ((unsigned)ix < (unsigned)DIN) & ((unsigned)iy < (unsigned)DIN)
                   & ((unsigned)iz < (unsigned)DIN);
        if (valid) {
            const float4* sa = (const float4*)(inb + (size_t)((iz * DIN + iy) * DIN + ix) * CIN
                                               + ic0 + aseg * 16);
            ra[0] = sa[0]; ra[1] = sa[1]; ra[2] = sa[2]; ra[3] = sa[3];
        } else {
            ra[0] = ra[1] = ra[2] = ra[3] = make_float4(0.f, 0.f, 0.f, 0.f);
        }
        size_t woff = (size_t)(tap * CIN + ic0 + bk) * COUT + bseg * (COUT / 8);
        const float4* sbh = (const float4*)(wh + woff);
        const float4* sbl = (const float4*)(wl + woff);
#pragma unroll
        for (int j = 0; j < BF4; j++) { rbh[j] = sbh[j]; rbl[j] = sbl[j]; }
    };
    auto sts = [&](int s) {
        float* Ah = dsm + s * STG;
        float* Al = Ah + 128 * SA;
        float* Bh = Al + 128 * SA;
        float* Bl = Bh + 32 * SBs;
#pragma unroll
        for (int j = 0; j < 4; j++) {
            float4 v = ra[j];
            uint4 h, l;
            h.x = f2tf(v.x); l.x = f2tf(v.x - __uint_as_float(h.x));
            h.y = f2tf(v.y); l.y = f2tf(v.y - __uint_as_float(h.y));
            h.z = f2tf(v.z); l.z = f2tf(v.z - __uint_as_float(h.z));
            h.w = f2tf(v.w); l.w = f2tf(v.w - __uint_as_float(h.w));
            *(uint4*)(Ah + ar * SA + aseg * 16 + 4 * j) = h;
            *(uint4*)(Al + ar * SA + aseg * 16 + 4 * j) = l;
        }
#pragma unroll
        for (int j = 0; j < BF4; j++) {
            *(float4*)(Bh + bk * SBs + bseg * (COUT / 8) + 4 * j) = rbh[j];
            *(float4*)(Bl + bk * SBs + bseg * (COUT / 8) + 4 * j) = rbl[j];
        }
    };
    const int rq = lane >> 2, cq = lane & 3;
    auto dom = [&](const uint32_t* Au, const uint32_t* Bu) {
#pragma unroll
        for (int q = 0; q < 4; q++) {
            const int kk = q * 8 + cq;
            uint32_t af[MT][4], bf[4][2];
#pragma unroll
            for (int mt = 0; mt < MT; mt++) {
                int row = wm * (MT * 16) + mt * 16 + rq;
                af[mt][0] = Au[row * SA + kk];
                af[mt][1] = Au[(row + 8) * SA + kk];
                af[mt][2] = Au[row * SA + kk + 4];
                af[mt][3] = Au[(row + 8) * SA + kk + 4];
            }
#pragma unroll
            for (int nt = 0; nt < 4; nt++) {
                int col = wn * 32 + nt * 8 + rq;
                bf[nt][0] = Bu[kk * SBs + col];
                bf[nt][1] = Bu[(kk + 4) * SBs + col];
            }
#pragma unroll
            for (int mt = 0; mt < MT; mt++)
#pragma unroll
                for (int nt = 0; nt < 4; nt++)
                    mma_tf32(acc[mt][nt], af[mt], bf[nt]);
        }
    };
    auto domma3 = [&](int s) {
        const uint32_t* Ah = (const uint32_t*)(dsm + s * STG);
        const uint32_t* Al = Ah + 128 * SA;
        const uint32_t* Bh = Al + 128 * SA;
        const uint32_t* Bl = Bh + 32 * SBs;
        dom(Ah, Bh);
        dom(Ah, Bl);
        dom(Al, Bh);
    };

    ldg(0); sts(0); __syncthreads();
#pragma unroll 1
    for (int c = 0; c < NCH; c++) {
        if (c + 1 < NCH) ldg(c + 1);
        domma3(c & 1);
        if (c + 1 < NCH) sts((c + 1) & 1);
        __syncthreads();
    }

    constexpr int SE = COUT + 1;
    float* E = dsm;
#pragma unroll
    for (int mt = 0; mt < MT; mt++)
#pragma unroll
        for (int nt = 0; nt < 4; nt++) {
            int row = wm * (MT * 16) + mt * 16 + rq;
            int col = wn * 32 + nt * 8 + 2 * cq;
            E[row * SE + col]           = acc[mt][nt][0];
            E[row * SE + col + 1]       = acc[mt][nt][1];
            E[(row + 8) * SE + col]     = acc[mt][nt][2];
            E[(row + 8) * SE + col + 1] = acc[mt][nt][3];
        }
    __syncthreads();
    float* ob = out_cl + ((size_t)bb * (DOUT * DOUT * DOUT) + pos0 + ar) * COUT;
#pragma unroll
    for (int j4 = 0; j4 < COUT / 8; j4++) {
        float4 v; float* pv = (float*)&v;
#pragma unroll
        for (int t = 0; t < 4; t++) {
            int ch = aseg * (COUT / 2) + j4 * 4 + t;
            float x = E[ar * SE + ch] + bias[ch];
            pv[t] = ACT ? silu(x) : x;
        }
        *(float4*)(ob + aseg * (COUT / 2) + j4 * 4) = v;
    }
}

// ---------- mma.sync tf32 implicit-GEMM 3x3x3 conv (128->128, 16^3), dec_in ----------
#define SB 136
#define STAGE_F (128*SA + 32*SB)

__launch_bounds__(256)
__global__ void conv_mma_dec(const float* __restrict__ in_cl, const float* __restrict__ bias,
                             float* __restrict__ out_cl)
{
    extern __shared__ float dsm[];
    const int tid = threadIdx.x;
    const int lane = tid & 31, wid = tid >> 5;
    const int wm = wid >> 2, wn = wid & 3;
    const int bb = blockIdx.z;
    const int pos0 = blockIdx.x * 128;
    const float* inb = in_cl + (size_t)bb * 4096 * 128;

    float acc[4][4][4];
#pragma unroll
    for (int mt = 0; mt < 4; mt++)
#pragma unroll
        for (int nt = 0; nt < 4; nt++)
#pragma unroll
            for (int k = 0; k < 4; k++) acc[mt][nt][k] = 0.f;

    const int ar = tid >> 1, aseg = tid & 1;
    const int apos = pos0 + ar;
    const int ax = apos & 15, ay = (apos >> 4) & 15, az = apos >> 8;
    const int bk = tid >> 3, bseg = tid & 7;

    float4 ra[4], rb[4];
    auto ldg = [&](int c) {
        int tap = c >> 2, ic0 = (c & 3) * 32;
        int tz = tap / 9, ty = (tap / 3) % 3, tx = tap % 3;
        int xx = ax + tx - 1, yy = ay + ty - 1, zz = az + tz - 1;
        bool valid = ((unsigned)xx < 16u) & ((unsigned)yy < 16u) & ((unsigned)zz < 16u);
        if (valid) {
            const float4* sa = (const float4*)(inb + (size_t)((zz * 16 + yy) * 16 + xx) * 128
                                               + ic0 + aseg * 16);
            ra[0] = sa[0]; ra[1] = sa[1]; ra[2] = sa[2]; ra[3] = sa[3];
        } else {
            ra[0] = ra[1] = ra[2] = ra[3] = make_float4(0.f, 0.f, 0.f, 0.f);
        }
        const float4* sb = (const float4*)(g_wt + (size_t)(tap * 128 + ic0 + bk) * 128
                                           + bseg * 16);
        rb[0] = sb[0]; rb[1] = sb[1]; rb[2] = sb[2]; rb[3] = sb[3];
    };
    auto sts = [&](int s) {
        float* Au = dsm + s * STAGE_F;
        float* Bu = Au + 128 * SA;
#pragma unroll
        for (int j = 0; j < 4; j++) {
            *(float4*)(Au + ar * SA + aseg * 16 + 4 * j) = ra[j];
            *(float4*)(Bu + bk * SB + bseg * 16 + 4 * j) = rb[j];
        }
    };
    auto domma = [&](int s) {
        const uint32_t* Au = (const uint32_t*)(dsm + s * STAGE_F);
        const uint32_t* Bu = Au + 128 * SA;
        const int rq = lane >> 2, cq = lane & 3;
#pragma unroll
        for (int q = 0; q < 4; q++) {
            const int kk = q * 8 + cq;
            uint32_t af[4][4], bf[4][2];
#pragma unroll
            for (int mt = 0; mt < 4; mt++) {
                int row = wm * 64 + mt * 16 + rq;
                af[mt][0] = Au[row * SA + kk];
                af[mt][1] = Au[(row + 8) * SA + kk];
                af[mt][2] = Au[row * SA + kk + 4];
                af[mt][3] = Au[(row + 8) * SA + kk + 4];
            }
#pragma unroll
            for (int nt = 0; nt < 4; nt++) {
                int col = wn * 32 + nt * 8 + rq;
                bf[nt][0] = Bu[kk * SB + col];
                bf[nt][1] = Bu[(kk + 4) * SB + col];
            }
#pragma unroll
            for (int mt = 0; mt < 4; mt++)
#pragma unroll
                for (int nt = 0; nt < 4; nt++)
                    mma_tf32(acc[mt][nt], af[mt], bf[nt]);
        }
    };

    ldg(0); sts(0); __syncthreads();
#pragma unroll 1
    for (int c = 0; c < 108; c++) {
        if (c < 107) ldg(c + 1);
        domma(c & 1);
        if (c < 107) sts((c + 1) & 1);
        __syncthreads();
    }

    float* E = dsm;
    const int rq = lane >> 2, cq = lane & 3;
#pragma unroll
    for (int mt = 0; mt < 4; mt++)
#pragma unroll
        for (int nt = 0; nt < 4; nt++) {
            int row = wm * 64 + mt * 16 + rq;
            int col = wn * 32 + nt * 8 + 2 * cq;
            E[row * 129 + col]           = acc[mt][nt][0];
            E[row * 129 + col + 1]       = acc[mt][nt][1];
            E[(row + 8) * 129 + col]     = acc[mt][nt][2];
            E[(row + 8) * 129 + col + 1] = acc[mt][nt][3];
        }
    __syncthreads();
    float* ob = out_cl + ((size_t)bb * 4096 + pos0 + ar) * 128;
#pragma unroll
    for (int j4 = 0; j4 < 16; j4++) {
        float4 v; float* pv = (float*)&v;
#pragma unroll
        for (int t = 0; t < 4; t++) {
            int ch = aseg * 64 + j4 * 4 + t;
            float x = E[ar * 129 + ch] + bias[ch];
            pv[t] = __uint_as_float(f2tf(silu(x)));
        }
        *(float4*)(ob + aseg * 64 + j4 * 4) = v;
    }
}

// ---------- mma.sync tf32 transposed conv via octant decomposition ----------
template<int CIN, int COUT, int DIN, int LOGD, int CLOUT>
__launch_bounds__(256)
__global__ void tconv_mma(const float* __restrict__ in_cl, const float* __restrict__ wtr,
                          const float* __restrict__ bias, float* __restrict__ out)
{
    extern __shared__ float dsm[];
    constexpr int NW_N = COUT / 32;
    constexpr int NW_M = 8 / NW_N;
    constexpr int MT = 128 / (NW_M * 16);
    constexpr int SAs = 36;
    constexpr int SBs = COUT + 8;
    constexpr int STG = 128 * SAs + 32 * SBs;
    constexpr int NIC = CIN / 32;
    constexpr int DOUT = 2 * DIN;
    constexpr int BF4 = COUT / 32;

    const int tid = threadIdx.x;
    const int lane = tid & 31, wid = tid >> 5;
    const int wm = wid / NW_N, wn = wid % NW_N;
    const int bb = blockIdx.z;
    const int oct = blockIdx.y;
    const int px = oct & 1, py = (oct >> 1) & 1, pz = (oct >> 2) & 1;
    const int ntx = 2 - px, nty = 2 - py;
    const int nchunks = ntx * nty * (2 - pz) * NIC;
    const int pos0 = blockIdx.x * 128;
    const float* inb = in_cl + (size_t)bb * (DIN * DIN * DIN) * CIN;

    float acc[MT][4][4];
#pragma unroll
    for (int mt = 0; mt < MT; mt++)
#pragma unroll
        for (int nt = 0; nt < 4; nt++)
#pragma unroll
            for (int k = 0; k < 4; k++) acc[mt][nt][k] = 0.f;

    const int ar = tid >> 1, aseg = tid & 1;
    const int pa = pos0 + ar;
    const int gx = pa & (DIN - 1), gy = (pa >> LOGD) & (DIN - 1), gz = pa >> (2 * LOGD);
    const int bk = tid >> 3, bseg = tid & 7;

    float4 ra[4], rb[BF4];

    auto ldg = [&](int c) {
        int tap = c / NIC, ic0 = (c % NIC) * 32;
        int txi = tap % ntx; int r2 = tap / ntx; int tyi = r2 % nty; int tzi = r2 / nty;
        int tx = px ? 1 : txi * 2, ty = py ? 1 : tyi * 2, tz = pz ? 1 : tzi * 2;
        int ix = gx + (px ? 0 : txi - 1);
        int iy = gy + (py ? 0 : tyi - 1);
        int iz = gz + (pz ? 0 : tzi - 1);
        bool valid = (ix >= 0) && (iy >= 0) && (iz >= 0);
        if (valid) {
            const float4* sa = (const float4*)(inb + (size_t)((iz * DIN + iy) * DIN + ix) * CIN
                                               + ic0 + aseg * 16);
            ra[0] = sa[0]; ra[1] = sa[1]; ra[2] = sa[2]; ra[3] = sa[3];
        } else {
            ra[0] = ra[1] = ra[2] = ra[3] = make_float4(0.f, 0.f, 0.f, 0.f);
        }
        int tap27 = tz * 9 + ty * 3 + tx;
        const float4* sb = (const float4*)(wtr + ((size_t)(tap27 * CIN) + ic0 + bk) * COUT
                                           + bseg * (COUT / 8));
#pragma unroll
        for (int j = 0; j < BF4; j++) rb[j] = sb[j];
    };
    auto sts = [&](int s) {
        float* Au = dsm + s * STG;
        float* Bu = Au + 128 * SAs;
#pragma unroll
        for (int j = 0; j < 4; j++)
            *(float4*)(Au + ar * SAs + aseg * 16 + 4 * j) = ra[j];
#pragma unroll
        for (int j = 0; j < BF4; j++)
            *(float4*)(Bu + bk * SBs + bseg * (COUT / 8) + 4 * j) = rb[j];
    };
    auto domma = [&](int s) {
        const uint32_t* Au = (const uint32_t*)(dsm + s * STG);
        const uint32_t* Bu = Au + 128 * SAs;
        const int rq = lane >> 2, cq = lane & 3;
#pragma unroll
        for (int q = 0; q < 4; q++) {
            const int kk = q * 8 + cq;
            uint32_t af[MT][4], bf[4][2];
#pragma unroll
            for (int mt = 0; mt < MT; mt++) {
                int row = wm * (MT * 16) + mt * 16 + rq;
                af[mt][0] = Au[row * SAs + kk];
                af[mt][1] = Au[(row + 8) * SAs + kk];
                af[mt][2] = Au[row * SAs + kk + 4];
                af[mt][3] = Au[(row + 8) * SAs + kk + 4];
            }
#pragma unroll
            for (int nt = 0; nt < 4; nt++) {
                int col = wn * 32 + nt * 8 + rq;
                bf[nt][0] = Bu[kk * SBs + col];
                bf[nt][1] = Bu[(kk + 4) * SBs + col];
            }
#pragma unroll
            for (int mt = 0; mt < MT; mt++)
#pragma unroll
                for (int nt = 0; nt < 4; nt++)
                    mma_tf32(acc[mt][nt], af[mt], bf[nt]);
        }
    };

    ldg(0); sts(0); __syncthreads();
#pragma unroll 1
    for (int c = 0; c < nchunks; c++) {
        if (c + 1 < nchunks) ldg(c + 1);
        domma(c & 1);
        if (c + 1 < nchunks) sts((c + 1) & 1);
        __syncthreads();
    }

    float* E = dsm;
    const int rq = lane >> 2, cq = lane & 3;
    if (CLOUT) {
        constexpr int SE = COUT + 1;
#pragma unroll
        for (int mt = 0; mt < MT; mt++)
#pragma unroll
            for (int nt = 0; nt < 4; nt++) {
                int row = wm * (MT * 16) + mt * 16 + rq;
                int col = wn * 32 + nt * 8 + 2 * cq;
                E[row * SE + col]           = acc[mt][nt][0];
                E[row * SE + col + 1]       = acc[mt][nt][1];
                E[(row + 8) * SE + col]     = acc[mt][nt][2];
                E[(row + 8) * SE + col + 1] = acc[mt][nt][3];
            }
        __syncthreads();
        int opos = ((2 * gz + pz) * DOUT + (2 * gy + py)) * DOUT + (2 * gx + px);
        float* ob = out + ((size_t)bb * DOUT * DOUT * DOUT + opos) * COUT;
#pragma unroll
        for (int j4 = 0; j4 < COUT / 8; j4++) {
            float4 v; float* pv = (float*)&v;
#pragma unroll
            for (int t = 0; t < 4; t++) {
                int ch = aseg * (COUT / 2) + j4 * 4 + t;
                float x = E[ar * SE + ch] + bias[ch];
                pv[t] = __uint_as_float(f2tf(silu(x)));
            }
            *(float4*)(ob + aseg * (COUT / 2) + j4 * 4) = v;
        }
    } else {
        constexpr int SE = 36;
#pragma unroll
        for (int mt = 0; mt < MT; mt++)
#pragma unroll
            for (int nt = 0; nt < 4; nt++) {
                int row = wm * (MT * 16) + mt * 16 + rq;
                int col = nt * 8 + 2 * cq;
                E[row * SE + col]           = acc[mt][nt][0];
                E[row * SE + col + 1]       = acc[mt][nt][1];
                E[(row + 8) * SE + col]     = acc[mt][nt][2];
                E[(row + 8) * SE + col + 1] = acc[mt][nt][3];
            }
        __syncthreads();
        int ch = tid >> 3;
        float bv = bias[ch];
        float* ob = out + ((size_t)bb * COUT + ch) * (DOUT * DOUT * DOUT);
#pragma unroll
        for (int j = 0; j < 16; j++) {
            int p = (tid & 7) + 8 * j;
            int pp = pos0 + p;
            int hx = pp & (DIN - 1), hy = (pp >> LOGD) & (DIN - 1), hz = pp >> (2 * LOGD);
            int opos = ((2 * hz + pz) * DOUT + (2 * hy + py)) * DOUT + (2 * hx + px);
            ob[opos] = silu(E[p * SE + ch] + bv);
        }
    }
}

// ---------------- input dtype probe ----------------
__global__ void initflag_kernel() { g_flags = 0; g_nnz = 0; }

__global__ void scan_kernel(const unsigned int* __restrict__ xw) {
    int base = blockIdx.x * 256 + threadIdx.x;
    unsigned int f = 0, u = 0;
#pragma unroll
    for (int j = 0; j < 16; j++) {
        unsigned int w = xw[base + j * 1048576];
        f |= (w & 0xFEFEFEFEu);
        u |= (w & 0x01010100u);
    }
    int bits = (f ? 1 : 0) | (u ? 2 : 0);
    if (bits) atomicOr(&g_flags, bits);
}

// ---------------- bit pack ----------------
__global__ void pack_kernel(const unsigned char* __restrict__ xb, float* __restrict__ mc) {
    int i = blockIdx.x * 256 + threadIdx.x;
    if (i >= N_MC) return;
    int k  = i & 63;
    int j  = (i >> 6) & 63;
    int zi = (i >> 12) & 63;
    int c  = (i >> 18) & 7;
    int b  = i >> 21;
    int a   = c >> 1;
    int bb0 = (2 * c) & 3;
    int base = (((b * 256) + 4 * zi + a) * 256 + 4 * j + bb0) * 256 + 4 * k;
    int s = 0;
    int flags = g_flags;
    if (flags & 1) {
        const float* xf = (const float*)xb;
        float4 f0 = *(const float4*)(xf + base);
        float4 f1 = *(const float4*)(xf + base + 256);
        if (f0.x != 0.f) s |= 1;   if (f0.y != 0.f) s |= 2;
        if (f0.z != 0.f) s |= 4;   if (f0.w != 0.f) s |= 8;
        if (f1.x != 0.f) s |= 16;  if (f1.y != 0.f) s |= 32;
        if (f1.z != 0.f) s |= 64;  if (f1.w != 0.f) s |= 128;
    } else if (flags & 2) {
        unsigned int r0 = *(const unsigned int*)(xb + base);
        unsigned int r1 = *(const unsigned int*)(xb + base + 256);
#pragma unroll
        for (int cc = 0; cc < 4; cc++) {
            if ((r0 >> (8 * cc)) & 0xFF) s |= 1 << cc;
            if ((r1 >> (8 * cc)) & 0xFF) s |= 1 << (4 + cc);
        }
    } else {
        const int* xi = (const int*)xb;
        int4 a0 = *(const int4*)(xi + base);
        int4 a1 = *(const int4*)(xi + base + 256);
        if (a0.x) s |= 1;   if (a0.y) s |= 2;
        if (a0.z) s |= 4;   if (a0.w) s |= 8;
        if (a1.x) s |= 16;  if (a1.y) s |= 32;
        if (a1.z) s |= 64;  if (a1.w) s |= 128;
    }
    mc[i] = (float)s * (1.0f / 255.0f);
}

// ---------------- zero-patch mask + nonzero-token compaction ----------------
__global__ void zmask_kernel(const float* __restrict__ mc) {
    int idx = blockIdx.x * 256 + threadIdx.x;
    int tok = idx >> 3, c = idx & 7;
    int p = tok & 4095, b = tok >> 12;
    int zk = p & 15, zj = (p >> 4) & 15, zi = p >> 8;
    bool any = false;
    const float* basep = mc + (((b * 8 + c) * 64 + 4 * zi) * 64 + 4 * zj) * 64 + 4 * zk;
#pragma unroll
    for (int dz = 0; dz < 4; dz++)
#pragma unroll
        for (int dy = 0; dy < 4; dy++) {
            float4 v = *(const float4*)(basep + (dz * 64 + dy) * 64);
            any |= (v.x != 0.f) | (v.y != 0.f) | (v.z != 0.f) | (v.w != 0.f);
        }
    unsigned m = __ballot_sync(0xFFFFFFFFu, any);
    if (c == 0) {
        int sh = threadIdx.x & 24;
        bool nz = ((m >> sh) & 0xFF) != 0;
        g_zmask[tok] = nz ? 0 : 1;
        if (nz) { int pp = atomicAdd(&g_nnz, 1); g_toklist[pp] = tok; }
    }
}

// ---------------- SIMT 3x3x3 conv, stride 1, XW=8, OCW=8 (CL: channel-last out) ----------------
template<int CIN, int OCW, int CL>
__launch_bounds__(256)
__global__ void conv_k3_x8(const float* __restrict__ in, const float* __restrict__ wt,
                           const float* __restrict__ bias, float* __restrict__ out,
                           int Din, int COUT, int act)
{
    extern __shared__ float sw[];
    const int oc0 = blockIdx.y * OCW;
    const int b   = blockIdx.z;
    for (int idx = threadIdx.x; idx < CIN * 27 * OCW; idx += 256) {
        int r = idx / OCW, o = idx % OCW;
        sw[idx] = wt[(oc0 + o) * (CIN * 27) + r];
    }
    __syncthreads();
    const int spatial = Din * Din * Din;
    int gpos = (blockIdx.x * 256 + threadIdx.x) * 8;
    if (gpos >= spatial) return;
    int x0 = gpos % Din; int t1 = gpos / Din; int y = t1 % Din; int z = t1 / Din;

    float acc[OCW][8];
#pragma unroll
    for (int o = 0; o < OCW; o++) {
        float bv = bias[oc0 + o];
#pragma unroll
        for (int xx = 0; xx < 8; xx++) acc[o][xx] = bv;
    }
    const float* inb = in + b * CIN * Din * Din * Din;
#pragma unroll 1
    for (int ic = 0; ic < CIN; ic++) {
        const float* inc = inb + ic * Din * Din * Din;
#pragma unroll 1
        for (int tz = 0; tz < 3; tz++) {
            int iz = z + tz - 1; if ((unsigned)iz >= (unsigned)Din) continue;
#pragma unroll
            for (int ty = 0; ty < 3; ty++) {
                int iy = y + ty - 1; if ((unsigned)iy >= (unsigned)Din) continue;
                const float* row = inc + (iz * Din + iy) * Din;
                float4 v0 = *(const float4*)(row + x0);
                float4 v1 = *(const float4*)(row + x0 + 4);
                float r[10];
                r[0] = (x0 > 0) ? row[x0 - 1] : 0.f;
                r[1] = v0.x; r[2] = v0.y; r[3] = v0.z; r[4] = v0.w;
                r[5] = v1.x; r[6] = v1.y; r[7] = v1.z; r[8] = v1.w;
                r[9] = (x0 + 8 < Din) ? row[x0 + 8] : 0.f;
                const float* swp = sw + (ic * 27 + tz * 9 + ty * 3) * OCW;
#pragma unroll
                for (int tx = 0; tx < 3; tx++) {
                    float w[OCW];
#pragma unroll
                    for (int o4 = 0; o4 < OCW / 4; o4++)
                        *(float4*)(w + 4 * o4) = *(const float4*)(swp + tx * OCW + 4 * o4);
#pragma unroll
                    for (int o = 0; o < OCW; o++)
#pragma unroll
                        for (int xx = 0; xx < 8; xx++) acc[o][xx] += w[o] * r[xx + tx];
                }
            }
        }
    }
    if (CL) {
        int pos = (z * Din + y) * Din + x0;
#pragma unroll
        for (int xx = 0; xx < 8; xx++) {
            float s[OCW];
#pragma unroll
            for (int o = 0; o < OCW; o++) {
                s[o] = acc[o][xx];
                if (act) s[o] = silu(s[o]);
            }
            float* op = out + ((size_t)b * spatial + pos + xx) * COUT + oc0;
#pragma unroll
            for (int o4 = 0; o4 < OCW / 4; o4++)
                *(float4*)(op + 4 * o4) = *(float4*)(s + 4 * o4);
        }
    } else {
        int obase0 = (z * Din + y) * Din + x0;
#pragma unroll
        for (int o = 0; o < OCW; o++) {
            float s[8];
#pragma unroll
            for (int xx = 0; xx < 8; xx++) {
                s[xx] = acc[o][xx];
                if (act) s[xx] = silu(s[xx]);
            }
            float* op = out + (size_t)(b * COUT + oc0 + o) * spatial + obase0;
            *(float4*)op = make_float4(s[0], s[1], s[2], s[3]);
            *(float4*)(op + 4) = make_float4(s[4], s[5], s[6], s[7]);
        }
    }
}

// ---------------- 1x1x1 convs ----------------
__global__ void quant_conv_cl_kernel(const float* __restrict__ h_cl, const float* __restrict__ w,
                                     const float* __restrict__ bias, float* __restrict__ seq)
{
    int i = blockIdx.x * 256 + threadIdx.x;
    if (i >= NTOK * EDIM) return;
    int e = i & 15; int p = (i >> 4) & 4095; int b = i >> 16;
    float acc = bias[e];
    const float4* hp = (const float4*)(h_cl + ((size_t)(b * 4096 + p)) * 128);
    const float4* wp = (const float4*)(w + e * 128);
#pragma unroll 8
    for (int ic4 = 0; ic4 < 32; ic4++) {
        float4 hv = hp[ic4], wv = wp[ic4];
        acc += wv.x * hv.x + wv.y * hv.y + wv.z * hv.z + wv.w * hv.w;
    }
    seq[i] = acc;
}

__global__ void post_quant_cl_kernel(const float* __restrict__ q, const float* __restrict__ w,
                                     const float* __restrict__ bias, float* __restrict__ out_cl)
{
    int i = blockIdx.x * 256 + threadIdx.x;
    if (i >= BATCH * 4096 * 128) return;
    int oc = i & 127; int p = (i >> 7) & 4095; int b = i >> 19;
    float acc = bias[oc];
    const float* qp = q + (b * EDIM) * 4096 + p;
    const float* wp = w + oc * EDIM;
#pragma unroll
    for (int e = 0; e < EDIM; e++) acc += wp[e] * qp[e * 4096];
    out_cl[i] = __uint_as_float(f2tf(acc));
}

// ---------------- VQ ----------------
__global__ void cnorm_kernel(const float* __restrict__ cb) {
    int k = blockIdx.x * 128 + threadIdx.x;
    if (k < KCODE) {
        float s = 0.f;
#pragma unroll
        for (int e = 0; e < EDIM; e++) { float c = cb[k * EDIM + e]; s += c * c; }
        g_cnorm[k] = s;
    }
}

__global__ void vq_kernel(const float* __restrict__ seq, const float* __restrict__ cb)
{
    __shared__ float stok[32 * 16];
    __shared__ float sc[128 * 16];
    __shared__ float sn[128];
    __shared__ float rd[128];
    __shared__ int   ri[128];
    const int nnz = g_nnz;
    const int tok0 = blockIdx.x * 32;
    if (tok0 >= nnz) return;
    const int tid = threadIdx.x;
    for (int i = tid; i < 512; i += 128) {
        int ti = tok0 + (i >> 4);
        int tok = g_toklist[ti < nnz ? ti : (nnz - 1)];
        stok[i] = seq[tok * 16 + (i & 15)];
    }
    __syncthreads();
    const int t = tid & 31, g = tid >> 5;
    float s[16];
#pragma unroll
    for (int e = 0; e < 16; e++) s[e] = stok[t * 16 + e];
    float best = 3.4e38f; int bidx = 0;
    for (int tile = 0; tile < KCODE / 128; tile++) {
        __syncthreads();
        for (int i = tid; i < 512; i += 128)
            *(float4*)&sc[i * 4] = *(const float4*)&cb[tile * 2048 + i * 4];
        if (tid < 128) sn[tid] = g_cnorm[tile * 128 + tid];
        __syncthreads();
#pragma unroll 4
        for (int kk = g; kk < 128; kk += 4) {
            const float4* c4 = (const float4*)&sc[kk * 16];
            float4 c0 = c4[0], c1 = c4[1], c2 = c4[2], c3 = c4[3];
            float dot = c0.x * s[0] + c0.y * s[1] + c0.z * s[2] + c0.w * s[3]
                      + c1.x * s[4] + c1.y * s[5] + c1.z * s[6] + c1.w * s[7]
                      + c2.x * s[8] + c2.y * s[9] + c2.z * s[10] + c2.w * s[11]
                      + c3.x * s[12] + c3.y * s[13] + c3.z * s[14] + c3.w * s[15];
            float d = sn[kk] - 2.f * dot;
            if (d < best) { best = d; bidx = tile * 128 + kk; }
        }
    }
    rd[tid] = best; ri[tid] = bidx;
    __syncthreads();
    if (g == 0) {
        for (int gg = 1; gg < 4; gg++) {
            float d = rd[gg * 32 + t]; int k = ri[gg * 32 + t];
            if (d < best || (d == best && k < bidx)) { best = d; bidx = k; }
        }
        int ti = tok0 + t;
        if (ti < nnz) g_idx[g_toklist[ti]] = bidx;
    }
}

// ---------------- commit loss ----------------
__global__ void commit_kernel(const float* __restrict__ seq, const float* __restrict__ cb)
{
    __shared__ float sh[128];
    int t = blockIdx.x * 128 + threadIdx.x;
    float v = 0.f;
    if (!g_zmask[t]) {
        const float* s = seq + t * 16;
        const float* c = cb + g_idx[t] * 16;
        float a = 0.f;
#pragma unroll
        for (int e = 0; e < 16; e++) { float d = c[e] - s[e]; a += d * d; }
        v = a * (1.f / 16.f);
    }
    sh[threadIdx.x] = v; __syncthreads();
    for (int st = 64; st; st >>= 1) {
        if (threadIdx.x < st) sh[threadIdx.x] += sh[threadIdx.x + st];
        __syncthreads();
    }
    if (threadIdx.x == 0) g_part[blockIdx.x] = sh[0];
}

__global__ void commit_final(float* __restrict__ out) {
    if (threadIdx.x == 0) {
        float s = 0.f;
        for (int i = 0; i < 128; i++) s += g_part[i];
        out[0] = 0.25f * s / 16384.f;
    }
}

__global__ void fullidx_kernel(float* __restrict__ out) {
    int i = blockIdx.x * 256 + threadIdx.x;
    if (i < NTOK) out[i] = g_zmask[i] ? 0.f : (float)(g_idx[i] + 1);
}

__global__ void qbuild_kernel(const float* __restrict__ cb, const float* __restrict__ rep,
                              const float* __restrict__ pos)
{
    int i = blockIdx.x * 256 + threadIdx.x;
    if (i >= BATCH * EDIM * 4096) return;
    int p = i & 4095; int e = (i >> 12) & 15; int b = i >> 16;
    int tok = (b << 12) + p;
    float v = g_zmask[tok] ? rep[e] : cb[g_idx[tok] * 16 + e];
    g_q[i] = v + pos[e * 4096 + p];
}

// ---------------- launch ----------------
extern "C" void kernel_launch(void* const* d_in, const int* in_sizes, int n_in,
                              void* d_out_, int out_size)
{
    const unsigned char* x = (const unsigned char*)d_in[0];
    const float* enc_in_w  = (const float*)d_in[1];
    const float* enc_in_b  = (const float*)d_in[2];
    const float* enc_d1_w  = (const float*)d_in[3];
    const float* enc_d1_b  = (const float*)d_in[4];
    const float* enc_d2_w  = (const float*)d_in[5];
    const float* enc_d2_b  = (const float*)d_in[6];
    const float* enc_out_w = (const float*)d_in[7];
    const float* enc_out_b = (const float*)d_in[8];
    const float* quant_w   = (const float*)d_in[9];
    const float* quant_b   = (const float*)d_in[10];
    const float* codebook  = (const float*)d_in[11];
    const float* rep_tok   = (const float*)d_in[12];
    const float* pos_emb   = (const float*)d_in[13];
    const float* pq_w      = (const float*)d_in[14];
    const float* pq_b      = (const float*)d_in[15];
    const float* dec_in_w  = (const float*)d_in[16];
    const float* dec_in_b  = (const float*)d_in[17];
    const float* dec_u1_w  = (const float*)d_in[18];
    const float* dec_u1_b  = (const float*)d_in[19];
    const float* dec_u2_w  = (const float*)d_in[20];
    const float* dec_u2_b  = (const float*)d_in[21];
    const float* dec_out_w = (const float*)d_in[22];
    const float* dec_out_b = (const float*)d_in[23];
    float* out = (float*)d_out_;

    float *pA, *pB, *pC, *pD, *pSeq, *pQ, *pCL, *pW, *pW1, *pW2;
    float *pH0, *pL0, *pH1, *pL1, *pH2, *pL2;
    cudaGetSymbolAddress((void**)&pA, g_bufA);
    cudaGetSymbolAddress((void**)&pB, g_bufB);
    cudaGetSymbolAddress((void**)&pC, g_bufC);
    cudaGetSymbolAddress((void**)&pD, g_bufD);
    cudaGetSymbolAddress((void**)&pSeq, g_seq);
    cudaGetSymbolAddress((void**)&pQ, g_q);
    cudaGetSymbolAddress((void**)&pCL, g_cl);
    cudaGetSymbolAddress((void**)&pW, g_wt);
    cudaGetSymbolAddress((void**)&pW1, g_wt1);
    cudaGetSymbolAddress((void**)&pW2, g_wt2);
    cudaGetSymbolAddress((void**)&pH0, g_wh0);
    cudaGetSymbolAddress((void**)&pL0, g_wl0);
    cudaGetSymbolAddress((void**)&pH1, g_wh1);
    cudaGetSymbolAddress((void**)&pL1, g_wl1);
    cudaGetSymbolAddress((void**)&pH2, g_wh2);
    cudaGetSymbolAddress((void**)&pL2, g_wl2);

    cudaFuncSetAttribute(conv_mma_dec, cudaFuncAttributeMaxDynamicSharedMemorySize, 2 * STAGE_F * 4);
    cudaFuncSetAttribute((conv_mma3<32, 64, 32, 5, 2, 1>),   cudaFuncAttributeMaxDynamicSharedMemorySize, 110592);
    cudaFuncSetAttribute((conv_mma3<64, 128, 16, 4, 2, 1>),  cudaFuncAttributeMaxDynamicSharedMemorySize, 143360);
    cudaFuncSetAttribute((conv_mma3<128, 128, 16, 4, 1, 0>), cudaFuncAttributeMaxDynamicSharedMemorySize, 143360);
    cudaFuncSetAttribute((tconv_mma<128, 64, 16, 4, 1>), cudaFuncAttributeMaxDynamicSharedMemorySize, 55296);
    cudaFuncSetAttribute((tconv_mma<64, 32, 32, 5, 0>),  cudaFuncAttributeMaxDynamicSharedMemorySize, 47104);

    float* mc = out + OFF_MC;
    dim3 blk(256);

    initflag_kernel<<<1, 1>>>();
    scan_kernel<<<4096, 256>>>((const unsigned int*)x);
    pack_kernel<<<N_MC / 256, 256>>>(x, mc);

    // weight transforms
    wtrans_hilo<<<216, 256>>>(enc_d1_w, pH1, pL1, 32, 64);
    wtrans_hilo<<<864, 256>>>(enc_d2_w, pH2, pL2, 64, 128);
    wtrans_hilo<<<1728, 256>>>(enc_out_w, pH0, pL0, 128, 128);
    wtrans2<<<1728, 256>>>(dec_in_w, pW, 128, 128);
    wtrans2<<<864, 256>>>(dec_u1_w, pW1, 128, 64);
    wtrans2<<<216, 256>>>(dec_u2_w, pW2, 64, 32);

    // encoder: enc_in SIMT (channel-last out), rest 3xtf32 mma (fp32-accurate)
    conv_k3_x8<8, 8, 1><<<dim3(128, 4, 4), blk, 8 * 27 * 8 * 4>>>(mc, enc_in_w, enc_in_b, pA, 64, 32, 1);
    zmask_kernel<<<512, 256>>>(mc);
    conv_mma3<32, 64, 32, 5, 2, 1><<<dim3(256, 1, 4), 256, 110592>>>(pA, pH1, pL1, enc_d1_b, pB);
    conv_mma3<64, 128, 16, 4, 2, 1><<<dim3(32, 1, 4), 256, 143360>>>(pB, pH2, pL2, enc_d2_b, pCL);
    conv_mma3<128, 128, 16, 4, 1, 0><<<dim3(32, 1, 4), 256, 143360>>>(pCL, pH0, pL0, enc_out_b, pD);

    // quantization path
    cnorm_kernel<<<KCODE / 128, 128>>>(codebook);
    quant_conv_cl_kernel<<<(NTOK * EDIM) / 256, 256>>>(pD, quant_w, quant_b, pSeq);
    vq_kernel<<<NTOK / 32, 128>>>(pSeq, codebook);
    commit_kernel<<<NTOK / 128, 128>>>(pSeq, codebook);
    commit_final<<<1, 1>>>(out + OFF_COMMIT);
    fullidx_kernel<<<NTOK / 256, 256>>>(out + OFF_IDX);
    qbuild_kernel<<<(BATCH * EDIM * 4096) / 256, 256>>>(codebook, rep_tok, pos_emb);
    post_quant_cl_kernel<<<(BATCH * 4096 * 128) / 256, 256>>>(pQ, pq_w, pq_b, pCL);

    // decoder: dec_in + both tconvs on tensor cores (tf32), dec_out SIMT XW=8
    conv_mma_dec<<<dim3(32, 1, 4), 256, 2 * STAGE_F * 4>>>(pCL, dec_in_b, pD);
    tconv_mma<128, 64, 16, 4, 1><<<dim3(32, 8, 4), 256, 55296>>>(pD, pW1, dec_u1_b, pB);
    tconv_mma<64, 32, 32, 5, 0><<<dim3(256, 8, 4), 256, 47104>>>(pB, pW2, dec_u2_b, pA);
    conv_k3_x8<32, 8, 0><<<dim3(128, 1, 4), blk, 32 * 27 * 8 * 4>>>(pA, dec_out_w, dec_out_b, out, 64, 8, 0);
}

// round 13
// speedup vs baseline: 1.3407x; 1.0412x over previous
#include <cuda_runtime.h>
#include <math.h>
#include <cstdint>

// ---------------- problem constants ----------------
#define BATCH 4
#define D64   64
#define D32   32
#define D16   16
#define NTOK  (BATCH*4096)
#define EDIM  16
#define KCODE 8192
#define N_MC  (BATCH*8*D64*D64*D64)
#define OFF_MC     8388608
#define OFF_COMMIT 16777216
#define OFF_IDX    16777217

// ---------------- device scratch ----------------
__device__ float g_bufA[BATCH*32*D64*D64*D64];
__device__ float g_bufB[BATCH*64*D32*D32*D32];
__device__ float g_bufC[BATCH*128*D16*D16*D16];
__device__ float g_bufD[BATCH*128*D16*D16*D16];
__device__ float g_seq[NTOK*EDIM];
__device__ float g_q[BATCH*EDIM*4096];
__device__ float g_cl[BATCH*4096*128];
__device__ float g_wt [27*128*128];
__device__ float g_wt1[27*128*64];
__device__ float g_wt2[27*64*32];
__device__ float g_wh0[27*128*128];
__device__ float g_wl0[27*128*128];
__device__ float g_wh1[27*32*64];
__device__ float g_wl1[27*32*64];
__device__ float g_wh2[27*64*128];
__device__ float g_wl2[27*64*128];
__device__ float g_cnorm[KCODE];
__device__ float g_part[128];
__device__ int   g_idx[NTOK];
__device__ unsigned char g_zmask[NTOK];
__device__ int   g_flags;
__device__ int   g_nnz;
__device__ int   g_toklist[NTOK];

__device__ __forceinline__ float silu(float v) { return v * __frcp_rn(1.f + __expf(-v)); }

__device__ __forceinline__ uint32_t f2tf(float f) {
    uint32_t r; asm("cvt.rna.tf32.f32 %0, %1;" : "=r"(r) : "f"(f)); return r;
}
__device__ __forceinline__ void mma_tf32(float* d, const uint32_t* a, const uint32_t* b) {
    asm volatile("mma.sync.aligned.m16n8k8.row.col.f32.tf32.tf32.f32 "
                 "{%0,%1,%2,%3}, {%4,%5,%6,%7}, {%8,%9}, {%0,%1,%2,%3};"
                 : "+f"(d[0]), "+f"(d[1]), "+f"(d[2]), "+f"(d[3])
                 : "r"(a[0]), "r"(a[1]), "r"(a[2]), "r"(a[3]), "r"(b[0]), "r"(b[1]));
}

// -------- weight transform: w[OC][IC][27] -> dst[tap][ic][oc], tf32-rounded --------
__global__ void wtrans2(const float* __restrict__ w, float* __restrict__ dst, int IC, int OC) {
    int i = blockIdx.x * 256 + threadIdx.x;
    int total = 27 * IC * OC;
    if (i >= total) return;
    int tap = i / (IC * OC); int rem = i % (IC * OC); int ic = rem / OC; int oc = rem % OC;
    dst[i] = __uint_as_float(f2tf(w[(oc * IC + ic) * 27 + tap]));
}

// -------- hi/lo split weight transform (3xtf32) --------
__global__ void wtrans_hilo(const float* __restrict__ w, float* __restrict__ dh,
                            float* __restrict__ dl, int IC, int OC) {
    int i = blockIdx.x * 256 + threadIdx.x;
    int total = 27 * IC * OC;
    if (i >= total) return;
    int tap = i / (IC * OC); int rem = i % (IC * OC); int ic = rem / OC; int oc = rem % OC;
    float v = w[(oc * IC + ic) * 27 + tap];
    float hi = __uint_as_float(f2tf(v));
    dh[i] = hi;
    dl[i] = __uint_as_float(f2tf(v - hi));
}

#define SA 36

// ---------- 3xtf32 error-compensated implicit GEMM conv (fp32-accurate) ----------
template<int CIN, int COUT, int DOUT, int LOGD, int STRIDE, int ACT>
__launch_bounds__(256)
__global__ void conv_mma3(const float* __restrict__ in_cl, const float* __restrict__ wh,
                          const float* __restrict__ wl, const float* __restrict__ bias,
                          float* __restrict__ out_cl)
{
    extern __shared__ float dsm[];
    constexpr int NW_N = COUT / 32;
    constexpr int NW_M = 8 / NW_N;
    constexpr int MT = 128 / (NW_M * 16);
    constexpr int SBs = COUT + 8;
    constexpr int STG = 2 * 128 * SA + 2 * 32 * SBs;
    constexpr int NIC = CIN / 32;
    constexpr int DIN = DOUT * STRIDE;
    constexpr int BF4 = COUT / 32;
    constexpr int NCH = 27 * NIC;

    const int tid = threadIdx.x;
    const int lane = tid & 31, wid = tid >> 5;
    const int wm = wid / NW_N, wn = wid % NW_N;
    const int bb = blockIdx.z;
    const int pos0 = blockIdx.x * 128;
    const float* inb = in_cl + (size_t)bb * (DIN * DIN * DIN) * CIN;

    float acc[MT][4][4];
#pragma unroll
    for (int mt = 0; mt < MT; mt++)
#pragma unroll
        for (int nt = 0; nt < 4; nt++)
#pragma unroll
            for (int k = 0; k < 4; k++) acc[mt][nt][k] = 0.f;

    const int ar = tid >> 1, aseg = tid & 1;
    const int apos = pos0 + ar;
    const int gx = apos & (DOUT - 1), gy = (apos >> LOGD) & (DOUT - 1), gz = apos >> (2 * LOGD);
    const int bk = tid >> 3, bseg = tid & 7;

    float4 ra[4], rbh[BF4], rbl[BF4];
    auto ldg = [&](int c) {
        int tap = c / NIC, ic0 = (c % NIC) * 32;
        int tz = tap / 9, ty = (tap / 3) % 3, tx = tap % 3;
        int ix = STRIDE * gx + tx - 1, iy = STRIDE * gy + ty - 1, iz = STRIDE * gz + tz - 1;
        bool valid = ((unsigned)ix < (unsigned)DIN) & ((unsigned)iy < (unsigned)DIN)
                   & ((unsigned)iz < (unsigned)DIN);
        if (valid) {
            const float4* sa = (const float4*)(inb + (size_t)((iz * DIN + iy) * DIN + ix) * CIN
                                               + ic0 + aseg * 16);
            ra[0] = sa[0]; ra[1] = sa[1]; ra[2] = sa[2]; ra[3] = sa[3];
        } else {
            ra[0] = ra[1] = ra[2] = ra[3] = make_float4(0.f, 0.f, 0.f, 0.f);
        }
        size_t woff = (size_t)(tap * CIN + ic0 + bk) * COUT + bseg * (COUT / 8);
        const float4* sbh = (const float4*)(wh + woff);
        const float4* sbl = (const float4*)(wl + woff);
#pragma unroll
        for (int j = 0; j < BF4; j++) { rbh[j] = sbh[j]; rbl[j] = sbl[j]; }
    };
    auto sts = [&](int s) {
        float* Ah = dsm + s * STG;
        float* Al = Ah + 128 * SA;
        float* Bh = Al + 128 * SA;
        float* Bl = Bh + 32 * SBs;
#pragma unroll
        for (int j = 0; j < 4; j++) {
            float4 v = ra[j];
            uint4 h, l;
            h.x = f2tf(v.x); l.x = f2tf(v.x - __uint_as_float(h.x));
            h.y = f2tf(v.y); l.y = f2tf(v.y - __uint_as_float(h.y));
            h.z = f2tf(v.z); l.z = f2tf(v.z - __uint_as_float(h.z));
            h.w = f2tf(v.w); l.w = f2tf(v.w - __uint_as_float(h.w));
            *(uint4*)(Ah + ar * SA + aseg * 16 + 4 * j) = h;
            *(uint4*)(Al + ar * SA + aseg * 16 + 4 * j) = l;
        }
#pragma unroll
        for (int j = 0; j < BF4; j++) {
            *(float4*)(Bh + bk * SBs + bseg * (COUT / 8) + 4 * j) = rbh[j];
            *(float4*)(Bl + bk * SBs + bseg * (COUT / 8) + 4 * j) = rbl[j];
        }
    };
    const int rq = lane >> 2, cq = lane & 3;
    auto dom = [&](const uint32_t* Au, const uint32_t* Bu) {
#pragma unroll
        for (int q = 0; q < 4; q++) {
            const int kk = q * 8 + cq;
            uint32_t af[MT][4], bf[4][2];
#pragma unroll
            for (int mt = 0; mt < MT; mt++) {
                int row = wm * (MT * 16) + mt * 16 + rq;
                af[mt][0] = Au[row * SA + kk];
                af[mt][1] = Au[(row + 8) * SA + kk];
                af[mt][2] = Au[row * SA + kk + 4];
                af[mt][3] = Au[(row + 8) * SA + kk + 4];
            }
#pragma unroll
            for (int nt = 0; nt < 4; nt++) {
                int col = wn * 32 + nt * 8 + rq;
                bf[nt][0] = Bu[kk * SBs + col];
                bf[nt][1] = Bu[(kk + 4) * SBs + col];
            }
#pragma unroll
            for (int mt = 0; mt < MT; mt++)
#pragma unroll
                for (int nt = 0; nt < 4; nt++)
                    mma_tf32(acc[mt][nt], af[mt], bf[nt]);
        }
    };
    auto domma3 = [&](int s) {
        const uint32_t* Ah = (const uint32_t*)(dsm + s * STG);
        const uint32_t* Al = Ah + 128 * SA;
        const uint32_t* Bh = Al + 128 * SA;
        const uint32_t* Bl = Bh + 32 * SBs;
        dom(Ah, Bh);
        dom(Ah, Bl);
        dom(Al, Bh);
    };

    ldg(0); sts(0); __syncthreads();
#pragma unroll 1
    for (int c = 0; c < NCH; c++) {
        if (c + 1 < NCH) ldg(c + 1);
        domma3(c & 1);
        if (c + 1 < NCH) sts((c + 1) & 1);
        __syncthreads();
    }

    constexpr int SE = COUT + 1;
    float* E = dsm;
#pragma unroll
    for (int mt = 0; mt < MT; mt++)
#pragma unroll
        for (int nt = 0; nt < 4; nt++) {
            int row = wm * (MT * 16) + mt * 16 + rq;
            int col = wn * 32 + nt * 8 + 2 * cq;
            E[row * SE + col]           = acc[mt][nt][0];
            E[row * SE + col + 1]       = acc[mt][nt][1];
            E[(row + 8) * SE + col]     = acc[mt][nt][2];
            E[(row + 8) * SE + col + 1] = acc[mt][nt][3];
        }
    __syncthreads();
    float* ob = out_cl + ((size_t)bb * (DOUT * DOUT * DOUT) + pos0 + ar) * COUT;
#pragma unroll
    for (int j4 = 0; j4 < COUT / 8; j4++) {
        float4 v; float* pv = (float*)&v;
#pragma unroll
        for (int t = 0; t < 4; t++) {
            int ch = aseg * (COUT / 2) + j4 * 4 + t;
            float x = E[ar * SE + ch] + bias[ch];
            pv[t] = ACT ? silu(x) : x;
        }
        *(float4*)(ob + aseg * (COUT / 2) + j4 * 4) = v;
    }
}

// ---------- mma.sync tf32 implicit-GEMM 3x3x3 conv (128->128, 16^3), dec_in ----------
#define SB 136
#define STAGE_F (128*SA + 32*SB)

__launch_bounds__(256)
__global__ void conv_mma_dec(const float* __restrict__ in_cl, const float* __restrict__ bias,
                             float* __restrict__ out_cl)
{
    extern __shared__ float dsm[];
    const int tid = threadIdx.x;
    const int lane = tid & 31, wid = tid >> 5;
    const int wm = wid >> 2, wn = wid & 3;
    const int bb = blockIdx.z;
    const int pos0 = blockIdx.x * 128;
    const float* inb = in_cl + (size_t)bb * 4096 * 128;

    float acc[4][4][4];
#pragma unroll
    for (int mt = 0; mt < 4; mt++)
#pragma unroll
        for (int nt = 0; nt < 4; nt++)
#pragma unroll
            for (int k = 0; k < 4; k++) acc[mt][nt][k] = 0.f;

    const int ar = tid >> 1, aseg = tid & 1;
    const int apos = pos0 + ar;
    const int ax = apos & 15, ay = (apos >> 4) & 15, az = apos >> 8;
    const int bk = tid >> 3, bseg = tid & 7;

    float4 ra[4], rb[4];
    auto ldg = [&](int c) {
        int tap = c >> 2, ic0 = (c & 3) * 32;
        int tz = tap / 9, ty = (tap / 3) % 3, tx = tap % 3;
        int xx = ax + tx - 1, yy = ay + ty - 1, zz = az + tz - 1;
        bool valid = ((unsigned)xx < 16u) & ((unsigned)yy < 16u) & ((unsigned)zz < 16u);
        if (valid) {
            const float4* sa = (const float4*)(inb + (size_t)((zz * 16 + yy) * 16 + xx) * 128
                                               + ic0 + aseg * 16);
            ra[0] = sa[0]; ra[1] = sa[1]; ra[2] = sa[2]; ra[3] = sa[3];
        } else {
            ra[0] = ra[1] = ra[2] = ra[3] = make_float4(0.f, 0.f, 0.f, 0.f);
        }
        const float4* sb = (const float4*)(g_wt + (size_t)(tap * 128 + ic0 + bk) * 128
                                           + bseg * 16);
        rb[0] = sb[0]; rb[1] = sb[1]; rb[2] = sb[2]; rb[3] = sb[3];
    };
    auto sts = [&](int s) {
        float* Au = dsm + s * STAGE_F;
        float* Bu = Au + 128 * SA;
#pragma unroll
        for (int j = 0; j < 4; j++) {
            *(float4*)(Au + ar * SA + aseg * 16 + 4 * j) = ra[j];
            *(float4*)(Bu + bk * SB + bseg * 16 + 4 * j) = rb[j];
        }
    };
    auto domma = [&](int s) {
        const uint32_t* Au = (const uint32_t*)(dsm + s * STAGE_F);
        const uint32_t* Bu = Au + 128 * SA;
        const int rq = lane >> 2, cq = lane & 3;
#pragma unroll
        for (int q = 0; q < 4; q++) {
            const int kk = q * 8 + cq;
            uint32_t af[4][4], bf[4][2];
#pragma unroll
            for (int mt = 0; mt < 4; mt++) {
                int row = wm * 64 + mt * 16 + rq;
                af[mt][0] = Au[row * SA + kk];
                af[mt][1] = Au[(row + 8) * SA + kk];
                af[mt][2] = Au[row * SA + kk + 4];
                af[mt][3] = Au[(row + 8) * SA + kk + 4];
            }
#pragma unroll
            for (int nt = 0; nt < 4; nt++) {
                int col = wn * 32 + nt * 8 + rq;
                bf[nt][0] = Bu[kk * SB + col];
                bf[nt][1] = Bu[(kk + 4) * SB + col];
            }
#pragma unroll
            for (int mt = 0; mt < 4; mt++)
#pragma unroll
                for (int nt = 0; nt < 4; nt++)
                    mma_tf32(acc[mt][nt], af[mt], bf[nt]);
        }
    };

    ldg(0); sts(0); __syncthreads();
#pragma unroll 1
    for (int c = 0; c < 108; c++) {
        if (c < 107) ldg(c + 1);
        domma(c & 1);
        if (c < 107) sts((c + 1) & 1);
        __syncthreads();
    }

    float* E = dsm;
    const int rq = lane >> 2, cq = lane & 3;
#pragma unroll
    for (int mt = 0; mt < 4; mt++)
#pragma unroll
        for (int nt = 0; nt < 4; nt++) {
            int row = wm * 64 + mt * 16 + rq;
            int col = wn * 32 + nt * 8 + 2 * cq;
            E[row * 129 + col]           = acc[mt][nt][0];
            E[row * 129 + col + 1]       = acc[mt][nt][1];
            E[(row + 8) * 129 + col]     = acc[mt][nt][2];
            E[(row + 8) * 129 + col + 1] = acc[mt][nt][3];
        }
    __syncthreads();
    float* ob = out_cl + ((size_t)bb * 4096 + pos0 + ar) * 128;
#pragma unroll
    for (int j4 = 0; j4 < 16; j4++) {
        float4 v; float* pv = (float*)&v;
#pragma unroll
        for (int t = 0; t < 4; t++) {
            int ch = aseg * 64 + j4 * 4 + t;
            float x = E[ar * 129 + ch] + bias[ch];
            pv[t] = __uint_as_float(f2tf(silu(x)));
        }
        *(float4*)(ob + aseg * 64 + j4 * 4) = v;
    }
}

// ---------- mma.sync tf32 transposed conv via octant decomposition ----------
template<int CIN, int COUT, int DIN, int LOGD, int CLOUT>
__launch_bounds__(256)
__global__ void tconv_mma(const float* __restrict__ in_cl, const float* __restrict__ wtr,
                          const float* __restrict__ bias, float* __restrict__ out)
{
    extern __shared__ float dsm[];
    constexpr int NW_N = COUT / 32;
    constexpr int NW_M = 8 / NW_N;
    constexpr int MT = 128 / (NW_M * 16);
    constexpr int SAs = 36;
    constexpr int SBs = COUT + 8;
    constexpr int STG = 128 * SAs + 32 * SBs;
    constexpr int NIC = CIN / 32;
    constexpr int DOUT = 2 * DIN;
    constexpr int BF4 = COUT / 32;

    const int tid = threadIdx.x;
    const int lane = tid & 31, wid = tid >> 5;
    const int wm = wid / NW_N, wn = wid % NW_N;
    const int bb = blockIdx.z;
    const int oct = blockIdx.y;
    const int px = oct & 1, py = (oct >> 1) & 1, pz = (oct >> 2) & 1;
    const int ntx = 2 - px, nty = 2 - py;
    const int nchunks = ntx * nty * (2 - pz) * NIC;
    const int pos0 = blockIdx.x * 128;
    const float* inb = in_cl + (size_t)bb * (DIN * DIN * DIN) * CIN;

    float acc[MT][4][4];
#pragma unroll
    for (int mt = 0; mt < MT; mt++)
#pragma unroll
        for (int nt = 0; nt < 4; nt++)
#pragma unroll
            for (int k = 0; k < 4; k++) acc[mt][nt][k] = 0.f;

    const int ar = tid >> 1, aseg = tid & 1;
    const int pa = pos0 + ar;
    const int gx = pa & (DIN - 1), gy = (pa >> LOGD) & (DIN - 1), gz = pa >> (2 * LOGD);
    const int bk = tid >> 3, bseg = tid & 7;

    float4 ra[4], rb[BF4];

    auto ldg = [&](int c) {
        int tap = c / NIC, ic0 = (c % NIC) * 32;
        int txi = tap % ntx; int r2 = tap / ntx; int tyi = r2 % nty; int tzi = r2 / nty;
        int tx = px ? 1 : txi * 2, ty = py ? 1 : tyi * 2, tz = pz ? 1 : tzi * 2;
        int ix = gx + (px ? 0 : txi - 1);
        int iy = gy + (py ? 0 : tyi - 1);
        int iz = gz + (pz ? 0 : tzi - 1);
        bool valid = (ix >= 0) && (iy >= 0) && (iz >= 0);
        if (valid) {
            const float4* sa = (const float4*)(inb + (size_t)((iz * DIN + iy) * DIN + ix) * CIN
                                               + ic0 + aseg * 16);
            ra[0] = sa[0]; ra[1] = sa[1]; ra[2] = sa[2]; ra[3] = sa[3];
        } else {
            ra[0] = ra[1] = ra[2] = ra[3] = make_float4(0.f, 0.f, 0.f, 0.f);
        }
        int tap27 = tz * 9 + ty * 3 + tx;
        const float4* sb = (const float4*)(wtr + ((size_t)(tap27 * CIN) + ic0 + bk) * COUT
                                           + bseg * (COUT / 8));
#pragma unroll
        for (int j = 0; j < BF4; j++) rb[j] = sb[j];
    };
    auto sts = [&](int s) {
        float* Au = dsm + s * STG;
        float* Bu = Au + 128 * SAs;
#pragma unroll
        for (int j = 0; j < 4; j++)
            *(float4*)(Au + ar * SAs + aseg * 16 + 4 * j) = ra[j];
#pragma unroll
        for (int j = 0; j < BF4; j++)
            *(float4*)(Bu + bk * SBs + bseg * (COUT / 8) + 4 * j) = rb[j];
    };
    auto domma = [&](int s) {
        const uint32_t* Au = (const uint32_t*)(dsm + s * STG);
        const uint32_t* Bu = Au + 128 * SAs;
        const int rq = lane >> 2, cq = lane & 3;
#pragma unroll
        for (int q = 0; q < 4; q++) {
            const int kk = q * 8 + cq;
            uint32_t af[MT][4], bf[4][2];
#pragma unroll
            for (int mt = 0; mt < MT; mt++) {
                int row = wm * (MT * 16) + mt * 16 + rq;
                af[mt][0] = Au[row * SAs + kk];
                af[mt][1] = Au[(row + 8) * SAs + kk];
                af[mt][2] = Au[row * SAs + kk + 4];
                af[mt][3] = Au[(row + 8) * SAs + kk + 4];
            }
#pragma unroll
            for (int nt = 0; nt < 4; nt++) {
                int col = wn * 32 + nt * 8 + rq;
                bf[nt][0] = Bu[kk * SBs + col];
                bf[nt][1] = Bu[(kk + 4) * SBs + col];
            }
#pragma unroll
            for (int mt = 0; mt < MT; mt++)
#pragma unroll
                for (int nt = 0; nt < 4; nt++)
                    mma_tf32(acc[mt][nt], af[mt], bf[nt]);
        }
    };

    ldg(0); sts(0); __syncthreads();
#pragma unroll 1
    for (int c = 0; c < nchunks; c++) {
        if (c + 1 < nchunks) ldg(c + 1);
        domma(c & 1);
        if (c + 1 < nchunks) sts((c + 1) & 1);
        __syncthreads();
    }

    float* E = dsm;
    const int rq = lane >> 2, cq = lane & 3;
    if (CLOUT) {
        constexpr int SE = COUT + 1;
#pragma unroll
        for (int mt = 0; mt < MT; mt++)
#pragma unroll
            for (int nt = 0; nt < 4; nt++) {
                int row = wm * (MT * 16) + mt * 16 + rq;
                int col = wn * 32 + nt * 8 + 2 * cq;
                E[row * SE + col]           = acc[mt][nt][0];
                E[row * SE + col + 1]       = acc[mt][nt][1];
                E[(row + 8) * SE + col]     = acc[mt][nt][2];
                E[(row + 8) * SE + col + 1] = acc[mt][nt][3];
            }
        __syncthreads();
        int opos = ((2 * gz + pz) * DOUT + (2 * gy + py)) * DOUT + (2 * gx + px);
        float* ob = out + ((size_t)bb * DOUT * DOUT * DOUT + opos) * COUT;
#pragma unroll
        for (int j4 = 0; j4 < COUT / 8; j4++) {
            float4 v; float* pv = (float*)&v;
#pragma unroll
            for (int t = 0; t < 4; t++) {
                int ch = aseg * (COUT / 2) + j4 * 4 + t;
                float x = E[ar * SE + ch] + bias[ch];
                pv[t] = __uint_as_float(f2tf(silu(x)));
            }
            *(float4*)(ob + aseg * (COUT / 2) + j4 * 4) = v;
        }
    } else {
        constexpr int SE = 36;
#pragma unroll
        for (int mt = 0; mt < MT; mt++)
#pragma unroll
            for (int nt = 0; nt < 4; nt++) {
                int row = wm * (MT * 16) + mt * 16 + rq;
                int col = nt * 8 + 2 * cq;
                E[row * SE + col]           = acc[mt][nt][0];
                E[row * SE + col + 1]       = acc[mt][nt][1];
                E[(row + 8) * SE + col]     = acc[mt][nt][2];
                E[(row + 8) * SE + col + 1] = acc[mt][nt][3];
            }
        __syncthreads();
        int ch = tid >> 3;
        float bv = bias[ch];
        float* ob = out + ((size_t)bb * COUT + ch) * (DOUT * DOUT * DOUT);
#pragma unroll
        for (int j = 0; j < 16; j++) {
            int p = (tid & 7) + 8 * j;
            int pp = pos0 + p;
            int hx = pp & (DIN - 1), hy = (pp >> LOGD) & (DIN - 1), hz = pp >> (2 * LOGD);
            int opos = ((2 * hz + pz) * DOUT + (2 * hy + py)) * DOUT + (2 * hx + px);
            ob[opos] = silu(E[p * SE + ch] + bv);
        }
    }
}

// ---------------- input dtype probe ----------------
__global__ void initflag_kernel() { g_flags = 0; g_nnz = 0; }

__global__ void scan_kernel(const unsigned int* __restrict__ xw) {
    int base = blockIdx.x * 256 + threadIdx.x;
    unsigned int f = 0, u = 0;
#pragma unroll
    for (int j = 0; j < 16; j++) {
        unsigned int w = xw[base + j * 1048576];
        f |= (w & 0xFEFEFEFEu);
        u |= (w & 0x01010100u);
    }
    int bits = (f ? 1 : 0) | (u ? 2 : 0);
    if (bits) atomicOr(&g_flags, bits);
}

// ---------------- bit pack ----------------
__global__ void pack_kernel(const unsigned char* __restrict__ xb, float* __restrict__ mc) {
    int i = blockIdx.x * 256 + threadIdx.x;
    if (i >= N_MC) return;
    int k  = i & 63;
    int j  = (i >> 6) & 63;
    int zi = (i >> 12) & 63;
    int c  = (i >> 18) & 7;
    int b  = i >> 21;
    int a   = c >> 1;
    int bb0 = (2 * c) & 3;
    int base = (((b * 256) + 4 * zi + a) * 256 + 4 * j + bb0) * 256 + 4 * k;
    int s = 0;
    int flags = g_flags;
    if (flags & 1) {
        const float* xf = (const float*)xb;
        float4 f0 = *(const float4*)(xf + base);
        float4 f1 = *(const float4*)(xf + base + 256);
        if (f0.x != 0.f) s |= 1;   if (f0.y != 0.f) s |= 2;
        if (f0.z != 0.f) s |= 4;   if (f0.w != 0.f) s |= 8;
        if (f1.x != 0.f) s |= 16;  if (f1.y != 0.f) s |= 32;
        if (f1.z != 0.f) s |= 64;  if (f1.w != 0.f) s |= 128;
    } else if (flags & 2) {
        unsigned int r0 = *(const unsigned int*)(xb + base);
        unsigned int r1 = *(const unsigned int*)(xb + base + 256);
#pragma unroll
        for (int cc = 0; cc < 4; cc++) {
            if ((r0 >> (8 * cc)) & 0xFF) s |= 1 << cc;
            if ((r1 >> (8 * cc)) & 0xFF) s |= 1 << (4 + cc);
        }
    } else {
        const int* xi = (const int*)xb;
        int4 a0 = *(const int4*)(xi + base);
        int4 a1 = *(const int4*)(xi + base + 256);
        if (a0.x) s |= 1;   if (a0.y) s |= 2;
        if (a0.z) s |= 4;   if (a0.w) s |= 8;
        if (a1.x) s |= 16;  if (a1.y) s |= 32;
        if (a1.z) s |= 64;  if (a1.w) s |= 128;
    }
    mc[i] = (float)s * (1.0f / 255.0f);
}

// ---------------- zero-patch mask + nonzero-token compaction ----------------
__global__ void zmask_kernel(const float* __restrict__ mc) {
    int idx = blockIdx.x * 256 + threadIdx.x;
    int tok = idx >> 3, c = idx & 7;
    int p = tok & 4095, b = tok >> 12;
    int zk = p & 15, zj = (p >> 4) & 15, zi = p >> 8;
    bool any = false;
    const float* basep = mc + (((b * 8 + c) * 64 + 4 * zi) * 64 + 4 * zj) * 64 + 4 * zk;
#pragma unroll
    for (int dz = 0; dz < 4; dz++)
#pragma unroll
        for (int dy = 0; dy < 4; dy++) {
            float4 v = *(const float4*)(basep + (dz * 64 + dy) * 64);
            any |= (v.x != 0.f) | (v.y != 0.f) | (v.z != 0.f) | (v.w != 0.f);
        }
    unsigned m = __ballot_sync(0xFFFFFFFFu, any);
    if (c == 0) {
        int sh = threadIdx.x & 24;
        bool nz = ((m >> sh) & 0xFF) != 0;
        g_zmask[tok] = nz ? 0 : 1;
        if (nz) { int pp = atomicAdd(&g_nnz, 1); g_toklist[pp] = tok; }
    }
}

// ---------------- SIMT 3x3x3 conv, stride 1, XW=8, OCW=8, ic-pair unrolled ----------------
template<int CIN, int OCW, int CL>
__launch_bounds__(256)
__global__ void conv_k3_x8(const float* __restrict__ in, const float* __restrict__ wt,
                           const float* __restrict__ bias, float* __restrict__ out,
                           int Din, int COUT, int act)
{
    extern __shared__ float sw[];
    const int oc0 = blockIdx.y * OCW;
    const int b   = blockIdx.z;
    for (int idx = threadIdx.x; idx < CIN * 27 * OCW; idx += 256) {
        int r = idx / OCW, o = idx % OCW;
        sw[idx] = wt[(oc0 + o) * (CIN * 27) + r];
    }
    __syncthreads();
    const int spatial = Din * Din * Din;
    int gpos = (blockIdx.x * 256 + threadIdx.x) * 8;
    if (gpos >= spatial) return;
    int x0 = gpos % Din; int t1 = gpos / Din; int y = t1 % Din; int z = t1 / Din;

    float acc[OCW][8];
#pragma unroll
    for (int o = 0; o < OCW; o++) {
        float bv = bias[oc0 + o];
#pragma unroll
        for (int xx = 0; xx < 8; xx++) acc[o][xx] = bv;
    }
    const float* inb = in + b * CIN * Din * Din * Din;
#pragma unroll 1
    for (int ic = 0; ic < CIN; ic += 2) {
        const float* inc0 = inb + ic * Din * Din * Din;
        const float* inc1 = inc0 + Din * Din * Din;
#pragma unroll 1
        for (int tz = 0; tz < 3; tz++) {
            int iz = z + tz - 1; if ((unsigned)iz >= (unsigned)Din) continue;
#pragma unroll
            for (int ty = 0; ty < 3; ty++) {
                int iy = y + ty - 1; if ((unsigned)iy >= (unsigned)Din) continue;
                int roff = (iz * Din + iy) * Din;
                const float* row0 = inc0 + roff;
                const float* row1 = inc1 + roff;
                // batch both channels' loads for MLP
                float4 a0 = *(const float4*)(row0 + x0);
                float4 a1 = *(const float4*)(row0 + x0 + 4);
                float4 b0 = *(const float4*)(row1 + x0);
                float4 b1 = *(const float4*)(row1 + x0 + 4);
                float am = (x0 > 0) ? row0[x0 - 1] : 0.f;
                float bm = (x0 > 0) ? row1[x0 - 1] : 0.f;
                float ap = (x0 + 8 < Din) ? row0[x0 + 8] : 0.f;
                float bp = (x0 + 8 < Din) ? row1[x0 + 8] : 0.f;
                float rA[10], rB[10];
                rA[0] = am; rA[1] = a0.x; rA[2] = a0.y; rA[3] = a0.z; rA[4] = a0.w;
                rA[5] = a1.x; rA[6] = a1.y; rA[7] = a1.z; rA[8] = a1.w; rA[9] = ap;
                rB[0] = bm; rB[1] = b0.x; rB[2] = b0.y; rB[3] = b0.z; rB[4] = b0.w;
                rB[5] = b1.x; rB[6] = b1.y; rB[7] = b1.z; rB[8] = b1.w; rB[9] = bp;
                const float* swp0 = sw + (ic * 27 + tz * 9 + ty * 3) * OCW;
                const float* swp1 = swp0 + 27 * OCW;
#pragma unroll
                for (int tx = 0; tx < 3; tx++) {
                    float w[OCW];
#pragma unroll
                    for (int o4 = 0; o4 < OCW / 4; o4++)
                        *(float4*)(w + 4 * o4) = *(const float4*)(swp0 + tx * OCW + 4 * o4);
#pragma unroll
                    for (int o = 0; o < OCW; o++)
#pragma unroll
                        for (int xx = 0; xx < 8; xx++) acc[o][xx] += w[o] * rA[xx + tx];
                }
#pragma unroll
                for (int tx = 0; tx < 3; tx++) {
                    float w[OCW];
#pragma unroll
                    for (int o4 = 0; o4 < OCW / 4; o4++)
                        *(float4*)(w + 4 * o4) = *(const float4*)(swp1 + tx * OCW + 4 * o4);
#pragma unroll
                    for (int o = 0; o < OCW; o++)
#pragma unroll
                        for (int xx = 0; xx < 8; xx++) acc[o][xx] += w[o] * rB[xx + tx];
                }
            }
        }
    }
    if (CL) {
        int pos = (z * Din + y) * Din + x0;
#pragma unroll
        for (int xx = 0; xx < 8; xx++) {
            float s[OCW];
#pragma unroll
            for (int o = 0; o < OCW; o++) {
                s[o] = acc[o][xx];
                if (act) s[o] = silu(s[o]);
            }
            float* op = out + ((size_t)b * spatial + pos + xx) * COUT + oc0;
#pragma unroll
            for (int o4 = 0; o4 < OCW / 4; o4++)
                *(float4*)(op + 4 * o4) = *(float4*)(s + 4 * o4);
        }
    } else {
        int obase0 = (z * Din + y) * Din + x0;
#pragma unroll
        for (int o = 0; o < OCW; o++) {
            float s[8];
#pragma unroll
            for (int xx = 0; xx < 8; xx++) {
                s[xx] = acc[o][xx];
                if (act) s[xx] = silu(s[xx]);
            }
            float* op = out + (size_t)(b * COUT + oc0 + o) * spatial + obase0;
            *(float4*)op = make_float4(s[0], s[1], s[2], s[3]);
            *(float4*)(op + 4) = make_float4(s[4], s[5], s[6], s[7]);
        }
    }
}

// ---------------- 1x1x1 convs ----------------
__global__ void quant_conv_cl_kernel(const float* __restrict__ h_cl, const float* __restrict__ w,
                                     const float* __restrict__ bias, float* __restrict__ seq)
{
    int i = blockIdx.x * 256 + threadIdx.x;
    if (i >= NTOK * EDIM) return;
    int e = i & 15; int p = (i >> 4) & 4095; int b = i >> 16;
    float acc = bias[e];
    const float4* hp = (const float4*)(h_cl + ((size_t)(b * 4096 + p)) * 128);
    const float4* wp = (const float4*)(w + e * 128);
#pragma unroll 8
    for (int ic4 = 0; ic4 < 32; ic4++) {
        float4 hv = hp[ic4], wv = wp[ic4];
        acc += wv.x * hv.x + wv.y * hv.y + wv.z * hv.z + wv.w * hv.w;
    }
    seq[i] = acc;
}

__global__ void post_quant_cl_kernel(const float* __restrict__ q, const float* __restrict__ w,
                                     const float* __restrict__ bias, float* __restrict__ out_cl)
{
    int i = blockIdx.x * 256 + threadIdx.x;
    if (i >= BATCH * 4096 * 128) return;
    int oc = i & 127; int p = (i >> 7) & 4095; int b = i >> 19;
    float acc = bias[oc];
    const float* qp = q + (b * EDIM) * 4096 + p;
    const float* wp = w + oc * EDIM;
#pragma unroll
    for (int e = 0; e < EDIM; e++) acc += wp[e] * qp[e * 4096];
    out_cl[i] = __uint_as_float(f2tf(acc));
}

// ---------------- VQ ----------------
__global__ void cnorm_kernel(const float* __restrict__ cb) {
    int k = blockIdx.x * 128 + threadIdx.x;
    if (k < KCODE) {
        float s = 0.f;
#pragma unroll
        for (int e = 0; e < EDIM; e++) { float c = cb[k * EDIM + e]; s += c * c; }
        g_cnorm[k] = s;
    }
}

// VQ over compacted list; 64 tokens/block, 2 tokens per thread-slot
__global__ void vq_kernel(const float* __restrict__ seq, const float* __restrict__ cb)
{
    __shared__ float stok[64 * 16];
    __shared__ float sc[128 * 16];
    __shared__ float sn[128];
    __shared__ float rd[256];
    __shared__ int   ri[256];
    const int nnz = g_nnz;
    const int tok0 = blockIdx.x * 64;
    if (tok0 >= nnz) return;
    const int tid = threadIdx.x;
    for (int i = tid; i < 1024; i += 128) {
        int ti = tok0 + (i >> 4);
        int tok = g_toklist[ti < nnz ? ti : (nnz - 1)];
        stok[i] = seq[tok * 16 + (i & 15)];
    }
    __syncthreads();
    const int t = tid & 31, g = tid >> 5;
    float sAv[16], sBv[16];
#pragma unroll
    for (int e = 0; e < 16; e++) {
        sAv[e] = stok[t * 16 + e];
        sBv[e] = stok[(t + 32) * 16 + e];
    }
    float bestA = 3.4e38f, bestB = 3.4e38f; int idxA = 0, idxB = 0;
    for (int tile = 0; tile < KCODE / 128; tile++) {
        __syncthreads();
        for (int i = tid; i < 512; i += 128)
            *(float4*)&sc[i * 4] = *(const float4*)&cb[tile * 2048 + i * 4];
        if (tid < 128) sn[tid] = g_cnorm[tile * 128 + tid];
        __syncthreads();
#pragma unroll 4
        for (int kk = g; kk < 128; kk += 4) {
            const float4* c4 = (const float4*)&sc[kk * 16];
            float4 c0 = c4[0], c1 = c4[1], c2 = c4[2], c3 = c4[3];
            float dA = c0.x * sAv[0] + c0.y * sAv[1] + c0.z * sAv[2] + c0.w * sAv[3]
                     + c1.x * sAv[4] + c1.y * sAv[5] + c1.z * sAv[6] + c1.w * sAv[7]
                     + c2.x * sAv[8] + c2.y * sAv[9] + c2.z * sAv[10] + c2.w * sAv[11]
                     + c3.x * sAv[12] + c3.y * sAv[13] + c3.z * sAv[14] + c3.w * sAv[15];
            float dB = c0.x * sBv[0] + c0.y * sBv[1] + c0.z * sBv[2] + c0.w * sBv[3]
                     + c1.x * sBv[4] + c1.y * sBv[5] + c1.z * sBv[6] + c1.w * sBv[7]
                     + c2.x * sBv[8] + c2.y * sBv[9] + c2.z * sBv[10] + c2.w * sBv[11]
                     + c3.x * sBv[12] + c3.y * sBv[13] + c3.z * sBv[14] + c3.w * sBv[15];
            float distA = sn[kk] - 2.f * dA;
            float distB = sn[kk] - 2.f * dB;
            if (distA < bestA) { bestA = distA; idxA = tile * 128 + kk; }
            if (distB < bestB) { bestB = distB; idxB = tile * 128 + kk; }
        }
    }
    rd[tid] = bestA; ri[tid] = idxA;
    rd[128 + tid] = bestB; ri[128 + tid] = idxB;
    __syncthreads();
    if (g == 0) {
        float best = rd[t]; int bidx = ri[t];
        for (int gg = 1; gg < 4; gg++) {
            float d = rd[gg * 32 + t]; int k = ri[gg * 32 + t];
            if (d < best || (d == best && k < bidx)) { best = d; bidx = k; }
        }
        int ti = tok0 + t;
        if (ti < nnz) g_idx[g_toklist[ti]] = bidx;
    } else if (g == 1) {
        float best = rd[128 + t]; int bidx = ri[128 + t];
        for (int gg = 1; gg < 4; gg++) {
            float d = rd[128 + gg * 32 + t]; int k = ri[128 + gg * 32 + t];
            if (d < best || (d == best && k < bidx)) { best = d; bidx = k; }
        }
        int ti = tok0 + 32 + t;
        if (ti < nnz) g_idx[g_toklist[ti]] = bidx;
    }
}

// ---------------- commit loss ----------------
__global__ void commit_kernel(const float* __restrict__ seq, const float* __restrict__ cb)
{
    __shared__ float sh[128];
    int t = blockIdx.x * 128 + threadIdx.x;
    float v = 0.f;
    if (!g_zmask[t]) {
        const float* s = seq + t * 16;
        const float* c = cb + g_idx[t] * 16;
        float a = 0.f;
#pragma unroll
        for (int e = 0; e < 16; e++) { float d = c[e] - s[e]; a += d * d; }
        v = a * (1.f / 16.f);
    }
    sh[threadIdx.x] = v; __syncthreads();
    for (int st = 64; st; st >>= 1) {
        if (threadIdx.x < st) sh[threadIdx.x] += sh[threadIdx.x + st];
        __syncthreads();
    }
    if (threadIdx.x == 0) g_part[blockIdx.x] = sh[0];
}

__global__ void commit_final(float* __restrict__ out) {
    if (threadIdx.x == 0) {
        float s = 0.f;
        for (int i = 0; i < 128; i++) s += g_part[i];
        out[0] = 0.25f * s / 16384.f;
    }
}

__global__ void fullidx_kernel(float* __restrict__ out) {
    int i = blockIdx.x * 256 + threadIdx.x;
    if (i < NTOK) out[i] = g_zmask[i] ? 0.f : (float)(g_idx[i] + 1);
}

__global__ void qbuild_kernel(const float* __restrict__ cb, const float* __restrict__ rep,
                              const float* __restrict__ pos)
{
    int i = blockIdx.x * 256 + threadIdx.x;
    if (i >= BATCH * EDIM * 4096) return;
    int p = i & 4095; int e = (i >> 12) & 15; int b = i >> 16;
    int tok = (b << 12) + p;
    float v = g_zmask[tok] ? rep[e] : cb[g_idx[tok] * 16 + e];
    g_q[i] = v + pos[e * 4096 + p];
}

// ---------------- launch ----------------
extern "C" void kernel_launch(void* const* d_in, const int* in_sizes, int n_in,
                              void* d_out_, int out_size)
{
    const unsigned char* x = (const unsigned char*)d_in[0];
    const float* enc_in_w  = (const float*)d_in[1];
    const float* enc_in_b  = (const float*)d_in[2];
    const float* enc_d1_w  = (const float*)d_in[3];
    const float* enc_d1_b  = (const float*)d_in[4];
    const float* enc_d2_w  = (const float*)d_in[5];
    const float* enc_d2_b  = (const float*)d_in[6];
    const float* enc_out_w = (const float*)d_in[7];
    const float* enc_out_b = (const float*)d_in[8];
    const float* quant_w   = (const float*)d_in[9];
    const float* quant_b   = (const float*)d_in[10];
    const float* codebook  = (const float*)d_in[11];
    const float* rep_tok   = (const float*)d_in[12];
    const float* pos_emb   = (const float*)d_in[13];
    const float* pq_w      = (const float*)d_in[14];
    const float* pq_b      = (const float*)d_in[15];
    const float* dec_in_w  = (const float*)d_in[16];
    const float* dec_in_b  = (const float*)d_in[17];
    const float* dec_u1_w  = (const float*)d_in[18];
    const float* dec_u1_b  = (const float*)d_in[19];
    const float* dec_u2_w  = (const float*)d_in[20];
    const float* dec_u2_b  = (const float*)d_in[21];
    const float* dec_out_w = (const float*)d_in[22];
    const float* dec_out_b = (const float*)d_in[23];
    float* out = (float*)d_out_;

    float *pA, *pB, *pC, *pD, *pSeq, *pQ, *pCL, *pW, *pW1, *pW2;
    float *pH0, *pL0, *pH1, *pL1, *pH2, *pL2;
    cudaGetSymbolAddress((void**)&pA, g_bufA);
    cudaGetSymbolAddress((void**)&pB, g_bufB);
    cudaGetSymbolAddress((void**)&pC, g_bufC);
    cudaGetSymbolAddress((void**)&pD, g_bufD);
    cudaGetSymbolAddress((void**)&pSeq, g_seq);
    cudaGetSymbolAddress((void**)&pQ, g_q);
    cudaGetSymbolAddress((void**)&pCL, g_cl);
    cudaGetSymbolAddress((void**)&pW, g_wt);
    cudaGetSymbolAddress((void**)&pW1, g_wt1);
    cudaGetSymbolAddress((void**)&pW2, g_wt2);
    cudaGetSymbolAddress((void**)&pH0, g_wh0);
    cudaGetSymbolAddress((void**)&pL0, g_wl0);
    cudaGetSymbolAddress((void**)&pH1, g_wh1);
    cudaGetSymbolAddress((void**)&pL1, g_wl1);
    cudaGetSymbolAddress((void**)&pH2, g_wh2);
    cudaGetSymbolAddress((void**)&pL2, g_wl2);

    cudaFuncSetAttribute(conv_mma_dec, cudaFuncAttributeMaxDynamicSharedMemorySize, 2 * STAGE_F * 4);
    cudaFuncSetAttribute((conv_mma3<32, 64, 32, 5, 2, 1>),   cudaFuncAttributeMaxDynamicSharedMemorySize, 110592);
    cudaFuncSetAttribute((conv_mma3<64, 128, 16, 4, 2, 1>),  cudaFuncAttributeMaxDynamicSharedMemorySize, 143360);
    cudaFuncSetAttribute((conv_mma3<128, 128, 16, 4, 1, 0>), cudaFuncAttributeMaxDynamicSharedMemorySize, 143360);
    cudaFuncSetAttribute((tconv_mma<128, 64, 16, 4, 1>), cudaFuncAttributeMaxDynamicSharedMemorySize, 55296);
    cudaFuncSetAttribute((tconv_mma<64, 32, 32, 5, 0>),  cudaFuncAttributeMaxDynamicSharedMemorySize, 47104);

    float* mc = out + OFF_MC;
    dim3 blk(256);

    initflag_kernel<<<1, 1>>>();
    scan_kernel<<<4096, 256>>>((const unsigned int*)x);
    pack_kernel<<<N_MC / 256, 256>>>(x, mc);

    // weight transforms
    wtrans_hilo<<<216, 256>>>(enc_d1_w, pH1, pL1, 32, 64);
    wtrans_hilo<<<864, 256>>>(enc_d2_w, pH2, pL2, 64, 128);
    wtrans_hilo<<<1728, 256>>>(enc_out_w, pH0, pL0, 128, 128);
    wtrans2<<<1728, 256>>>(dec_in_w, pW, 128, 128);
    wtrans2<<<864, 256>>>(dec_u1_w, pW1, 128, 64);
    wtrans2<<<216, 256>>>(dec_u2_w, pW2, 64, 32);

    // encoder: enc_in SIMT (channel-last out), rest 3xtf32 mma (fp32-accurate)
    conv_k3_x8<8, 8, 1><<<dim3(128, 4, 4), blk, 8 * 27 * 8 * 4>>>(mc, enc_in_w, enc_in_b, pA, 64, 32, 1);
    zmask_kernel<<<512, 256>>>(mc);
    conv_mma3<32, 64, 32, 5, 2, 1><<<dim3(256, 1, 4), 256, 110592>>>(pA, pH1, pL1, enc_d1_b, pB);
    conv_mma3<64, 128, 16, 4, 2, 1><<<dim3(32, 1, 4), 256, 143360>>>(pB, pH2, pL2, enc_d2_b, pCL);
    conv_mma3<128, 128, 16, 4, 1, 0><<<dim3(32, 1, 4), 256, 143360>>>(pCL, pH0, pL0, enc_out_b, pD);

    // quantization path
    cnorm_kernel<<<KCODE / 128, 128>>>(codebook);
    quant_conv_cl_kernel<<<(NTOK * EDIM) / 256, 256>>>(pD, quant_w, quant_b, pSeq);
    vq_kernel<<<NTOK / 64, 128>>>(pSeq, codebook);
    commit_kernel<<<NTOK / 128, 128>>>(pSeq, codebook);
    commit_final<<<1, 1>>>(out + OFF_COMMIT);
    fullidx_kernel<<<NTOK / 256, 256>>>(out + OFF_IDX);
    qbuild_kernel<<<(BATCH * EDIM * 4096) / 256, 256>>>(codebook, rep_tok, pos_emb);
    post_quant_cl_kernel<<<(BATCH * 4096 * 128) / 256, 256>>>(pQ, pq_w, pq_b, pCL);

    // decoder: dec_in + both tconvs on tensor cores (tf32), dec_out SIMT XW=8
    conv_mma_dec<<<dim3(32, 1, 4), 256, 2 * STAGE_F * 4>>>(pCL, dec_in_b, pD);
    tconv_mma<128, 64, 16, 4, 1><<<dim3(32, 8, 4), 256, 55296>>>(pD, pW1, dec_u1_b, pB);
    tconv_mma<64, 32, 32, 5, 0><<<dim3(256, 8, 4), 256, 47104>>>(pB, pW2, dec_u2_b, pA);
    conv_k3_x8<32, 8, 0><<<dim3(128, 1, 4), blk, 32 * 27 * 8 * 4>>>(pA, dec_out_w, dec_out_b, out, 64, 8, 0);
}